// round 3
// baseline (speedup 1.0000x reference)
#include <cuda_runtime.h>
#include <math.h>
#include <stdint.h>

#define BATCH 4
#define RAYS  8192
#define NRAYS (BATCH*RAYS)          // 32768
#define NS    48
#define RES   48
#define CH    32
#define NPTS  (NRAYS*NS)            // 1572864

#define DT    0.03125f              // (FAR-NEAR)/NS

// ---------------- device scratch ----------------
__device__ __align__(16) float g_mat_t[3*BATCH*RES*RES*CH];
__device__ __align__(16) float g_vec_t[3*BATCH*RES*CH];
__device__ __align__(16) float g_rgb[(size_t)NPTS*3];
__device__ __align__(16) float g_f[(size_t)NPTS*72];
__device__ __align__(16) float g_bias[(size_t)NRAYS*64];
__device__ float g_w2[192];

__device__ __forceinline__ float gelu_exact(float x) {
    return 0.5f * x * (1.0f + erff(x * 0.70710678118654752f));
}

__device__ __forceinline__ uint32_t f2tf32(float f) {
    uint32_t u;
    asm("cvt.rna.tf32.f32 %0, %1;" : "=r"(u) : "f"(f));
    return u;
}

__device__ __forceinline__ void mma_tf32(float d[4],
                                         uint32_t a0, uint32_t a1, uint32_t a2, uint32_t a3,
                                         uint32_t b0, uint32_t b1) {
    asm volatile("mma.sync.aligned.m16n8k8.row.col.f32.tf32.tf32.f32 "
                 "{%0,%1,%2,%3}, {%4,%5,%6,%7}, {%8,%9}, {%0,%1,%2,%3};"
                 : "+f"(d[0]), "+f"(d[1]), "+f"(d[2]), "+f"(d[3])
                 : "r"(a0), "r"(a1), "r"(a2), "r"(a3), "r"(b0), "r"(b1));
}

__global__ void k_transpose_mat(const float* __restrict__ m) {
    int idx = blockIdx.x * blockDim.x + threadIdx.x;
    if (idx >= 3*BATCH*RES*RES*CH) return;
    int c   = idx % CH;
    int pix = (idx / CH) % (RES*RES);
    int ib  = idx / (CH*RES*RES);
    g_mat_t[idx] = m[((size_t)ib*CH + c)*(RES*RES) + pix];
}

__global__ void k_transpose_vec(const float* __restrict__ v) {
    int idx = blockIdx.x * blockDim.x + threadIdx.x;
    if (idx >= 3*BATCH*RES*CH) return;
    int c  = idx % CH;
    int r  = (idx / CH) % RES;
    int ib = idx / (CH*RES);
    g_vec_t[idx] = v[((size_t)ib*CH + c)*RES + r];
}

__global__ void k_copy_w2(const float* __restrict__ w2) {
    int i = threadIdx.x;
    if (i < 192) g_w2[i] = w2[i];
}

__global__ void k_bias(const float* __restrict__ rays_d,
                       const float* __restrict__ w1, const float* __restrict__ b1) {
    int q = blockIdx.x * blockDim.x + threadIdx.x;
    if (q >= NRAYS) return;
    float dx = rays_d[q*3+0], dy = rays_d[q*3+1], dz = rays_d[q*3+2];
    float inv = 1.0f / sqrtf(dx*dx + dy*dy + dz*dz);
    dx *= inv; dy *= inv; dz *= inv;
    float pe[27];
    pe[0] = dx; pe[1] = dy; pe[2] = dz;
    float f = 1.0f;
    #pragma unroll
    for (int fi = 0; fi < 4; fi++) {
        float s, c;
        sincosf(dx*f, &s, &c); pe[3 + fi*3 + 0] = s; pe[15 + fi*3 + 0] = c;
        sincosf(dy*f, &s, &c); pe[3 + fi*3 + 1] = s; pe[15 + fi*3 + 1] = c;
        sincosf(dz*f, &s, &c); pe[3 + fi*3 + 2] = s; pe[15 + fi*3 + 2] = c;
        f *= 2.0f;
    }
    float acc[64];
    #pragma unroll
    for (int j = 0; j < 64; j++) acc[j] = b1[j];
    #pragma unroll 1
    for (int k = 0; k < 27; k++) {
        float v = pe[k];
        const float* wr = w1 + (64 + k) * 64;
        #pragma unroll
        for (int j = 0; j < 64; j++) acc[j] += v * wr[j];
    }
    float* o = g_bias + (size_t)q * 64;
    #pragma unroll
    for (int j = 0; j < 64; j++) o[j] = acc[j];
}

__global__ __launch_bounds__(128)
void k_sample(const float* __restrict__ rays_o, const float* __restrict__ rays_d,
              float* __restrict__ out_sigma) {
    const int p   = blockIdx.x * 128 + threadIdx.x;
    const int s   = p % NS;
    const int ray = p / NS;
    const int b   = ray / RAYS;

    const float ox = rays_o[ray*3+0], oy = rays_o[ray*3+1], oz = rays_o[ray*3+2];
    const float dx = rays_d[ray*3+0], dy = rays_d[ray*3+1], dz = rays_d[ray*3+2];
    const float t  = ((float)s + 0.5f) * DT;

    const float px = ((ox + dx*t) + 0.8f) * 1.25f - 1.0f;
    const float py = ((oy + dy*t) + 0.8f) * 1.25f - 1.0f;
    const float pz = ((oz + dz*t) + 0.8f) * 1.25f - 1.0f;

    float sigma = 0.0f;
    float* fo = g_f + (size_t)p * 72;

    #pragma unroll 1
    for (int pl = 0; pl < 3; pl++) {
        const float cx = (pl == 0) ? px : ((pl == 1) ? pz : py);
        const float cy = (pl == 0) ? py : ((pl == 1) ? px : pz);
        const float cz = (pl == 0) ? pz : ((pl == 1) ? py : px);

        const float fx = (cx + 1.0f) * 23.5f;
        const float fy = (cy + 1.0f) * 23.5f;
        const float fz = (cz + 1.0f) * 23.5f;
        const float x0f = floorf(fx), y0f = floorf(fy), z0f = floorf(fz);
        const float wx = fx - x0f, wy = fy - y0f, wz = fz - z0f;
        const int ix0 = (int)x0f, iy0 = (int)y0f, iz0 = (int)z0f;

        const float mx0 = (ix0 >= 0  && ix0 <  RES)   ? 1.0f : 0.0f;
        const float mx1 = (ix0 >= -1 && ix0 <  RES-1) ? 1.0f : 0.0f;
        const float my0 = (iy0 >= 0  && iy0 <  RES)   ? 1.0f : 0.0f;
        const float my1 = (iy0 >= -1 && iy0 <  RES-1) ? 1.0f : 0.0f;
        const float mz0 = (iz0 >= 0  && iz0 <  RES)   ? 1.0f : 0.0f;
        const float mz1 = (iz0 >= -1 && iz0 <  RES-1) ? 1.0f : 0.0f;

        const int cx0 = min(max(ix0,   0), RES-1), cx1 = min(max(ix0+1, 0), RES-1);
        const int cy0 = min(max(iy0,   0), RES-1), cy1 = min(max(iy0+1, 0), RES-1);
        const int cz0 = min(max(iz0,   0), RES-1), cz1 = min(max(iz0+1, 0), RES-1);

        const float w00 = (1.0f-wx)*(1.0f-wy)*mx0*my0;
        const float w10 = wx*(1.0f-wy)*mx1*my0;
        const float w01 = (1.0f-wx)*wy*mx0*my1;
        const float w11 = wx*wy*mx1*my1;
        const float u0  = (1.0f-wz)*mz0;
        const float u1  = wz*mz1;

        const float* mb = g_mat_t + ((size_t)(pl*BATCH + b) * (RES*RES)) * CH;
        const float* vb = g_vec_t + ((size_t)(pl*BATCH + b) * RES) * CH;
        const float4* p00 = (const float4*)(mb + (size_t)(cy0*RES + cx0) * CH);
        const float4* p10 = (const float4*)(mb + (size_t)(cy0*RES + cx1) * CH);
        const float4* p01 = (const float4*)(mb + (size_t)(cy1*RES + cx0) * CH);
        const float4* p11 = (const float4*)(mb + (size_t)(cy1*RES + cx1) * CH);
        const float4* q0  = (const float4*)(vb + (size_t)cz0 * CH);
        const float4* q1  = (const float4*)(vb + (size_t)cz1 * CH);

        #pragma unroll 1
        for (int ch = 0; ch < 2; ch++) {
            float4 a = p00[ch], bb = p10[ch], c4 = p01[ch], d4 = p11[ch];
            float4 e = q0[ch],  f4 = q1[ch];
            float pf0 = w00*a.x + w10*bb.x + w01*c4.x + w11*d4.x;
            float pf1 = w00*a.y + w10*bb.y + w01*c4.y + w11*d4.y;
            float pf2 = w00*a.z + w10*bb.z + w01*c4.z + w11*d4.z;
            float pf3 = w00*a.w + w10*bb.w + w01*c4.w + w11*d4.w;
            float lf0 = u0*e.x + u1*f4.x;
            float lf1 = u0*e.y + u1*f4.y;
            float lf2 = u0*e.z + u1*f4.z;
            float lf3 = u0*e.w + u1*f4.w;
            sigma += pf0*lf0 + pf1*lf1 + pf2*lf2 + pf3*lf3;
        }
        #pragma unroll 1
        for (int ch = 2; ch < 8; ch++) {
            float4 a = p00[ch], bb = p10[ch], c4 = p01[ch], d4 = p11[ch];
            float4 e = q0[ch],  f4 = q1[ch];
            float4 g;
            g.x = gelu_exact((w00*a.x + w10*bb.x + w01*c4.x + w11*d4.x) * (u0*e.x + u1*f4.x));
            g.y = gelu_exact((w00*a.y + w10*bb.y + w01*c4.y + w11*d4.y) * (u0*e.y + u1*f4.y));
            g.z = gelu_exact((w00*a.z + w10*bb.z + w01*c4.z + w11*d4.z) * (u0*e.z + u1*f4.z));
            g.w = gelu_exact((w00*a.w + w10*bb.w + w01*c4.w + w11*d4.w) * (u0*e.w + u1*f4.w));
            *(float4*)(fo + pl*24 + (ch-2)*4) = g;
        }
    }
    out_sigma[p] = fmaxf(sigma, 0.0f);
}

#define OF_F    0
#define OF_B1H  9728
#define OF_B1L  (OF_B1H + 5184)
#define OF_B2H  (OF_B1L + 5184)
#define OF_B2L  (OF_B2H + 4608)
#define OF_W2   (OF_B2L + 4608)
#define SMEM_FLOATS (OF_W2 + 192)

__global__ __launch_bounds__(256)
void k_mlp(const float* __restrict__ w_mat, const float* __restrict__ b_mat,
           const float* __restrict__ w1, const float* __restrict__ b2) {
    extern __shared__ float sm[];
    float* sF   = sm + OF_F;
    float* sB1h = sm + OF_B1H;
    float* sB1l = sm + OF_B1L;
    float* sB2h = sm + OF_B2H;
    float* sB2l = sm + OF_B2L;
    float* sW2  = sm + OF_W2;

    const int tid  = threadIdx.x;
    const int lane = tid & 31;
    const int wid  = tid >> 5;
    const int q    = lane & 3;
    const int g    = lane >> 2;
    const int pbase = blockIdx.x * 128;

    for (int i = tid; i < 72*64; i += 256) {
        int k = i >> 6, n = i & 63;
        float f = w_mat[i];
        float hi = __uint_as_float(f2tf32(f));
        sB1h[k*72 + n] = hi;
        sB1l[k*72 + n] = __uint_as_float(f2tf32(f - hi));
    }
    for (int i = tid; i < 64*64; i += 256) {
        int k = i >> 6, n = i & 63;
        float f = w1[i];
        float hi = __uint_as_float(f2tf32(f));
        sB2h[k*72 + n] = hi;
        sB2l[k*72 + n] = __uint_as_float(f2tf32(f - hi));
    }
    const float4* gf4 = (const float4*)(g_f + (size_t)pbase * 72);
    for (int i = tid; i < 128*18; i += 256) {
        int row = i / 18, c4 = i % 18;
        float4 v = gf4[row*18 + c4];
        *(float4*)(sF + row*76 + c4*4) = v;
    }
    if (tid < 192) sW2[tid] = g_w2[tid];
    __syncthreads();

    const int m0 = wid * 16;
    float acc[8][4];
    #pragma unroll
    for (int nb = 0; nb < 8; nb++) {
        float bv0 = b_mat[nb*8 + 2*q];
        float bv1 = b_mat[nb*8 + 2*q + 1];
        acc[nb][0] = bv0; acc[nb][1] = bv1; acc[nb][2] = bv0; acc[nb][3] = bv1;
    }
    #pragma unroll 1
    for (int kb = 0; kb < 9; kb++) {
        int ab = (m0 + g)*76 + kb*8 + q;
        float f0 = sF[ab], f1 = sF[ab + 8*76], f2 = sF[ab + 4], f3 = sF[ab + 8*76 + 4];
        uint32_t ah0 = f2tf32(f0), ah1 = f2tf32(f1), ah2 = f2tf32(f2), ah3 = f2tf32(f3);
        uint32_t al0 = f2tf32(f0 - __uint_as_float(ah0));
        uint32_t al1 = f2tf32(f1 - __uint_as_float(ah1));
        uint32_t al2 = f2tf32(f2 - __uint_as_float(ah2));
        uint32_t al3 = f2tf32(f3 - __uint_as_float(ah3));
        #pragma unroll
        for (int nb = 0; nb < 8; nb++) {
            int b0i = (kb*8 + q)*72 + nb*8 + g;
            int b1i = b0i + 4*72;
            uint32_t bh0 = __float_as_uint(sB1h[b0i]);
            uint32_t bh1 = __float_as_uint(sB1h[b1i]);
            uint32_t bl0 = __float_as_uint(sB1l[b0i]);
            uint32_t bl1 = __float_as_uint(sB1l[b1i]);
            mma_tf32(acc[nb], ah0, ah1, ah2, ah3, bh0, bh1);
            mma_tf32(acc[nb], ah0, ah1, ah2, ah3, bl0, bl1);
            mma_tf32(acc[nb], al0, al1, al2, al3, bh0, bh1);
        }
    }
    __syncwarp();
    #pragma unroll
    for (int nb = 0; nb < 8; nb++) {
        int c0 = nb*8 + 2*q;
        int rA = (m0 + g)*76, rB = rA + 8*76;
        sF[rA + c0]     = gelu_exact(acc[nb][0]);
        sF[rA + c0 + 1] = gelu_exact(acc[nb][1]);
        sF[rB + c0]     = gelu_exact(acc[nb][2]);
        sF[rB + c0 + 1] = gelu_exact(acc[nb][3]);
    }
    __syncwarp();

    float acc2[8][4];
    #pragma unroll
    for (int nb = 0; nb < 8; nb++)
        acc2[nb][0] = acc2[nb][1] = acc2[nb][2] = acc2[nb][3] = 0.0f;
    #pragma unroll 1
    for (int kb = 0; kb < 8; kb++) {
        int ab = (m0 + g)*76 + kb*8 + q;
        float f0 = sF[ab], f1 = sF[ab + 8*76], f2 = sF[ab + 4], f3 = sF[ab + 8*76 + 4];
        uint32_t ah0 = f2tf32(f0), ah1 = f2tf32(f1), ah2 = f2tf32(f2), ah3 = f2tf32(f3);
        uint32_t al0 = f2tf32(f0 - __uint_as_float(ah0));
        uint32_t al1 = f2tf32(f1 - __uint_as_float(ah1));
        uint32_t al2 = f2tf32(f2 - __uint_as_float(ah2));
        uint32_t al3 = f2tf32(f3 - __uint_as_float(ah3));
        #pragma unroll
        for (int nb = 0; nb < 8; nb++) {
            int b0i = (kb*8 + q)*72 + nb*8 + g;
            int b1i = b0i + 4*72;
            uint32_t bh0 = __float_as_uint(sB2h[b0i]);
            uint32_t bh1 = __float_as_uint(sB2h[b1i]);
            uint32_t bl0 = __float_as_uint(sB2l[b0i]);
            uint32_t bl1 = __float_as_uint(sB2l[b1i]);
            mma_tf32(acc2[nb], ah0, ah1, ah2, ah3, bh0, bh1);
            mma_tf32(acc2[nb], ah0, ah1, ah2, ah3, bl0, bl1);
            mma_tf32(acc2[nb], al0, al1, al2, al3, bh0, bh1);
        }
    }

    const int pA = pbase + m0 + g;
    const int pB = pA + 8;
    const float* biasA = g_bias + (size_t)(pA / NS) * 64;
    const float* biasB = g_bias + (size_t)(pB / NS) * 64;
    float rA0 = 0.f, rA1 = 0.f, rA2 = 0.f, rB0 = 0.f, rB1 = 0.f, rB2 = 0.f;
    #pragma unroll
    for (int nb = 0; nb < 8; nb++) {
        int c0 = nb*8 + 2*q, c1 = c0 + 1;
        float v00 = gelu_exact(acc2[nb][0] + biasA[c0]);
        float v01 = gelu_exact(acc2[nb][1] + biasA[c1]);
        float v10 = gelu_exact(acc2[nb][2] + biasB[c0]);
        float v11 = gelu_exact(acc2[nb][3] + biasB[c1]);
        float w00 = sW2[c0*3+0], w01 = sW2[c0*3+1], w02 = sW2[c0*3+2];
        float w10 = sW2[c1*3+0], w11 = sW2[c1*3+1], w12 = sW2[c1*3+2];
        rA0 += v00*w00 + v01*w10;
        rA1 += v00*w01 + v01*w11;
        rA2 += v00*w02 + v01*w12;
        rB0 += v10*w00 + v11*w10;
        rB1 += v10*w01 + v11*w11;
        rB2 += v10*w02 + v11*w12;
    }
    #pragma unroll
    for (int off = 1; off <= 2; off <<= 1) {
        rA0 += __shfl_xor_sync(0xffffffffu, rA0, off);
        rA1 += __shfl_xor_sync(0xffffffffu, rA1, off);
        rA2 += __shfl_xor_sync(0xffffffffu, rA2, off);
        rB0 += __shfl_xor_sync(0xffffffffu, rB0, off);
        rB1 += __shfl_xor_sync(0xffffffffu, rB1, off);
        rB2 += __shfl_xor_sync(0xffffffffu, rB2, off);
    }
    if (q == 0) {
        float c0 = b2[0], c1 = b2[1], c2 = b2[2];
        float* oA = g_rgb + (size_t)pA * 3;
        oA[0] = 1.0f / (1.0f + expf(-(rA0 + c0)));
        oA[1] = 1.0f / (1.0f + expf(-(rA1 + c1)));
        oA[2] = 1.0f / (1.0f + expf(-(rA2 + c2)));
        float* oB = g_rgb + (size_t)pB * 3;
        oB[0] = 1.0f / (1.0f + expf(-(rB0 + c0)));
        oB[1] = 1.0f / (1.0f + expf(-(rB1 + c1)));
        oB[2] = 1.0f / (1.0f + expf(-(rB2 + c2)));
    }
}

__global__ void k_render(float* __restrict__ out_rgb, float* __restrict__ out_depth,
                         float* __restrict__ w) {
    int qq = blockIdx.x * blockDim.x + threadIdx.x;
    if (qq >= NRAYS) return;
    float T = 1.0f, a0 = 0.0f, a1 = 0.0f, a2 = 0.0f, dep = 0.0f;
    const float* rp = g_rgb + (size_t)qq * NS * 3;
    float* wp = w + (size_t)qq * NS;
    #pragma unroll 1
    for (int s = 0; s < NS; s++) {
        float sg = wp[s];
        float al = 1.0f - expf(-sg * DT);
        float wt = al * T;
        T *= (1.0f - al + 1e-10f);
        wp[s] = wt;
        dep += wt * (((float)s + 0.5f) * DT);
        a0 += wt * rp[s*3+0];
        a1 += wt * rp[s*3+1];
        a2 += wt * rp[s*3+2];
    }
    out_rgb[qq*3+0] = a0;
    out_rgb[qq*3+1] = a1;
    out_rgb[qq*3+2] = a2;
    out_depth[qq]   = dep;
}

extern "C" void kernel_launch(void* const* d_in, const int* in_sizes, int n_in,
                              void* d_out, int out_size) {
    const float* rays_o  = (const float*)d_in[0];
    const float* rays_d  = (const float*)d_in[1];
    const float* matrixs = (const float*)d_in[2];
    const float* vectors = (const float*)d_in[3];
    const float* w_mat   = (const float*)d_in[4];
    const float* b_mat   = (const float*)d_in[5];
    const float* w1      = (const float*)d_in[6];
    const float* b1      = (const float*)d_in[7];
    const float* w2      = (const float*)d_in[8];
    const float* b2      = (const float*)d_in[9];

    float* out       = (float*)d_out;
    float* out_rgb   = out;
    float* out_depth = out + NRAYS*3;
    float* out_w     = out + NRAYS*4;

    static bool attr_set = false;
    if (!attr_set) {
        cudaFuncSetAttribute(k_mlp, cudaFuncAttributeMaxDynamicSharedMemorySize,
                             SMEM_FLOATS * sizeof(float));
        attr_set = true;
    }

    k_transpose_mat<<<(3*BATCH*RES*RES*CH + 255)/256, 256>>>(matrixs);
    k_transpose_vec<<<(3*BATCH*RES*CH + 255)/256, 256>>>(vectors);
    k_bias<<<(NRAYS + 127)/128, 128>>>(rays_d, w1, b1);
    k_copy_w2<<<1, 192>>>(w2);
    k_sample<<<NPTS/128, 128>>>(rays_o, rays_d, out_w);
    k_mlp<<<NPTS/128, 256, SMEM_FLOATS * sizeof(float)>>>(w_mat, b_mat, w1, b2);
    k_render<<<(NRAYS + 127)/128, 128>>>(out_rgb, out_depth, out_w);
}

// round 4
// speedup vs baseline: 1.3320x; 1.3320x over previous
#include <cuda_runtime.h>
#include <math.h>
#include <stdint.h>

#define BATCH 4
#define RAYS  8192
#define NRAYS (BATCH*RAYS)          // 32768
#define NS    48
#define RES   48
#define CH    32
#define NPTS  (NRAYS*NS)            // 1572864
#define NTILES (NPTS/128)           // 12288

#define DT    0.03125f              // (FAR-NEAR)/NS

// ---------------- device scratch ----------------
__device__ __align__(16) float g_mat_t[3*BATCH*RES*RES*CH];
__device__ __align__(16) float g_vec_t[3*BATCH*RES*CH];
__device__ __align__(16) float g_rgb[(size_t)NPTS*3];
__device__ __align__(16) float g_f[(size_t)NPTS*72];
__device__ __align__(16) float g_bias[(size_t)NRAYS*64];

__device__ __forceinline__ float gelu_exact(float x) {
    return 0.5f * x * (1.0f + erff(x * 0.70710678118654752f));
}

__device__ __forceinline__ uint32_t f2tf32(float f) {
    uint32_t u;
    asm("cvt.rna.tf32.f32 %0, %1;" : "=r"(u) : "f"(f));
    return u;
}

__device__ __forceinline__ void mma_tf32(float d[4],
                                         uint32_t a0, uint32_t a1, uint32_t a2, uint32_t a3,
                                         uint32_t b0, uint32_t b1) {
    asm volatile("mma.sync.aligned.m16n8k8.row.col.f32.tf32.tf32.f32 "
                 "{%0,%1,%2,%3}, {%4,%5,%6,%7}, {%8,%9}, {%0,%1,%2,%3};"
                 : "+f"(d[0]), "+f"(d[1]), "+f"(d[2]), "+f"(d[3])
                 : "r"(a0), "r"(a1), "r"(a2), "r"(a3), "r"(b0), "r"(b1));
}

__device__ __forceinline__ void cp_async16(uint32_t saddr, const void* g) {
    asm volatile("cp.async.cg.shared.global [%0], [%1], 16;" :: "r"(saddr), "l"(g));
}
#define CP_COMMIT() asm volatile("cp.async.commit_group;")
#define CP_WAIT1()  asm volatile("cp.async.wait_group 1;")

// ---------------- prep kernels ----------------
__global__ void k_transpose_mat(const float* __restrict__ m) {
    int idx = blockIdx.x * blockDim.x + threadIdx.x;
    if (idx >= 3*BATCH*RES*RES*CH) return;
    int c   = idx % CH;
    int pix = (idx / CH) % (RES*RES);
    int ib  = idx / (CH*RES*RES);
    g_mat_t[idx] = m[((size_t)ib*CH + c)*(RES*RES) + pix];
}

__global__ void k_transpose_vec(const float* __restrict__ v) {
    int idx = blockIdx.x * blockDim.x + threadIdx.x;
    if (idx >= 3*BATCH*RES*CH) return;
    int c  = idx % CH;
    int r  = (idx / CH) % RES;
    int ib = idx / (CH*RES);
    g_vec_t[idx] = v[((size_t)ib*CH + c)*RES + r];
}

__global__ void k_bias(const float* __restrict__ rays_d,
                       const float* __restrict__ w1, const float* __restrict__ b1) {
    int q = blockIdx.x * blockDim.x + threadIdx.x;
    if (q >= NRAYS) return;
    float dx = rays_d[q*3+0], dy = rays_d[q*3+1], dz = rays_d[q*3+2];
    float inv = 1.0f / sqrtf(dx*dx + dy*dy + dz*dz);
    dx *= inv; dy *= inv; dz *= inv;
    float pe[27];
    pe[0] = dx; pe[1] = dy; pe[2] = dz;
    float f = 1.0f;
    #pragma unroll
    for (int fi = 0; fi < 4; fi++) {
        float s, c;
        sincosf(dx*f, &s, &c); pe[3 + fi*3 + 0] = s; pe[15 + fi*3 + 0] = c;
        sincosf(dy*f, &s, &c); pe[3 + fi*3 + 1] = s; pe[15 + fi*3 + 1] = c;
        sincosf(dz*f, &s, &c); pe[3 + fi*3 + 2] = s; pe[15 + fi*3 + 2] = c;
        f *= 2.0f;
    }
    float acc[64];
    #pragma unroll
    for (int j = 0; j < 64; j++) acc[j] = b1[j];
    #pragma unroll 1
    for (int k = 0; k < 27; k++) {
        float v = pe[k];
        const float* wr = w1 + (64 + k) * 64;
        #pragma unroll
        for (int j = 0; j < 64; j++) acc[j] += v * wr[j];
    }
    float* o = g_bias + (size_t)q * 64;
    #pragma unroll
    for (int j = 0; j < 64; j++) o[j] = acc[j];
}

// ---------------- sampling ----------------
__global__ __launch_bounds__(128)
void k_sample(const float* __restrict__ rays_o, const float* __restrict__ rays_d,
              float* __restrict__ out_sigma) {
    const int p   = blockIdx.x * 128 + threadIdx.x;
    const int s   = p % NS;
    const int ray = p / NS;
    const int b   = ray / RAYS;

    const float ox = rays_o[ray*3+0], oy = rays_o[ray*3+1], oz = rays_o[ray*3+2];
    const float dx = rays_d[ray*3+0], dy = rays_d[ray*3+1], dz = rays_d[ray*3+2];
    const float t  = ((float)s + 0.5f) * DT;

    const float px = ((ox + dx*t) + 0.8f) * 1.25f - 1.0f;
    const float py = ((oy + dy*t) + 0.8f) * 1.25f - 1.0f;
    const float pz = ((oz + dz*t) + 0.8f) * 1.25f - 1.0f;

    float sigma = 0.0f;
    float* fo = g_f + (size_t)p * 72;

    #pragma unroll 1
    for (int pl = 0; pl < 3; pl++) {
        const float cx = (pl == 0) ? px : ((pl == 1) ? pz : py);
        const float cy = (pl == 0) ? py : ((pl == 1) ? px : pz);
        const float cz = (pl == 0) ? pz : ((pl == 1) ? py : px);

        const float fx = (cx + 1.0f) * 23.5f;
        const float fy = (cy + 1.0f) * 23.5f;
        const float fz = (cz + 1.0f) * 23.5f;
        const float x0f = floorf(fx), y0f = floorf(fy), z0f = floorf(fz);
        const float wx = fx - x0f, wy = fy - y0f, wz = fz - z0f;
        const int ix0 = (int)x0f, iy0 = (int)y0f, iz0 = (int)z0f;

        const float mx0 = (ix0 >= 0  && ix0 <  RES)   ? 1.0f : 0.0f;
        const float mx1 = (ix0 >= -1 && ix0 <  RES-1) ? 1.0f : 0.0f;
        const float my0 = (iy0 >= 0  && iy0 <  RES)   ? 1.0f : 0.0f;
        const float my1 = (iy0 >= -1 && iy0 <  RES-1) ? 1.0f : 0.0f;
        const float mz0 = (iz0 >= 0  && iz0 <  RES)   ? 1.0f : 0.0f;
        const float mz1 = (iz0 >= -1 && iz0 <  RES-1) ? 1.0f : 0.0f;

        const int cx0 = min(max(ix0,   0), RES-1), cx1 = min(max(ix0+1, 0), RES-1);
        const int cy0 = min(max(iy0,   0), RES-1), cy1 = min(max(iy0+1, 0), RES-1);
        const int cz0 = min(max(iz0,   0), RES-1), cz1 = min(max(iz0+1, 0), RES-1);

        const float w00 = (1.0f-wx)*(1.0f-wy)*mx0*my0;
        const float w10 = wx*(1.0f-wy)*mx1*my0;
        const float w01 = (1.0f-wx)*wy*mx0*my1;
        const float w11 = wx*wy*mx1*my1;
        const float u0  = (1.0f-wz)*mz0;
        const float u1  = wz*mz1;

        const float* mb = g_mat_t + ((size_t)(pl*BATCH + b) * (RES*RES)) * CH;
        const float* vb = g_vec_t + ((size_t)(pl*BATCH + b) * RES) * CH;
        const float4* p00 = (const float4*)(mb + (size_t)(cy0*RES + cx0) * CH);
        const float4* p10 = (const float4*)(mb + (size_t)(cy0*RES + cx1) * CH);
        const float4* p01 = (const float4*)(mb + (size_t)(cy1*RES + cx0) * CH);
        const float4* p11 = (const float4*)(mb + (size_t)(cy1*RES + cx1) * CH);
        const float4* q0  = (const float4*)(vb + (size_t)cz0 * CH);
        const float4* q1  = (const float4*)(vb + (size_t)cz1 * CH);

        #pragma unroll 1
        for (int ch = 0; ch < 2; ch++) {
            float4 a = p00[ch], bb = p10[ch], c4 = p01[ch], d4 = p11[ch];
            float4 e = q0[ch],  f4 = q1[ch];
            float pf0 = w00*a.x + w10*bb.x + w01*c4.x + w11*d4.x;
            float pf1 = w00*a.y + w10*bb.y + w01*c4.y + w11*d4.y;
            float pf2 = w00*a.z + w10*bb.z + w01*c4.z + w11*d4.z;
            float pf3 = w00*a.w + w10*bb.w + w01*c4.w + w11*d4.w;
            float lf0 = u0*e.x + u1*f4.x;
            float lf1 = u0*e.y + u1*f4.y;
            float lf2 = u0*e.z + u1*f4.z;
            float lf3 = u0*e.w + u1*f4.w;
            sigma += pf0*lf0 + pf1*lf1 + pf2*lf2 + pf3*lf3;
        }
        #pragma unroll 1
        for (int ch = 2; ch < 8; ch++) {
            float4 a = p00[ch], bb = p10[ch], c4 = p01[ch], d4 = p11[ch];
            float4 e = q0[ch],  f4 = q1[ch];
            float4 g;
            g.x = gelu_exact((w00*a.x + w10*bb.x + w01*c4.x + w11*d4.x) * (u0*e.x + u1*f4.x));
            g.y = gelu_exact((w00*a.y + w10*bb.y + w01*c4.y + w11*d4.y) * (u0*e.y + u1*f4.y));
            g.z = gelu_exact((w00*a.z + w10*bb.z + w01*c4.z + w11*d4.z) * (u0*e.z + u1*f4.z));
            g.w = gelu_exact((w00*a.w + w10*bb.w + w01*c4.w + w11*d4.w) * (u0*e.w + u1*f4.w));
            *(float4*)(fo + pl*24 + (ch-2)*4) = g;
        }
    }
    out_sigma[p] = fmaxf(sigma, 0.0f);
}

// ---------------- persistent fused tensor-core MLP ------------------------------
// smem layout (floats): two F buffers then weights
#define F_BUF   9728                          // 128 rows x 76 pad
#define OF_B1H  (2*F_BUF)                     // 19456
#define OF_B1L  (OF_B1H + 5184)
#define OF_B2H  (OF_B1L + 5184)
#define OF_B2L  (OF_B2H + 4608)
#define OF_W2   (OF_B2L + 4608)
#define OF_BM   (OF_W2 + 192)
#define SMEM_FLOATS (OF_BM + 64)              // 39296 floats = 157184 B

__global__ __launch_bounds__(256)
void k_mlp(const float* __restrict__ w_mat, const float* __restrict__ b_mat,
           const float* __restrict__ w1, const float* __restrict__ w2,
           const float* __restrict__ b2) {
    extern __shared__ float sm[];
    float* sB1h = sm + OF_B1H;
    float* sB1l = sm + OF_B1L;
    float* sB2h = sm + OF_B2H;
    float* sB2l = sm + OF_B2L;
    float* sW2  = sm + OF_W2;
    float* sBm  = sm + OF_BM;

    const int tid  = threadIdx.x;
    const int lane = tid & 31;
    const int wid  = tid >> 5;
    const int q    = lane & 3;
    const int g    = lane >> 2;
    const uint32_t smem_base = (uint32_t)__cvta_generic_to_shared(sm);

    // ---- one-time weight conversion ----
    for (int i = tid; i < 72*64; i += 256) {
        int k = i >> 6, n = i & 63;
        float f = w_mat[i];
        float hi = __uint_as_float(f2tf32(f));
        sB1h[k*72 + n] = hi;
        sB1l[k*72 + n] = __uint_as_float(f2tf32(f - hi));
    }
    for (int i = tid; i < 64*64; i += 256) {
        int k = i >> 6, n = i & 63;
        float f = w1[i];
        float hi = __uint_as_float(f2tf32(f));
        sB2h[k*72 + n] = hi;
        sB2l[k*72 + n] = __uint_as_float(f2tf32(f - hi));
    }
    if (tid < 192) sW2[tid] = w2[tid];
    if (tid < 64)  sBm[tid] = b_mat[tid];

    const int m0 = wid * 16;
    int tile = blockIdx.x;
    const int stride = gridDim.x;

    // prologue: async copy of first tile into buf 0
    {
        const float* src = g_f + (size_t)tile * 128 * 72;
        for (int i = tid; i < 128*18; i += 256) {
            int row = i / 18, c = i % 18;
            cp_async16(smem_base + (row*76 + c*4)*4, src + row*72 + c*4);
        }
        CP_COMMIT();
    }

    int buf = 0;
    #pragma unroll 1
    for (; tile < NTILES; tile += stride, buf ^= 1) {
        // prefetch next tile into other buffer
        int nxt = tile + stride;
        if (nxt < NTILES) {
            const float* src = g_f + (size_t)nxt * 128 * 72;
            uint32_t dst = smem_base + (buf ^ 1) * F_BUF * 4;
            for (int i = tid; i < 128*18; i += 256) {
                int row = i / 18, c = i % 18;
                cp_async16(dst + (row*76 + c*4)*4, src + row*72 + c*4);
            }
        }
        CP_COMMIT();
        CP_WAIT1();                 // current buf's copy complete
        __syncthreads();            // (also covers one-time weight fill on iter 0)

        float* sF = sm + buf * F_BUF;
        const int pbase = tile * 128;

        // ---- GEMM1: acc = F @ Wmat + b_mat ----
        float acc[8][4];
        #pragma unroll
        for (int nb = 0; nb < 8; nb++) {
            float bv0 = sBm[nb*8 + 2*q];
            float bv1 = sBm[nb*8 + 2*q + 1];
            acc[nb][0] = bv0; acc[nb][1] = bv1; acc[nb][2] = bv0; acc[nb][3] = bv1;
        }
        #pragma unroll 1
        for (int kb = 0; kb < 9; kb++) {
            int ab = (m0 + g)*76 + kb*8 + q;
            float f0 = sF[ab], f1 = sF[ab + 8*76], f2 = sF[ab + 4], f3 = sF[ab + 8*76 + 4];
            uint32_t ah0 = f2tf32(f0), ah1 = f2tf32(f1), ah2 = f2tf32(f2), ah3 = f2tf32(f3);
            uint32_t al0 = f2tf32(f0 - __uint_as_float(ah0));
            uint32_t al1 = f2tf32(f1 - __uint_as_float(ah1));
            uint32_t al2 = f2tf32(f2 - __uint_as_float(ah2));
            uint32_t al3 = f2tf32(f3 - __uint_as_float(ah3));
            #pragma unroll
            for (int nb = 0; nb < 8; nb++) {
                int b0i = (kb*8 + q)*72 + nb*8 + g;
                int b1i = b0i + 4*72;
                uint32_t bh0 = __float_as_uint(sB1h[b0i]);
                uint32_t bh1 = __float_as_uint(sB1h[b1i]);
                uint32_t bl0 = __float_as_uint(sB1l[b0i]);
                uint32_t bl1 = __float_as_uint(sB1l[b1i]);
                mma_tf32(acc[nb], ah0, ah1, ah2, ah3, bh0, bh1);
                mma_tf32(acc[nb], ah0, ah1, ah2, ah3, bl0, bl1);
                mma_tf32(acc[nb], al0, al1, al2, al3, bh0, bh1);
            }
        }
        // ---- epilogue 1: gelu -> back into sF (warp-private rows) ----
        __syncwarp();
        #pragma unroll
        for (int nb = 0; nb < 8; nb++) {
            int c0 = nb*8 + 2*q;
            int rA = (m0 + g)*76, rB = rA + 8*76;
            sF[rA + c0]     = gelu_exact(acc[nb][0]);
            sF[rA + c0 + 1] = gelu_exact(acc[nb][1]);
            sF[rB + c0]     = gelu_exact(acc[nb][2]);
            sF[rB + c0 + 1] = gelu_exact(acc[nb][3]);
        }
        __syncwarp();
        // ---- GEMM2: acc2 = H @ W1a ----
        float acc2[8][4];
        #pragma unroll
        for (int nb = 0; nb < 8; nb++)
            acc2[nb][0] = acc2[nb][1] = acc2[nb][2] = acc2[nb][3] = 0.0f;
        #pragma unroll 1
        for (int kb = 0; kb < 8; kb++) {
            int ab = (m0 + g)*76 + kb*8 + q;
            float f0 = sF[ab], f1 = sF[ab + 8*76], f2 = sF[ab + 4], f3 = sF[ab + 8*76 + 4];
            uint32_t ah0 = f2tf32(f0), ah1 = f2tf32(f1), ah2 = f2tf32(f2), ah3 = f2tf32(f3);
            uint32_t al0 = f2tf32(f0 - __uint_as_float(ah0));
            uint32_t al1 = f2tf32(f1 - __uint_as_float(ah1));
            uint32_t al2 = f2tf32(f2 - __uint_as_float(ah2));
            uint32_t al3 = f2tf32(f3 - __uint_as_float(ah3));
            #pragma unroll
            for (int nb = 0; nb < 8; nb++) {
                int b0i = (kb*8 + q)*72 + nb*8 + g;
                int b1i = b0i + 4*72;
                uint32_t bh0 = __float_as_uint(sB2h[b0i]);
                uint32_t bh1 = __float_as_uint(sB2h[b1i]);
                uint32_t bl0 = __float_as_uint(sB2l[b0i]);
                uint32_t bl1 = __float_as_uint(sB2l[b1i]);
                mma_tf32(acc2[nb], ah0, ah1, ah2, ah3, bh0, bh1);
                mma_tf32(acc2[nb], ah0, ah1, ah2, ah3, bl0, bl1);
                mma_tf32(acc2[nb], al0, al1, al2, al3, bh0, bh1);
            }
        }
        // ---- epilogue 2: +rayBias, gelu, xW2, quad-reduce, sigmoid ----
        const int pA = pbase + m0 + g;
        const int pB = pA + 8;
        const float* biasA = g_bias + (size_t)(pA / NS) * 64;
        const float* biasB = g_bias + (size_t)(pB / NS) * 64;
        float rA0 = 0.f, rA1 = 0.f, rA2 = 0.f, rB0 = 0.f, rB1 = 0.f, rB2 = 0.f;
        #pragma unroll
        for (int nb = 0; nb < 8; nb++) {
            int c0 = nb*8 + 2*q, c1 = c0 + 1;
            float v00 = gelu_exact(acc2[nb][0] + biasA[c0]);
            float v01 = gelu_exact(acc2[nb][1] + biasA[c1]);
            float v10 = gelu_exact(acc2[nb][2] + biasB[c0]);
            float v11 = gelu_exact(acc2[nb][3] + biasB[c1]);
            float w00 = sW2[c0*3+0], w01 = sW2[c0*3+1], w02 = sW2[c0*3+2];
            float w10 = sW2[c1*3+0], w11 = sW2[c1*3+1], w12 = sW2[c1*3+2];
            rA0 += v00*w00 + v01*w10;
            rA1 += v00*w01 + v01*w11;
            rA2 += v00*w02 + v01*w12;
            rB0 += v10*w00 + v11*w10;
            rB1 += v10*w01 + v11*w11;
            rB2 += v10*w02 + v11*w12;
        }
        #pragma unroll
        for (int off = 1; off <= 2; off <<= 1) {
            rA0 += __shfl_xor_sync(0xffffffffu, rA0, off);
            rA1 += __shfl_xor_sync(0xffffffffu, rA1, off);
            rA2 += __shfl_xor_sync(0xffffffffu, rA2, off);
            rB0 += __shfl_xor_sync(0xffffffffu, rB0, off);
            rB1 += __shfl_xor_sync(0xffffffffu, rB1, off);
            rB2 += __shfl_xor_sync(0xffffffffu, rB2, off);
        }
        if (q == 0) {
            float c0 = b2[0], c1 = b2[1], c2 = b2[2];
            float* oA = g_rgb + (size_t)pA * 3;
            oA[0] = 1.0f / (1.0f + expf(-(rA0 + c0)));
            oA[1] = 1.0f / (1.0f + expf(-(rA1 + c1)));
            oA[2] = 1.0f / (1.0f + expf(-(rA2 + c2)));
            float* oB = g_rgb + (size_t)pB * 3;
            oB[0] = 1.0f / (1.0f + expf(-(rB0 + c0)));
            oB[1] = 1.0f / (1.0f + expf(-(rB1 + c1)));
            oB[2] = 1.0f / (1.0f + expf(-(rB2 + c2)));
        }
        __syncthreads();   // compute done before this buf is reused by prefetch
    }
}

// ---------------- per-ray compositing ----------------
__global__ void k_render(float* __restrict__ out_rgb, float* __restrict__ out_depth,
                         float* __restrict__ w) {
    int qq = blockIdx.x * blockDim.x + threadIdx.x;
    if (qq >= NRAYS) return;
    float T = 1.0f, a0 = 0.0f, a1 = 0.0f, a2 = 0.0f, dep = 0.0f;
    const float* rp = g_rgb + (size_t)qq * NS * 3;
    float* wp = w + (size_t)qq * NS;
    #pragma unroll 1
    for (int s = 0; s < NS; s++) {
        float sg = wp[s];
        float al = 1.0f - expf(-sg * DT);
        float wt = al * T;
        T *= (1.0f - al + 1e-10f);
        wp[s] = wt;
        dep += wt * (((float)s + 0.5f) * DT);
        a0 += wt * rp[s*3+0];
        a1 += wt * rp[s*3+1];
        a2 += wt * rp[s*3+2];
    }
    out_rgb[qq*3+0] = a0;
    out_rgb[qq*3+1] = a1;
    out_rgb[qq*3+2] = a2;
    out_depth[qq]   = dep;
}

// ---------------- launch ----------------
extern "C" void kernel_launch(void* const* d_in, const int* in_sizes, int n_in,
                              void* d_out, int out_size) {
    const float* rays_o  = (const float*)d_in[0];
    const float* rays_d  = (const float*)d_in[1];
    const float* matrixs = (const float*)d_in[2];
    const float* vectors = (const float*)d_in[3];
    const float* w_mat   = (const float*)d_in[4];
    const float* b_mat   = (const float*)d_in[5];
    const float* w1      = (const float*)d_in[6];
    const float* b1      = (const float*)d_in[7];
    const float* w2      = (const float*)d_in[8];
    const float* b2      = (const float*)d_in[9];

    float* out       = (float*)d_out;
    float* out_rgb   = out;
    float* out_depth = out + NRAYS*3;
    float* out_w     = out + NRAYS*4;

    static int nsm = 0;
    if (nsm == 0) {
        cudaDeviceProp prop;
        cudaGetDeviceProperties(&prop, 0);
        nsm = prop.multiProcessorCount;
        cudaFuncSetAttribute(k_mlp, cudaFuncAttributeMaxDynamicSharedMemorySize,
                             SMEM_FLOATS * sizeof(float));
    }

    k_transpose_mat<<<(3*BATCH*RES*RES*CH + 255)/256, 256>>>(matrixs);
    k_transpose_vec<<<(3*BATCH*RES*CH + 255)/256, 256>>>(vectors);
    k_bias<<<(NRAYS + 127)/128, 128>>>(rays_d, w1, b1);
    k_sample<<<NPTS/128, 128>>>(rays_o, rays_d, out_w);
    k_mlp<<<nsm, 256, SMEM_FLOATS * sizeof(float)>>>(w_mat, b_mat, w1, w2, b2);
    k_render<<<(NRAYS + 127)/128, 128>>>(out_rgb, out_depth, out_w);
}

// round 5
// speedup vs baseline: 1.5416x; 1.1574x over previous
#include <cuda_runtime.h>
#include <cuda_fp16.h>
#include <math.h>
#include <stdint.h>

#define BATCH 4
#define RAYS  8192
#define NRAYS (BATCH*RAYS)          // 32768
#define NS    48
#define RES   48
#define CH    32
#define NPTS  (NRAYS*NS)            // 1572864
#define NTILES (NPTS/128)           // 12288

#define DT    0.03125f

// ---------------- device scratch ----------------
__device__ __align__(16) __half g_mat_h[3*BATCH*RES*RES*CH];
__device__ __align__(16) __half g_vec_h[3*BATCH*RES*CH];
__device__ __align__(16) __half g_fh[(size_t)NPTS*72];      // staged features (fp16)
__device__ __align__(16) float  g_rgb[(size_t)NPTS*3];
__device__ __align__(16) float  g_bias[(size_t)NRAYS*64];

__device__ __forceinline__ float gelu_exact(float x) {
    return 0.5f * x * (1.0f + erff(x * 0.70710678118654752f));
}

__device__ __forceinline__ uint32_t f2tf32(float f) {
    uint32_t u;
    asm("cvt.rna.tf32.f32 %0, %1;" : "=r"(u) : "f"(f));
    return u;
}

__device__ __forceinline__ void mma_tf32(float d[4],
                                         uint32_t a0, uint32_t a1, uint32_t a2, uint32_t a3,
                                         uint32_t b0, uint32_t b1) {
    asm volatile("mma.sync.aligned.m16n8k8.row.col.f32.tf32.tf32.f32 "
                 "{%0,%1,%2,%3}, {%4,%5,%6,%7}, {%8,%9}, {%0,%1,%2,%3};"
                 : "+f"(d[0]), "+f"(d[1]), "+f"(d[2]), "+f"(d[3])
                 : "r"(a0), "r"(a1), "r"(a2), "r"(a3), "r"(b0), "r"(b1));
}

__device__ __forceinline__ void cp_async16(uint32_t saddr, const void* g) {
    asm volatile("cp.async.cg.shared.global [%0], [%1], 16;" :: "r"(saddr), "l"(g));
}
#define CP_COMMIT() asm volatile("cp.async.commit_group;")
#define CP_WAIT1()  asm volatile("cp.async.wait_group 1;")

// ---------------- prep: transposes to channel-last fp16 ----------------
__global__ void k_transpose_mat(const float* __restrict__ m) {
    int idx = blockIdx.x * blockDim.x + threadIdx.x;
    if (idx >= 3*BATCH*RES*RES*CH) return;
    int c   = idx % CH;
    int pix = (idx / CH) % (RES*RES);
    int ib  = idx / (CH*RES*RES);
    g_mat_h[idx] = __float2half_rn(m[((size_t)ib*CH + c)*(RES*RES) + pix]);
}

__global__ void k_transpose_vec(const float* __restrict__ v) {
    int idx = blockIdx.x * blockDim.x + threadIdx.x;
    if (idx >= 3*BATCH*RES*CH) return;
    int c  = idx % CH;
    int r  = (idx / CH) % RES;
    int ib = idx / (CH*RES);
    g_vec_h[idx] = __float2half_rn(v[((size_t)ib*CH + c)*RES + r]);
}

__global__ void k_bias(const float* __restrict__ rays_d,
                       const float* __restrict__ w1, const float* __restrict__ b1) {
    int q = blockIdx.x * blockDim.x + threadIdx.x;
    if (q >= NRAYS) return;
    float dx = rays_d[q*3+0], dy = rays_d[q*3+1], dz = rays_d[q*3+2];
    float inv = 1.0f / sqrtf(dx*dx + dy*dy + dz*dz);
    dx *= inv; dy *= inv; dz *= inv;
    float pe[27];
    pe[0] = dx; pe[1] = dy; pe[2] = dz;
    float f = 1.0f;
    #pragma unroll
    for (int fi = 0; fi < 4; fi++) {
        float s, c;
        sincosf(dx*f, &s, &c); pe[3 + fi*3 + 0] = s; pe[15 + fi*3 + 0] = c;
        sincosf(dy*f, &s, &c); pe[3 + fi*3 + 1] = s; pe[15 + fi*3 + 1] = c;
        sincosf(dz*f, &s, &c); pe[3 + fi*3 + 2] = s; pe[15 + fi*3 + 2] = c;
        f *= 2.0f;
    }
    float acc[64];
    #pragma unroll
    for (int j = 0; j < 64; j++) acc[j] = b1[j];
    #pragma unroll 1
    for (int k = 0; k < 27; k++) {
        float v = pe[k];
        const float* wr = w1 + (64 + k) * 64;
        #pragma unroll
        for (int j = 0; j < 64; j++) acc[j] += v * wr[j];
    }
    float* o = g_bias + (size_t)q * 64;
    #pragma unroll
    for (int j = 0; j < 64; j++) o[j] = acc[j];
}

// ---------------- sampling (fp16 grids, fp32 math) ----------------
__global__ __launch_bounds__(128)
void k_sample(const float* __restrict__ rays_o, const float* __restrict__ rays_d,
              float* __restrict__ out_sigma) {
    const int p   = blockIdx.x * 128 + threadIdx.x;
    const int s   = p % NS;
    const int ray = p / NS;
    const int b   = ray / RAYS;

    const float ox = rays_o[ray*3+0], oy = rays_o[ray*3+1], oz = rays_o[ray*3+2];
    const float dx = rays_d[ray*3+0], dy = rays_d[ray*3+1], dz = rays_d[ray*3+2];
    const float t  = ((float)s + 0.5f) * DT;

    const float px = ((ox + dx*t) + 0.8f) * 1.25f - 1.0f;
    const float py = ((oy + dy*t) + 0.8f) * 1.25f - 1.0f;
    const float pz = ((oz + dz*t) + 0.8f) * 1.25f - 1.0f;

    float sigma = 0.0f;
    __half* fo = g_fh + (size_t)p * 72;

    #pragma unroll 1
    for (int pl = 0; pl < 3; pl++) {
        const float cx = (pl == 0) ? px : ((pl == 1) ? pz : py);
        const float cy = (pl == 0) ? py : ((pl == 1) ? px : pz);
        const float cz = (pl == 0) ? pz : ((pl == 1) ? py : px);

        const float fx = (cx + 1.0f) * 23.5f;
        const float fy = (cy + 1.0f) * 23.5f;
        const float fz = (cz + 1.0f) * 23.5f;
        const float x0f = floorf(fx), y0f = floorf(fy), z0f = floorf(fz);
        const float wx = fx - x0f, wy = fy - y0f, wz = fz - z0f;
        const int ix0 = (int)x0f, iy0 = (int)y0f, iz0 = (int)z0f;

        const float mx0 = (ix0 >= 0  && ix0 <  RES)   ? 1.0f : 0.0f;
        const float mx1 = (ix0 >= -1 && ix0 <  RES-1) ? 1.0f : 0.0f;
        const float my0 = (iy0 >= 0  && iy0 <  RES)   ? 1.0f : 0.0f;
        const float my1 = (iy0 >= -1 && iy0 <  RES-1) ? 1.0f : 0.0f;
        const float mz0 = (iz0 >= 0  && iz0 <  RES)   ? 1.0f : 0.0f;
        const float mz1 = (iz0 >= -1 && iz0 <  RES-1) ? 1.0f : 0.0f;

        const int cx0 = min(max(ix0,   0), RES-1), cx1 = min(max(ix0+1, 0), RES-1);
        const int cy0 = min(max(iy0,   0), RES-1), cy1 = min(max(iy0+1, 0), RES-1);
        const int cz0 = min(max(iz0,   0), RES-1), cz1 = min(max(iz0+1, 0), RES-1);

        const float w00 = (1.0f-wx)*(1.0f-wy)*mx0*my0;
        const float w10 = wx*(1.0f-wy)*mx1*my0;
        const float w01 = (1.0f-wx)*wy*mx0*my1;
        const float w11 = wx*wy*mx1*my1;
        const float u0  = (1.0f-wz)*mz0;
        const float u1  = wz*mz1;

        const __half* mb = g_mat_h + ((size_t)(pl*BATCH + b) * (RES*RES)) * CH;
        const __half* vb = g_vec_h + ((size_t)(pl*BATCH + b) * RES) * CH;
        const uint4* p00 = (const uint4*)(mb + (size_t)(cy0*RES + cx0) * CH);
        const uint4* p10 = (const uint4*)(mb + (size_t)(cy0*RES + cx1) * CH);
        const uint4* p01 = (const uint4*)(mb + (size_t)(cy1*RES + cx0) * CH);
        const uint4* p11 = (const uint4*)(mb + (size_t)(cy1*RES + cx1) * CH);
        const uint4* q0  = (const uint4*)(vb + (size_t)cz0 * CH);
        const uint4* q1  = (const uint4*)(vb + (size_t)cz1 * CH);

        // each uint4 chunk = 8 fp16 channels
        #pragma unroll 1
        for (int cc = 0; cc < 4; cc++) {
            uint4 ua = p00[cc], ub = p10[cc], uc = p01[cc], ud = p11[cc];
            uint4 ue = q0[cc],  uf = q1[cc];
            const __half2* ha = (const __half2*)&ua;
            const __half2* hb = (const __half2*)&ub;
            const __half2* hc = (const __half2*)&uc;
            const __half2* hd = (const __half2*)&ud;
            const __half2* he = (const __half2*)&ue;
            const __half2* hf = (const __half2*)&uf;
            float vals[8];
            #pragma unroll
            for (int j = 0; j < 4; j++) {
                float2 fa = __half22float2(ha[j]);
                float2 fb = __half22float2(hb[j]);
                float2 fc = __half22float2(hc[j]);
                float2 fd = __half22float2(hd[j]);
                float2 fe = __half22float2(he[j]);
                float2 ff = __half22float2(hf[j]);
                float pf0 = w00*fa.x + w10*fb.x + w01*fc.x + w11*fd.x;
                float pf1 = w00*fa.y + w10*fb.y + w01*fc.y + w11*fd.y;
                float lf0 = u0*fe.x + u1*ff.x;
                float lf1 = u0*fe.y + u1*ff.y;
                vals[j*2]   = pf0 * lf0;
                vals[j*2+1] = pf1 * lf1;
            }
            if (cc == 0) {
                #pragma unroll
                for (int j = 0; j < 8; j++) sigma += vals[j];
            } else {
                __half2* dst = (__half2*)(fo + pl*24 + (cc-1)*8);
                #pragma unroll
                for (int j = 0; j < 4; j++) {
                    dst[j] = __floats2half2_rn(gelu_exact(vals[j*2]),
                                               gelu_exact(vals[j*2+1]));
                }
            }
        }
    }
    out_sigma[p] = fmaxf(sigma, 0.0f);
}

// ---------------- persistent fused tensor-core MLP ------------------------------
// F buffers hold fp16 rows: 128 rows x 80-half pitch (160 B)
#define F_BUF_FLOATS 5120                 // 128*80 halves / 2
#define F_BUF_BYTES  20480
#define OF_B1   (2*F_BUF_FLOATS)          // 10240, packed [9][4][260]
#define OF_B2   (OF_B1 + 9*4*260)         // + 9360 -> 19600, packed [8][4][260]
#define OF_W2   (OF_B2 + 8*4*260)         // + 8320 -> 27920
#define OF_BM   (OF_W2 + 192)             // 28112
#define SMEM_FLOATS (OF_BM + 64)          // 28176 floats = 112704 B

__global__ __launch_bounds__(256)
void k_mlp(const float* __restrict__ w_mat, const float* __restrict__ b_mat,
           const float* __restrict__ w1, const float* __restrict__ w2,
           const float* __restrict__ b2) {
    extern __shared__ float sm[];
    float* sB1 = sm + OF_B1;
    float* sB2 = sm + OF_B2;
    float* sW2 = sm + OF_W2;
    float* sBm = sm + OF_BM;

    const int tid  = threadIdx.x;
    const int lane = tid & 31;
    const int wid  = tid >> 5;
    const int q    = lane & 3;
    const int g    = lane >> 2;
    const uint32_t smem_base = (uint32_t)__cvta_generic_to_shared(sm);

    // ---- one-time packed weight conversion: {hi(k), hi(k+4), lo(k), lo(k+4)} ----
    for (int i = tid; i < 9*4*64; i += 256) {
        int kb = i >> 8, qq = (i >> 6) & 3, n = i & 63;
        int k0 = kb*8 + qq;
        float v0 = w_mat[k0*64 + n];
        float v1 = w_mat[(k0+4)*64 + n];
        float h0 = __uint_as_float(f2tf32(v0));
        float h1 = __uint_as_float(f2tf32(v1));
        float* dst = sB1 + (kb*4 + qq)*260 + n*4;
        dst[0] = h0; dst[1] = h1;
        dst[2] = __uint_as_float(f2tf32(v0 - h0));
        dst[3] = __uint_as_float(f2tf32(v1 - h1));
    }
    for (int i = tid; i < 8*4*64; i += 256) {
        int kb = i >> 8, qq = (i >> 6) & 3, n = i & 63;
        int k0 = kb*8 + qq;
        float v0 = w1[k0*64 + n];
        float v1 = w1[(k0+4)*64 + n];
        float h0 = __uint_as_float(f2tf32(v0));
        float h1 = __uint_as_float(f2tf32(v1));
        float* dst = sB2 + (kb*4 + qq)*260 + n*4;
        dst[0] = h0; dst[1] = h1;
        dst[2] = __uint_as_float(f2tf32(v0 - h0));
        dst[3] = __uint_as_float(f2tf32(v1 - h1));
    }
    if (tid < 192) sW2[tid] = w2[tid];
    if (tid < 64)  sBm[tid] = b_mat[tid];

    const int m0 = wid * 16;
    int tile = blockIdx.x;
    const int stride = gridDim.x;

    // prologue: async copy first tile into buf 0 (9 x 16B chunks per 72-half row)
    {
        const __half* src = g_fh + (size_t)tile * 128 * 72;
        for (int i = tid; i < 128*9; i += 256) {
            int row = i / 9, c = i % 9;
            cp_async16(smem_base + row*160 + c*16, src + row*72 + c*8);
        }
        CP_COMMIT();
    }

    int buf = 0;
    #pragma unroll 1
    for (; tile < NTILES; tile += stride, buf ^= 1) {
        int nxt = tile + stride;
        if (nxt < NTILES) {
            const __half* src = g_fh + (size_t)nxt * 128 * 72;
            uint32_t dst = smem_base + (buf ^ 1) * F_BUF_BYTES;
            for (int i = tid; i < 128*9; i += 256) {
                int row = i / 9, c = i % 9;
                cp_async16(dst + row*160 + c*16, src + row*72 + c*8);
            }
        }
        CP_COMMIT();
        CP_WAIT1();
        __syncthreads();

        __half* sF = (__half*)(sm + buf * F_BUF_FLOATS);
        const int pbase = tile * 128;

        // ---- GEMM1: acc = F @ Wmat + b_mat  (A fp16-exact tf32, B hi+lo) ----
        float acc[8][4];
        #pragma unroll
        for (int nb = 0; nb < 8; nb++) {
            float bv0 = sBm[nb*8 + 2*q];
            float bv1 = sBm[nb*8 + 2*q + 1];
            acc[nb][0] = bv0; acc[nb][1] = bv1; acc[nb][2] = bv0; acc[nb][3] = bv1;
        }
        #pragma unroll 1
        for (int kb = 0; kb < 9; kb++) {
            int rA = (m0 + g)*80 + kb*8 + q;
            uint32_t a0 = __float_as_uint(__half2float(sF[rA]));
            uint32_t a1 = __float_as_uint(__half2float(sF[rA + 8*80]));
            uint32_t a2 = __float_as_uint(__half2float(sF[rA + 4]));
            uint32_t a3 = __float_as_uint(__half2float(sF[rA + 8*80 + 4]));
            const float* brow = sB1 + (kb*4 + q)*260 + g*4;
            #pragma unroll
            for (int nb = 0; nb < 8; nb++) {
                float4 bv = *(const float4*)(brow + nb*32);
                mma_tf32(acc[nb], a0, a1, a2, a3,
                         __float_as_uint(bv.x), __float_as_uint(bv.y));
                mma_tf32(acc[nb], a0, a1, a2, a3,
                         __float_as_uint(bv.z), __float_as_uint(bv.w));
            }
        }
        // ---- epilogue 1: gelu -> fp16 back into sF (warp-private rows) ----
        __syncwarp();
        #pragma unroll
        for (int nb = 0; nb < 8; nb++) {
            int c0 = nb*8 + 2*q;
            __half2* dA = (__half2*)(sF + (m0 + g)*80 + c0);
            __half2* dB = (__half2*)(sF + (m0 + g + 8)*80 + c0);
            *dA = __floats2half2_rn(gelu_exact(acc[nb][0]), gelu_exact(acc[nb][1]));
            *dB = __floats2half2_rn(gelu_exact(acc[nb][2]), gelu_exact(acc[nb][3]));
        }
        __syncwarp();
        // ---- GEMM2: acc2 = H @ W1a ----
        float acc2[8][4];
        #pragma unroll
        for (int nb = 0; nb < 8; nb++)
            acc2[nb][0] = acc2[nb][1] = acc2[nb][2] = acc2[nb][3] = 0.0f;
        #pragma unroll 1
        for (int kb = 0; kb < 8; kb++) {
            int rA = (m0 + g)*80 + kb*8 + q;
            uint32_t a0 = __float_as_uint(__half2float(sF[rA]));
            uint32_t a1 = __float_as_uint(__half2float(sF[rA + 8*80]));
            uint32_t a2 = __float_as_uint(__half2float(sF[rA + 4]));
            uint32_t a3 = __float_as_uint(__half2float(sF[rA + 8*80 + 4]));
            const float* brow = sB2 + (kb*4 + q)*260 + g*4;
            #pragma unroll
            for (int nb = 0; nb < 8; nb++) {
                float4 bv = *(const float4*)(brow + nb*32);
                mma_tf32(acc2[nb], a0, a1, a2, a3,
                         __float_as_uint(bv.x), __float_as_uint(bv.y));
                mma_tf32(acc2[nb], a0, a1, a2, a3,
                         __float_as_uint(bv.z), __float_as_uint(bv.w));
            }
        }
        // ---- epilogue 2: +rayBias, gelu, xW2, quad-reduce, sigmoid ----
        const int pA = pbase + m0 + g;
        const int pB = pA + 8;
        const float* biasA = g_bias + (size_t)(pA / NS) * 64;
        const float* biasB = g_bias + (size_t)(pB / NS) * 64;
        float rA0 = 0.f, rA1 = 0.f, rA2 = 0.f, rB0 = 0.f, rB1 = 0.f, rB2 = 0.f;
        #pragma unroll
        for (int nb = 0; nb < 8; nb++) {
            int c0 = nb*8 + 2*q, c1 = c0 + 1;
            float v00 = gelu_exact(acc2[nb][0] + biasA[c0]);
            float v01 = gelu_exact(acc2[nb][1] + biasA[c1]);
            float v10 = gelu_exact(acc2[nb][2] + biasB[c0]);
            float v11 = gelu_exact(acc2[nb][3] + biasB[c1]);
            float w00 = sW2[c0*3+0], w01 = sW2[c0*3+1], w02 = sW2[c0*3+2];
            float w10 = sW2[c1*3+0], w11 = sW2[c1*3+1], w12 = sW2[c1*3+2];
            rA0 += v00*w00 + v01*w10;
            rA1 += v00*w01 + v01*w11;
            rA2 += v00*w02 + v01*w12;
            rB0 += v10*w00 + v11*w10;
            rB1 += v10*w01 + v11*w11;
            rB2 += v10*w02 + v11*w12;
        }
        #pragma unroll
        for (int off = 1; off <= 2; off <<= 1) {
            rA0 += __shfl_xor_sync(0xffffffffu, rA0, off);
            rA1 += __shfl_xor_sync(0xffffffffu, rA1, off);
            rA2 += __shfl_xor_sync(0xffffffffu, rA2, off);
            rB0 += __shfl_xor_sync(0xffffffffu, rB0, off);
            rB1 += __shfl_xor_sync(0xffffffffu, rB1, off);
            rB2 += __shfl_xor_sync(0xffffffffu, rB2, off);
        }
        if (q == 0) {
            float c0 = b2[0], c1 = b2[1], c2 = b2[2];
            float* oA = g_rgb + (size_t)pA * 3;
            oA[0] = 1.0f / (1.0f + expf(-(rA0 + c0)));
            oA[1] = 1.0f / (1.0f + expf(-(rA1 + c1)));
            oA[2] = 1.0f / (1.0f + expf(-(rA2 + c2)));
            float* oB = g_rgb + (size_t)pB * 3;
            oB[0] = 1.0f / (1.0f + expf(-(rB0 + c0)));
            oB[1] = 1.0f / (1.0f + expf(-(rB1 + c1)));
            oB[2] = 1.0f / (1.0f + expf(-(rB2 + c2)));
        }
        __syncthreads();
    }
}

// ---------------- per-ray compositing ----------------
__global__ void k_render(float* __restrict__ out_rgb, float* __restrict__ out_depth,
                         float* __restrict__ w) {
    int qq = blockIdx.x * blockDim.x + threadIdx.x;
    if (qq >= NRAYS) return;
    float T = 1.0f, a0 = 0.0f, a1 = 0.0f, a2 = 0.0f, dep = 0.0f;
    const float* rp = g_rgb + (size_t)qq * NS * 3;
    float* wp = w + (size_t)qq * NS;
    #pragma unroll 1
    for (int s = 0; s < NS; s++) {
        float sg = wp[s];
        float al = 1.0f - expf(-sg * DT);
        float wt = al * T;
        T *= (1.0f - al + 1e-10f);
        wp[s] = wt;
        dep += wt * (((float)s + 0.5f) * DT);
        a0 += wt * rp[s*3+0];
        a1 += wt * rp[s*3+1];
        a2 += wt * rp[s*3+2];
    }
    out_rgb[qq*3+0] = a0;
    out_rgb[qq*3+1] = a1;
    out_rgb[qq*3+2] = a2;
    out_depth[qq]   = dep;
}

// ---------------- launch ----------------
extern "C" void kernel_launch(void* const* d_in, const int* in_sizes, int n_in,
                              void* d_out, int out_size) {
    const float* rays_o  = (const float*)d_in[0];
    const float* rays_d  = (const float*)d_in[1];
    const float* matrixs = (const float*)d_in[2];
    const float* vectors = (const float*)d_in[3];
    const float* w_mat   = (const float*)d_in[4];
    const float* b_mat   = (const float*)d_in[5];
    const float* w1      = (const float*)d_in[6];
    const float* b1      = (const float*)d_in[7];
    const float* w2      = (const float*)d_in[8];
    const float* b2      = (const float*)d_in[9];

    float* out       = (float*)d_out;
    float* out_rgb   = out;
    float* out_depth = out + NRAYS*3;
    float* out_w     = out + NRAYS*4;

    static int nsm = 0;
    if (nsm == 0) {
        cudaDeviceProp prop;
        cudaGetDeviceProperties(&prop, 0);
        nsm = prop.multiProcessorCount;
        cudaFuncSetAttribute(k_mlp, cudaFuncAttributeMaxDynamicSharedMemorySize,
                             SMEM_FLOATS * sizeof(float));
    }

    k_transpose_mat<<<(3*BATCH*RES*RES*CH + 255)/256, 256>>>(matrixs);
    k_transpose_vec<<<(3*BATCH*RES*CH + 255)/256, 256>>>(vectors);
    k_bias<<<(NRAYS + 127)/128, 128>>>(rays_d, w1, b1);
    k_sample<<<NPTS/128, 128>>>(rays_o, rays_d, out_w);
    k_mlp<<<nsm, 256, SMEM_FLOATS * sizeof(float)>>>(w_mat, b_mat, w1, w2, b2);
    k_render<<<(NRAYS + 127)/128, 128>>>(out_rgb, out_depth, out_w);
}

// round 6
// speedup vs baseline: 2.3622x; 1.5323x over previous
#include <cuda_runtime.h>
#include <cuda_fp16.h>
#include <math.h>
#include <stdint.h>

#define BATCH 4
#define RAYS  8192
#define NRAYS (BATCH*RAYS)          // 32768
#define NS    48
#define RES   48
#define CH    32
#define NPTS  (NRAYS*NS)            // 1572864
#define NTILES (NPTS/128)           // 12288

#define DT    0.03125f

// ---------------- device scratch ----------------
__device__ __align__(16) __half g_mat_h[3*BATCH*RES*RES*CH];
__device__ __align__(16) __half g_vec_h[3*BATCH*RES*CH];
__device__ __align__(16) __half g_fh[(size_t)NPTS*72];      // staged features (fp16)
__device__ __align__(16) float  g_rgb[(size_t)NPTS*3];
__device__ __align__(16) float  g_bias[(size_t)NRAYS*64];

__device__ __forceinline__ float gelu_exact(float x) {
    return 0.5f * x * (1.0f + erff(x * 0.70710678118654752f));
}

__device__ __forceinline__ void mma_f16(float d[4],
                                        uint32_t a0, uint32_t a1, uint32_t a2, uint32_t a3,
                                        uint32_t b0, uint32_t b1) {
    asm volatile("mma.sync.aligned.m16n8k16.row.col.f32.f16.f16.f32 "
                 "{%0,%1,%2,%3}, {%4,%5,%6,%7}, {%8,%9}, {%0,%1,%2,%3};"
                 : "+f"(d[0]), "+f"(d[1]), "+f"(d[2]), "+f"(d[3])
                 : "r"(a0), "r"(a1), "r"(a2), "r"(a3), "r"(b0), "r"(b1));
}

__device__ __forceinline__ void cp_async16(uint32_t saddr, const void* g) {
    asm volatile("cp.async.cg.shared.global [%0], [%1], 16;" :: "r"(saddr), "l"(g));
}
#define CP_COMMIT() asm volatile("cp.async.commit_group;")
#define CP_WAIT1()  asm volatile("cp.async.wait_group 1;")

// ---------------- prep: transposes to channel-last fp16 ----------------
__global__ void k_transpose_mat(const float* __restrict__ m) {
    int idx = blockIdx.x * blockDim.x + threadIdx.x;
    if (idx >= 3*BATCH*RES*RES*CH) return;
    int c   = idx % CH;
    int pix = (idx / CH) % (RES*RES);
    int ib  = idx / (CH*RES*RES);
    g_mat_h[idx] = __float2half_rn(m[((size_t)ib*CH + c)*(RES*RES) + pix]);
}

__global__ void k_transpose_vec(const float* __restrict__ v) {
    int idx = blockIdx.x * blockDim.x + threadIdx.x;
    if (idx >= 3*BATCH*RES*CH) return;
    int c  = idx % CH;
    int r  = (idx / CH) % RES;
    int ib = idx / (CH*RES);
    g_vec_h[idx] = __float2half_rn(v[((size_t)ib*CH + c)*RES + r]);
}

__global__ void k_bias(const float* __restrict__ rays_d,
                       const float* __restrict__ w1, const float* __restrict__ b1) {
    int q = blockIdx.x * blockDim.x + threadIdx.x;
    if (q >= NRAYS) return;
    float dx = rays_d[q*3+0], dy = rays_d[q*3+1], dz = rays_d[q*3+2];
    float inv = 1.0f / sqrtf(dx*dx + dy*dy + dz*dz);
    dx *= inv; dy *= inv; dz *= inv;
    float pe[27];
    pe[0] = dx; pe[1] = dy; pe[2] = dz;
    float f = 1.0f;
    #pragma unroll
    for (int fi = 0; fi < 4; fi++) {
        float s, c;
        sincosf(dx*f, &s, &c); pe[3 + fi*3 + 0] = s; pe[15 + fi*3 + 0] = c;
        sincosf(dy*f, &s, &c); pe[3 + fi*3 + 1] = s; pe[15 + fi*3 + 1] = c;
        sincosf(dz*f, &s, &c); pe[3 + fi*3 + 2] = s; pe[15 + fi*3 + 2] = c;
        f *= 2.0f;
    }
    float acc[64];
    #pragma unroll
    for (int j = 0; j < 64; j++) acc[j] = b1[j];
    #pragma unroll 1
    for (int k = 0; k < 27; k++) {
        float v = pe[k];
        const float* wr = w1 + (64 + k) * 64;
        #pragma unroll
        for (int j = 0; j < 64; j++) acc[j] += v * wr[j];
    }
    float* o = g_bias + (size_t)q * 64;
    #pragma unroll
    for (int j = 0; j < 64; j++) o[j] = acc[j];
}

// ---------------- sampling (fp16 grids, fp32 math) ----------------
__global__ __launch_bounds__(128)
void k_sample(const float* __restrict__ rays_o, const float* __restrict__ rays_d,
              float* __restrict__ out_sigma) {
    const int p   = blockIdx.x * 128 + threadIdx.x;
    const int s   = p % NS;
    const int ray = p / NS;
    const int b   = ray / RAYS;

    const float ox = rays_o[ray*3+0], oy = rays_o[ray*3+1], oz = rays_o[ray*3+2];
    const float dx = rays_d[ray*3+0], dy = rays_d[ray*3+1], dz = rays_d[ray*3+2];
    const float t  = ((float)s + 0.5f) * DT;

    const float px = ((ox + dx*t) + 0.8f) * 1.25f - 1.0f;
    const float py = ((oy + dy*t) + 0.8f) * 1.25f - 1.0f;
    const float pz = ((oz + dz*t) + 0.8f) * 1.25f - 1.0f;

    float sigma = 0.0f;
    __half* fo = g_fh + (size_t)p * 72;

    #pragma unroll 1
    for (int pl = 0; pl < 3; pl++) {
        const float cx = (pl == 0) ? px : ((pl == 1) ? pz : py);
        const float cy = (pl == 0) ? py : ((pl == 1) ? px : pz);
        const float cz = (pl == 0) ? pz : ((pl == 1) ? py : px);

        const float fx = (cx + 1.0f) * 23.5f;
        const float fy = (cy + 1.0f) * 23.5f;
        const float fz = (cz + 1.0f) * 23.5f;
        const float x0f = floorf(fx), y0f = floorf(fy), z0f = floorf(fz);
        const float wx = fx - x0f, wy = fy - y0f, wz = fz - z0f;
        const int ix0 = (int)x0f, iy0 = (int)y0f, iz0 = (int)z0f;

        const float mx0 = (ix0 >= 0  && ix0 <  RES)   ? 1.0f : 0.0f;
        const float mx1 = (ix0 >= -1 && ix0 <  RES-1) ? 1.0f : 0.0f;
        const float my0 = (iy0 >= 0  && iy0 <  RES)   ? 1.0f : 0.0f;
        const float my1 = (iy0 >= -1 && iy0 <  RES-1) ? 1.0f : 0.0f;
        const float mz0 = (iz0 >= 0  && iz0 <  RES)   ? 1.0f : 0.0f;
        const float mz1 = (iz0 >= -1 && iz0 <  RES-1) ? 1.0f : 0.0f;

        const int cx0 = min(max(ix0,   0), RES-1), cx1 = min(max(ix0+1, 0), RES-1);
        const int cy0 = min(max(iy0,   0), RES-1), cy1 = min(max(iy0+1, 0), RES-1);
        const int cz0 = min(max(iz0,   0), RES-1), cz1 = min(max(iz0+1, 0), RES-1);

        const float w00 = (1.0f-wx)*(1.0f-wy)*mx0*my0;
        const float w10 = wx*(1.0f-wy)*mx1*my0;
        const float w01 = (1.0f-wx)*wy*mx0*my1;
        const float w11 = wx*wy*mx1*my1;
        const float u0  = (1.0f-wz)*mz0;
        const float u1  = wz*mz1;

        const __half* mb = g_mat_h + ((size_t)(pl*BATCH + b) * (RES*RES)) * CH;
        const __half* vb = g_vec_h + ((size_t)(pl*BATCH + b) * RES) * CH;
        const uint4* p00 = (const uint4*)(mb + (size_t)(cy0*RES + cx0) * CH);
        const uint4* p10 = (const uint4*)(mb + (size_t)(cy0*RES + cx1) * CH);
        const uint4* p01 = (const uint4*)(mb + (size_t)(cy1*RES + cx0) * CH);
        const uint4* p11 = (const uint4*)(mb + (size_t)(cy1*RES + cx1) * CH);
        const uint4* q0  = (const uint4*)(vb + (size_t)cz0 * CH);
        const uint4* q1  = (const uint4*)(vb + (size_t)cz1 * CH);

        #pragma unroll 1
        for (int cc = 0; cc < 4; cc++) {
            uint4 ua = p00[cc], ub = p10[cc], uc = p01[cc], ud = p11[cc];
            uint4 ue = q0[cc],  uf = q1[cc];
            const __half2* ha = (const __half2*)&ua;
            const __half2* hb = (const __half2*)&ub;
            const __half2* hc = (const __half2*)&uc;
            const __half2* hd = (const __half2*)&ud;
            const __half2* he = (const __half2*)&ue;
            const __half2* hf = (const __half2*)&uf;
            float vals[8];
            #pragma unroll
            for (int j = 0; j < 4; j++) {
                float2 fa = __half22float2(ha[j]);
                float2 fb = __half22float2(hb[j]);
                float2 fc = __half22float2(hc[j]);
                float2 fd = __half22float2(hd[j]);
                float2 fe = __half22float2(he[j]);
                float2 ff = __half22float2(hf[j]);
                float pf0 = w00*fa.x + w10*fb.x + w01*fc.x + w11*fd.x;
                float pf1 = w00*fa.y + w10*fb.y + w01*fc.y + w11*fd.y;
                float lf0 = u0*fe.x + u1*ff.x;
                float lf1 = u0*fe.y + u1*ff.y;
                vals[j*2]   = pf0 * lf0;
                vals[j*2+1] = pf1 * lf1;
            }
            if (cc == 0) {
                #pragma unroll
                for (int j = 0; j < 8; j++) sigma += vals[j];
            } else {
                __half2* dst = (__half2*)(fo + pl*24 + (cc-1)*8);
                #pragma unroll
                for (int j = 0; j < 4; j++) {
                    dst[j] = __floats2half2_rn(gelu_exact(vals[j*2]),
                                               gelu_exact(vals[j*2+1]));
                }
            }
        }
    }
    out_sigma[p] = fmaxf(sigma, 0.0f);
}

// ---------------- persistent fused fp16 tensor-core MLP -------------------------
// F buffers: 128 rows x 80-half pitch (160 B); cols 72..79 stay zero forever.
#define F_BUF_FLOATS 5120                 // 128*80/2
#define F_BUF_BYTES  20480
// B layout: [kb][q] rows of 64 uint4 entries, row stride 264 words (conflict-free)
#define OF_B1   (2*F_BUF_FLOATS)          // 10240
#define OF_B2   (OF_B1 + 5*4*264)         // +5280 -> 15520
#define OF_W2   (OF_B2 + 4*4*264)         // +4224 -> 19744
#define OF_BM   (OF_W2 + 192)             // 19936
#define SMEM_FLOATS (OF_BM + 64)          // 20000 floats = 80000 B

__device__ __forceinline__ uint32_t pack_h2(float lo, float hi) {
    __half2 h = __floats2half2_rn(lo, hi);
    return *(uint32_t*)&h;
}

__global__ __launch_bounds__(256)
void k_mlp(const float* __restrict__ w_mat, const float* __restrict__ b_mat,
           const float* __restrict__ w1, const float* __restrict__ w2,
           const float* __restrict__ b2) {
    extern __shared__ float sm[];
    float* sB1 = sm + OF_B1;
    float* sB2 = sm + OF_B2;
    float* sW2 = sm + OF_W2;
    float* sBm = sm + OF_BM;

    const int tid  = threadIdx.x;
    const int lane = tid & 31;
    const int wid  = tid >> 5;
    const int q    = lane & 3;
    const int g    = lane >> 2;
    const uint32_t smem_base = (uint32_t)__cvta_generic_to_shared(sm);

    // ---- zero the fixed pad (cols 72..79) of both F buffers ----
    for (int i = tid; i < 256; i += 256) {
        int bufr = i >> 7, row = i & 127;
        *(uint4*)((char*)sm + bufr*F_BUF_BYTES + row*160 + 144) = make_uint4(0,0,0,0);
    }

    // ---- one-time fp16 hi/lo weight packing ----
    // entry(kb,q,n) = { h2(w[k0],w[k0+1]), h2(w[k0+8],w[k0+9]), lo-pair0, lo-pair1 }
    for (int i = tid; i < 5*4*64; i += 256) {
        int kb = i >> 8, qq = (i >> 6) & 3, n = i & 63;
        int k0 = kb*16 + 2*qq;
        float v0 = w_mat[k0*64 + n];
        float v1 = w_mat[(k0+1)*64 + n];
        float v2 = (k0+8 < 72) ? w_mat[(k0+8)*64 + n] : 0.0f;
        float v3 = (k0+9 < 72) ? w_mat[(k0+9)*64 + n] : 0.0f;
        __half h0 = __float2half_rn(v0), h1 = __float2half_rn(v1);
        __half h2v = __float2half_rn(v2), h3 = __float2half_rn(v3);
        uint32_t b0h = pack_h2(__half2float(h0), __half2float(h1));
        uint32_t b1h = pack_h2(__half2float(h2v), __half2float(h3));
        uint32_t b0l = pack_h2(v0 - __half2float(h0), v1 - __half2float(h1));
        uint32_t b1l = pack_h2(v2 - __half2float(h2v), v3 - __half2float(h3));
        *(uint4*)(sB1 + (kb*4 + qq)*264 + n*4) = make_uint4(b0h, b1h, b0l, b1l);
    }
    for (int i = tid; i < 4*4*64; i += 256) {
        int kb = i >> 8, qq = (i >> 6) & 3, n = i & 63;
        int k0 = kb*16 + 2*qq;
        float v0 = w1[k0*64 + n];
        float v1 = w1[(k0+1)*64 + n];
        float v2 = w1[(k0+8)*64 + n];
        float v3 = w1[(k0+9)*64 + n];
        __half h0 = __float2half_rn(v0), h1 = __float2half_rn(v1);
        __half h2v = __float2half_rn(v2), h3 = __float2half_rn(v3);
        uint32_t b0h = pack_h2(__half2float(h0), __half2float(h1));
        uint32_t b1h = pack_h2(__half2float(h2v), __half2float(h3));
        uint32_t b0l = pack_h2(v0 - __half2float(h0), v1 - __half2float(h1));
        uint32_t b1l = pack_h2(v2 - __half2float(h2v), v3 - __half2float(h3));
        *(uint4*)(sB2 + (kb*4 + qq)*264 + n*4) = make_uint4(b0h, b1h, b0l, b1l);
    }
    if (tid < 192) sW2[tid] = w2[tid];
    if (tid < 64)  sBm[tid] = b_mat[tid];

    const int m0 = wid * 16;
    int tile = blockIdx.x;
    const int stride = gridDim.x;

    // prologue: async copy first tile into buf 0
    {
        const __half* src = g_fh + (size_t)tile * 128 * 72;
        for (int i = tid; i < 128*9; i += 256) {
            int row = i / 9, c = i % 9;
            cp_async16(smem_base + row*160 + c*16, src + row*72 + c*8);
        }
        CP_COMMIT();
    }

    int buf = 0;
    #pragma unroll 1
    for (; tile < NTILES; tile += stride, buf ^= 1) {
        int nxt = tile + stride;
        if (nxt < NTILES) {
            const __half* src = g_fh + (size_t)nxt * 128 * 72;
            uint32_t dst = smem_base + (buf ^ 1) * F_BUF_BYTES;
            for (int i = tid; i < 128*9; i += 256) {
                int row = i / 9, c = i % 9;
                cp_async16(dst + row*160 + c*16, src + row*72 + c*8);
            }
        }
        CP_COMMIT();
        CP_WAIT1();
        __syncthreads();

        __half* sF = (__half*)(sm + buf * F_BUF_FLOATS);
        const int pbase = tile * 128;

        // ---- GEMM1: acc = F @ Wmat + b_mat (fp16 A exact, B hi+lo) ----
        float acc[8][4];
        #pragma unroll
        for (int nb = 0; nb < 8; nb++) {
            float bv0 = sBm[nb*8 + 2*q];
            float bv1 = sBm[nb*8 + 2*q + 1];
            acc[nb][0] = bv0; acc[nb][1] = bv1; acc[nb][2] = bv0; acc[nb][3] = bv1;
        }
        #pragma unroll 1
        for (int kb = 0; kb < 5; kb++) {
            int r0 = (m0 + g)*80 + kb*16 + 2*q;
            uint32_t a0 = *(const uint32_t*)(sF + r0);
            uint32_t a1 = *(const uint32_t*)(sF + r0 + 8*80);
            uint32_t a2 = *(const uint32_t*)(sF + r0 + 8);
            uint32_t a3 = *(const uint32_t*)(sF + r0 + 8*80 + 8);
            const float* brow = sB1 + (kb*4 + q)*264 + g*4;
            #pragma unroll
            for (int nb = 0; nb < 8; nb++) {
                uint4 bv = *(const uint4*)(brow + nb*32);
                mma_f16(acc[nb], a0, a1, a2, a3, bv.x, bv.y);
                mma_f16(acc[nb], a0, a1, a2, a3, bv.z, bv.w);
            }
        }
        // ---- epilogue 1: gelu -> fp16 back into sF (warp-private rows) ----
        __syncwarp();
        #pragma unroll
        for (int nb = 0; nb < 8; nb++) {
            int c0 = nb*8 + 2*q;
            __half2* dA = (__half2*)(sF + (m0 + g)*80 + c0);
            __half2* dB = (__half2*)(sF + (m0 + g + 8)*80 + c0);
            *dA = __floats2half2_rn(gelu_exact(acc[nb][0]), gelu_exact(acc[nb][1]));
            *dB = __floats2half2_rn(gelu_exact(acc[nb][2]), gelu_exact(acc[nb][3]));
        }
        __syncwarp();
        // ---- GEMM2: acc2 = H @ W1a ----
        float acc2[8][4];
        #pragma unroll
        for (int nb = 0; nb < 8; nb++)
            acc2[nb][0] = acc2[nb][1] = acc2[nb][2] = acc2[nb][3] = 0.0f;
        #pragma unroll 1
        for (int kb = 0; kb < 4; kb++) {
            int r0 = (m0 + g)*80 + kb*16 + 2*q;
            uint32_t a0 = *(const uint32_t*)(sF + r0);
            uint32_t a1 = *(const uint32_t*)(sF + r0 + 8*80);
            uint32_t a2 = *(const uint32_t*)(sF + r0 + 8);
            uint32_t a3 = *(const uint32_t*)(sF + r0 + 8*80 + 8);
            const float* brow = sB2 + (kb*4 + q)*264 + g*4;
            #pragma unroll
            for (int nb = 0; nb < 8; nb++) {
                uint4 bv = *(const uint4*)(brow + nb*32);
                mma_f16(acc2[nb], a0, a1, a2, a3, bv.x, bv.y);
                mma_f16(acc2[nb], a0, a1, a2, a3, bv.z, bv.w);
            }
        }
        // ---- epilogue 2: +rayBias, gelu, xW2, quad-reduce, sigmoid ----
        const int pA = pbase + m0 + g;
        const int pB = pA + 8;
        const float* biasA = g_bias + (size_t)(pA / NS) * 64;
        const float* biasB = g_bias + (size_t)(pB / NS) * 64;
        float rA0 = 0.f, rA1 = 0.f, rA2 = 0.f, rB0 = 0.f, rB1 = 0.f, rB2 = 0.f;
        #pragma unroll
        for (int nb = 0; nb < 8; nb++) {
            int c0 = nb*8 + 2*q, c1 = c0 + 1;
            float v00 = gelu_exact(acc2[nb][0] + biasA[c0]);
            float v01 = gelu_exact(acc2[nb][1] + biasA[c1]);
            float v10 = gelu_exact(acc2[nb][2] + biasB[c0]);
            float v11 = gelu_exact(acc2[nb][3] + biasB[c1]);
            float w00 = sW2[c0*3+0], w01 = sW2[c0*3+1], w02 = sW2[c0*3+2];
            float w10 = sW2[c1*3+0], w11 = sW2[c1*3+1], w12 = sW2[c1*3+2];
            rA0 += v00*w00 + v01*w10;
            rA1 += v00*w01 + v01*w11;
            rA2 += v00*w02 + v01*w12;
            rB0 += v10*w00 + v11*w10;
            rB1 += v10*w01 + v11*w11;
            rB2 += v10*w02 + v11*w12;
        }
        #pragma unroll
        for (int off = 1; off <= 2; off <<= 1) {
            rA0 += __shfl_xor_sync(0xffffffffu, rA0, off);
            rA1 += __shfl_xor_sync(0xffffffffu, rA1, off);
            rA2 += __shfl_xor_sync(0xffffffffu, rA2, off);
            rB0 += __shfl_xor_sync(0xffffffffu, rB0, off);
            rB1 += __shfl_xor_sync(0xffffffffu, rB1, off);
            rB2 += __shfl_xor_sync(0xffffffffu, rB2, off);
        }
        if (q == 0) {
            float c0 = b2[0], c1 = b2[1], c2 = b2[2];
            float* oA = g_rgb + (size_t)pA * 3;
            oA[0] = 1.0f / (1.0f + expf(-(rA0 + c0)));
            oA[1] = 1.0f / (1.0f + expf(-(rA1 + c1)));
            oA[2] = 1.0f / (1.0f + expf(-(rA2 + c2)));
            float* oB = g_rgb + (size_t)pB * 3;
            oB[0] = 1.0f / (1.0f + expf(-(rB0 + c0)));
            oB[1] = 1.0f / (1.0f + expf(-(rB1 + c1)));
            oB[2] = 1.0f / (1.0f + expf(-(rB2 + c2)));
        }
        __syncthreads();
    }
}

// ---------------- per-ray compositing ----------------
__global__ void k_render(float* __restrict__ out_rgb, float* __restrict__ out_depth,
                         float* __restrict__ w) {
    int qq = blockIdx.x * blockDim.x + threadIdx.x;
    if (qq >= NRAYS) return;
    float T = 1.0f, a0 = 0.0f, a1 = 0.0f, a2 = 0.0f, dep = 0.0f;
    const float* rp = g_rgb + (size_t)qq * NS * 3;
    float* wp = w + (size_t)qq * NS;
    #pragma unroll 1
    for (int s = 0; s < NS; s++) {
        float sg = wp[s];
        float al = 1.0f - expf(-sg * DT);
        float wt = al * T;
        T *= (1.0f - al + 1e-10f);
        wp[s] = wt;
        dep += wt * (((float)s + 0.5f) * DT);
        a0 += wt * rp[s*3+0];
        a1 += wt * rp[s*3+1];
        a2 += wt * rp[s*3+2];
    }
    out_rgb[qq*3+0] = a0;
    out_rgb[qq*3+1] = a1;
    out_rgb[qq*3+2] = a2;
    out_depth[qq]   = dep;
}

// ---------------- launch ----------------
extern "C" void kernel_launch(void* const* d_in, const int* in_sizes, int n_in,
                              void* d_out, int out_size) {
    const float* rays_o  = (const float*)d_in[0];
    const float* rays_d  = (const float*)d_in[1];
    const float* matrixs = (const float*)d_in[2];
    const float* vectors = (const float*)d_in[3];
    const float* w_mat   = (const float*)d_in[4];
    const float* b_mat   = (const float*)d_in[5];
    const float* w1      = (const float*)d_in[6];
    const float* b1      = (const float*)d_in[7];
    const float* w2      = (const float*)d_in[8];
    const float* b2      = (const float*)d_in[9];

    float* out       = (float*)d_out;
    float* out_rgb   = out;
    float* out_depth = out + NRAYS*3;
    float* out_w     = out + NRAYS*4;

    static int nsm = 0;
    if (nsm == 0) {
        cudaDeviceProp prop;
        cudaGetDeviceProperties(&prop, 0);
        nsm = prop.multiProcessorCount;
        cudaFuncSetAttribute(k_mlp, cudaFuncAttributeMaxDynamicSharedMemorySize,
                             SMEM_FLOATS * sizeof(float));
    }

    k_transpose_mat<<<(3*BATCH*RES*RES*CH + 255)/256, 256>>>(matrixs);
    k_transpose_vec<<<(3*BATCH*RES*CH + 255)/256, 256>>>(vectors);
    k_bias<<<(NRAYS + 127)/128, 128>>>(rays_d, w1, b1);
    k_sample<<<NPTS/128, 128>>>(rays_o, rays_d, out_w);
    k_mlp<<<2*nsm, 256, SMEM_FLOATS * sizeof(float)>>>(w_mat, b_mat, w1, w2, b2);
    k_render<<<(NRAYS + 127)/128, 128>>>(out_rgb, out_depth, out_w);
}

// round 7
// speedup vs baseline: 2.9304x; 1.2406x over previous
#include <cuda_runtime.h>
#include <cuda_fp16.h>
#include <math.h>
#include <stdint.h>

#define BATCH 4
#define RAYS  8192
#define NRAYS (BATCH*RAYS)          // 32768
#define NS    48
#define RES   48
#define CH    32
#define NPTS  (NRAYS*NS)            // 1572864
#define NTILES (NPTS/128)           // 12288

#define DT    0.03125f

// ---------------- device scratch ----------------
__device__ __align__(16) __half g_mat_h[3*BATCH*RES*RES*CH];
__device__ __align__(16) __half g_vec_h[3*BATCH*RES*CH];
__device__ __align__(16) float  g_rgb[(size_t)NPTS*3];
__device__ __align__(16) float  g_bias[(size_t)NRAYS*64];

__device__ __forceinline__ float gelu_exact(float x) {
    return 0.5f * x * (1.0f + erff(x * 0.70710678118654752f));
}

__device__ __forceinline__ void mma_f16(float d[4],
                                        uint32_t a0, uint32_t a1, uint32_t a2, uint32_t a3,
                                        uint32_t b0, uint32_t b1) {
    asm volatile("mma.sync.aligned.m16n8k16.row.col.f32.f16.f16.f32 "
                 "{%0,%1,%2,%3}, {%4,%5,%6,%7}, {%8,%9}, {%0,%1,%2,%3};"
                 : "+f"(d[0]), "+f"(d[1]), "+f"(d[2]), "+f"(d[3])
                 : "r"(a0), "r"(a1), "r"(a2), "r"(a3), "r"(b0), "r"(b1));
}

__device__ __forceinline__ uint32_t pack_h2(float lo, float hi) {
    __half2 h = __floats2half2_rn(lo, hi);
    return *(uint32_t*)&h;
}

// ---------------- prep: transposes to channel-last fp16 ----------------
__global__ void k_transpose_mat(const float* __restrict__ m) {
    int idx = blockIdx.x * blockDim.x + threadIdx.x;
    if (idx >= 3*BATCH*RES*RES*CH) return;
    int c   = idx % CH;
    int pix = (idx / CH) % (RES*RES);
    int ib  = idx / (CH*RES*RES);
    g_mat_h[idx] = __float2half_rn(m[((size_t)ib*CH + c)*(RES*RES) + pix]);
}

__global__ void k_transpose_vec(const float* __restrict__ v) {
    int idx = blockIdx.x * blockDim.x + threadIdx.x;
    if (idx >= 3*BATCH*RES*CH) return;
    int c  = idx % CH;
    int r  = (idx / CH) % RES;
    int ib = idx / (CH*RES);
    g_vec_h[idx] = __float2half_rn(v[((size_t)ib*CH + c)*RES + r]);
}

__global__ void k_bias(const float* __restrict__ rays_d,
                       const float* __restrict__ w1, const float* __restrict__ b1) {
    int q = blockIdx.x * blockDim.x + threadIdx.x;
    if (q >= NRAYS) return;
    float dx = rays_d[q*3+0], dy = rays_d[q*3+1], dz = rays_d[q*3+2];
    float inv = 1.0f / sqrtf(dx*dx + dy*dy + dz*dz);
    dx *= inv; dy *= inv; dz *= inv;
    float pe[27];
    pe[0] = dx; pe[1] = dy; pe[2] = dz;
    float f = 1.0f;
    #pragma unroll
    for (int fi = 0; fi < 4; fi++) {
        float s, c;
        sincosf(dx*f, &s, &c); pe[3 + fi*3 + 0] = s; pe[15 + fi*3 + 0] = c;
        sincosf(dy*f, &s, &c); pe[3 + fi*3 + 1] = s; pe[15 + fi*3 + 1] = c;
        sincosf(dz*f, &s, &c); pe[3 + fi*3 + 2] = s; pe[15 + fi*3 + 2] = c;
        f *= 2.0f;
    }
    float acc[64];
    #pragma unroll
    for (int j = 0; j < 64; j++) acc[j] = b1[j];
    #pragma unroll 1
    for (int k = 0; k < 27; k++) {
        float v = pe[k];
        const float* wr = w1 + (64 + k) * 64;
        #pragma unroll
        for (int j = 0; j < 64; j++) acc[j] += v * wr[j];
    }
    float* o = g_bias + (size_t)q * 64;
    #pragma unroll
    for (int j = 0; j < 64; j++) o[j] = acc[j];
}

// ---------------- fused persistent: sample -> GEMM1 -> GEMM2 -> head ------------
// smem: F tile 128 rows x 80-half pitch; then packed weights
#define F_BUF_FLOATS 5120                 // 128*80/2
#define OF_B1   F_BUF_FLOATS              // 5120, [5][4] rows x 264 words
#define OF_B2   (OF_B1 + 5*4*264)         // +5280 -> 10400
#define OF_W2   (OF_B2 + 4*4*264)         // +4224 -> 14624
#define OF_BM   (OF_W2 + 192)             // 14816
#define SMEM_FLOATS (OF_BM + 64)          // 14880 floats = 59520 B

__global__ __launch_bounds__(256, 2)
void k_fused(const float* __restrict__ rays_o, const float* __restrict__ rays_d,
             const float* __restrict__ w_mat, const float* __restrict__ b_mat,
             const float* __restrict__ w1, const float* __restrict__ w2,
             const float* __restrict__ b2, float* __restrict__ out_sigma) {
    extern __shared__ float sm[];
    float* sB1 = sm + OF_B1;
    float* sB2 = sm + OF_B2;
    float* sW2 = sm + OF_W2;
    float* sBm = sm + OF_BM;
    __half* sF = (__half*)sm;

    const int tid  = threadIdx.x;
    const int lane = tid & 31;
    const int wid  = tid >> 5;
    const int q    = lane & 3;
    const int g    = lane >> 2;

    // ---- zero pad cols 72..79 of F tile (never written again) ----
    if (tid < 128)
        *(uint4*)(sF + tid*80 + 72) = make_uint4(0,0,0,0);

    // ---- one-time fp16 hi/lo weight packing ----
    for (int i = tid; i < 5*4*64; i += 256) {
        int kb = i >> 8, qq = (i >> 6) & 3, n = i & 63;
        int k0 = kb*16 + 2*qq;
        float v0 = w_mat[k0*64 + n];
        float v1 = w_mat[(k0+1)*64 + n];
        float v2 = (k0+8 < 72) ? w_mat[(k0+8)*64 + n] : 0.0f;
        float v3 = (k0+9 < 72) ? w_mat[(k0+9)*64 + n] : 0.0f;
        __half h0 = __float2half_rn(v0), h1 = __float2half_rn(v1);
        __half h2v = __float2half_rn(v2), h3 = __float2half_rn(v3);
        uint32_t b0h = pack_h2(__half2float(h0), __half2float(h1));
        uint32_t b1h = pack_h2(__half2float(h2v), __half2float(h3));
        uint32_t b0l = pack_h2(v0 - __half2float(h0), v1 - __half2float(h1));
        uint32_t b1l = pack_h2(v2 - __half2float(h2v), v3 - __half2float(h3));
        *(uint4*)(sB1 + (kb*4 + qq)*264 + n*4) = make_uint4(b0h, b1h, b0l, b1l);
    }
    for (int i = tid; i < 4*4*64; i += 256) {
        int kb = i >> 8, qq = (i >> 6) & 3, n = i & 63;
        int k0 = kb*16 + 2*qq;
        float v0 = w1[k0*64 + n];
        float v1 = w1[(k0+1)*64 + n];
        float v2 = w1[(k0+8)*64 + n];
        float v3 = w1[(k0+9)*64 + n];
        __half h0 = __float2half_rn(v0), h1 = __float2half_rn(v1);
        __half h2v = __float2half_rn(v2), h3 = __float2half_rn(v3);
        uint32_t b0h = pack_h2(__half2float(h0), __half2float(h1));
        uint32_t b1h = pack_h2(__half2float(h2v), __half2float(h3));
        uint32_t b0l = pack_h2(v0 - __half2float(h0), v1 - __half2float(h1));
        uint32_t b1l = pack_h2(v2 - __half2float(h2v), v3 - __half2float(h3));
        *(uint4*)(sB2 + (kb*4 + qq)*264 + n*4) = make_uint4(b0h, b1h, b0l, b1l);
    }
    if (tid < 192) sW2[tid] = w2[tid];
    if (tid < 64)  sBm[tid] = b_mat[tid];
    __syncthreads();

    const int m0 = wid * 16;
    const int lp = tid & 127;       // local point row
    const int halfsel = tid >> 7;   // 0: chunks 0,1  1: chunks 2,3

    #pragma unroll 1
    for (int tile = blockIdx.x; tile < NTILES; tile += gridDim.x) {
        const int pbase = tile * 128;

        // ================= sampling phase: 2 threads per point =================
        {
            const int p   = pbase + lp;
            const int s   = p % NS;
            const int ray = p / NS;
            const int b   = ray / RAYS;

            const float ox = rays_o[ray*3+0], oy = rays_o[ray*3+1], oz = rays_o[ray*3+2];
            const float dx = rays_d[ray*3+0], dy = rays_d[ray*3+1], dz = rays_d[ray*3+2];
            const float t  = ((float)s + 0.5f) * DT;

            const float px = ((ox + dx*t) + 0.8f) * 1.25f - 1.0f;
            const float py = ((oy + dy*t) + 0.8f) * 1.25f - 1.0f;
            const float pz = ((oz + dz*t) + 0.8f) * 1.25f - 1.0f;

            float sigma = 0.0f;
            __half* fo = sF + lp*80;
            const int cc0 = halfsel*2;

            #pragma unroll 1
            for (int pl = 0; pl < 3; pl++) {
                const float cx = (pl == 0) ? px : ((pl == 1) ? pz : py);
                const float cy = (pl == 0) ? py : ((pl == 1) ? px : pz);
                const float cz = (pl == 0) ? pz : ((pl == 1) ? py : px);

                const float fx = (cx + 1.0f) * 23.5f;
                const float fy = (cy + 1.0f) * 23.5f;
                const float fz = (cz + 1.0f) * 23.5f;
                const float x0f = floorf(fx), y0f = floorf(fy), z0f = floorf(fz);
                const float wx = fx - x0f, wy = fy - y0f, wz = fz - z0f;
                const int ix0 = (int)x0f, iy0 = (int)y0f, iz0 = (int)z0f;

                const float mx0 = (ix0 >= 0  && ix0 <  RES)   ? 1.0f : 0.0f;
                const float mx1 = (ix0 >= -1 && ix0 <  RES-1) ? 1.0f : 0.0f;
                const float my0 = (iy0 >= 0  && iy0 <  RES)   ? 1.0f : 0.0f;
                const float my1 = (iy0 >= -1 && iy0 <  RES-1) ? 1.0f : 0.0f;
                const float mz0 = (iz0 >= 0  && iz0 <  RES)   ? 1.0f : 0.0f;
                const float mz1 = (iz0 >= -1 && iz0 <  RES-1) ? 1.0f : 0.0f;

                const int cx0 = min(max(ix0,   0), RES-1), cx1 = min(max(ix0+1, 0), RES-1);
                const int cy0 = min(max(iy0,   0), RES-1), cy1 = min(max(iy0+1, 0), RES-1);
                const int cz0 = min(max(iz0,   0), RES-1), cz1 = min(max(iz0+1, 0), RES-1);

                const float w00 = (1.0f-wx)*(1.0f-wy)*mx0*my0;
                const float w10 = wx*(1.0f-wy)*mx1*my0;
                const float w01 = (1.0f-wx)*wy*mx0*my1;
                const float w11 = wx*wy*mx1*my1;
                const float u0  = (1.0f-wz)*mz0;
                const float u1  = wz*mz1;

                const __half* mb = g_mat_h + ((size_t)(pl*BATCH + b) * (RES*RES)) * CH;
                const __half* vb = g_vec_h + ((size_t)(pl*BATCH + b) * RES) * CH;
                const uint4* p00 = (const uint4*)(mb + (size_t)(cy0*RES + cx0) * CH);
                const uint4* p10 = (const uint4*)(mb + (size_t)(cy0*RES + cx1) * CH);
                const uint4* p01 = (const uint4*)(mb + (size_t)(cy1*RES + cx0) * CH);
                const uint4* p11 = (const uint4*)(mb + (size_t)(cy1*RES + cx1) * CH);
                const uint4* q0  = (const uint4*)(vb + (size_t)cz0 * CH);
                const uint4* q1  = (const uint4*)(vb + (size_t)cz1 * CH);

                #pragma unroll
                for (int ci = 0; ci < 2; ci++) {
                    const int cc = cc0 + ci;
                    uint4 ua = p00[cc], ub = p10[cc], uc = p01[cc], ud = p11[cc];
                    uint4 ue = q0[cc],  uf = q1[cc];
                    const __half2* ha = (const __half2*)&ua;
                    const __half2* hb = (const __half2*)&ub;
                    const __half2* hc = (const __half2*)&uc;
                    const __half2* hd = (const __half2*)&ud;
                    const __half2* he = (const __half2*)&ue;
                    const __half2* hf = (const __half2*)&uf;
                    float vals[8];
                    #pragma unroll
                    for (int j = 0; j < 4; j++) {
                        float2 fa = __half22float2(ha[j]);
                        float2 fb = __half22float2(hb[j]);
                        float2 fc = __half22float2(hc[j]);
                        float2 fd = __half22float2(hd[j]);
                        float2 fe = __half22float2(he[j]);
                        float2 ff = __half22float2(hf[j]);
                        float pf0 = w00*fa.x + w10*fb.x + w01*fc.x + w11*fd.x;
                        float pf1 = w00*fa.y + w10*fb.y + w01*fc.y + w11*fd.y;
                        float lf0 = u0*fe.x + u1*ff.x;
                        float lf1 = u0*fe.y + u1*ff.y;
                        vals[j*2]   = pf0 * lf0;
                        vals[j*2+1] = pf1 * lf1;
                    }
                    if (cc == 0) {
                        #pragma unroll
                        for (int j = 0; j < 8; j++) sigma += vals[j];
                    } else {
                        uint4 packed;
                        packed.x = pack_h2(gelu_exact(vals[0]), gelu_exact(vals[1]));
                        packed.y = pack_h2(gelu_exact(vals[2]), gelu_exact(vals[3]));
                        packed.z = pack_h2(gelu_exact(vals[4]), gelu_exact(vals[5]));
                        packed.w = pack_h2(gelu_exact(vals[6]), gelu_exact(vals[7]));
                        *(uint4*)(fo + pl*24 + (cc-1)*8) = packed;
                    }
                }
            }
            if (halfsel == 0) out_sigma[p] = fmaxf(sigma, 0.0f);
        }
        __syncthreads();

        // ================= GEMM1: acc = F @ Wmat + b_mat =================
        float acc[8][4];
        #pragma unroll
        for (int nb = 0; nb < 8; nb++) {
            float bv0 = sBm[nb*8 + 2*q];
            float bv1 = sBm[nb*8 + 2*q + 1];
            acc[nb][0] = bv0; acc[nb][1] = bv1; acc[nb][2] = bv0; acc[nb][3] = bv1;
        }
        #pragma unroll 1
        for (int kb = 0; kb < 5; kb++) {
            int r0 = (m0 + g)*80 + kb*16 + 2*q;
            uint32_t a0 = *(const uint32_t*)(sF + r0);
            uint32_t a1 = *(const uint32_t*)(sF + r0 + 8*80);
            uint32_t a2 = *(const uint32_t*)(sF + r0 + 8);
            uint32_t a3 = *(const uint32_t*)(sF + r0 + 8*80 + 8);
            const float* brow = sB1 + (kb*4 + q)*264 + g*4;
            #pragma unroll
            for (int nb = 0; nb < 8; nb++) {
                uint4 bv = *(const uint4*)(brow + nb*32);
                mma_f16(acc[nb], a0, a1, a2, a3, bv.x, bv.y);
                mma_f16(acc[nb], a0, a1, a2, a3, bv.z, bv.w);
            }
        }
        // ---- epilogue 1: gelu -> fp16 back into sF (warp-private rows) ----
        __syncwarp();
        #pragma unroll
        for (int nb = 0; nb < 8; nb++) {
            int c0 = nb*8 + 2*q;
            __half2* dA = (__half2*)(sF + (m0 + g)*80 + c0);
            __half2* dB = (__half2*)(sF + (m0 + g + 8)*80 + c0);
            *dA = __floats2half2_rn(gelu_exact(acc[nb][0]), gelu_exact(acc[nb][1]));
            *dB = __floats2half2_rn(gelu_exact(acc[nb][2]), gelu_exact(acc[nb][3]));
        }
        __syncwarp();
        // ================= GEMM2: acc2 = H @ W1a =================
        float acc2[8][4];
        #pragma unroll
        for (int nb = 0; nb < 8; nb++)
            acc2[nb][0] = acc2[nb][1] = acc2[nb][2] = acc2[nb][3] = 0.0f;
        #pragma unroll 1
        for (int kb = 0; kb < 4; kb++) {
            int r0 = (m0 + g)*80 + kb*16 + 2*q;
            uint32_t a0 = *(const uint32_t*)(sF + r0);
            uint32_t a1 = *(const uint32_t*)(sF + r0 + 8*80);
            uint32_t a2 = *(const uint32_t*)(sF + r0 + 8);
            uint32_t a3 = *(const uint32_t*)(sF + r0 + 8*80 + 8);
            const float* brow = sB2 + (kb*4 + q)*264 + g*4;
            #pragma unroll
            for (int nb = 0; nb < 8; nb++) {
                uint4 bv = *(const uint4*)(brow + nb*32);
                mma_f16(acc2[nb], a0, a1, a2, a3, bv.x, bv.y);
                mma_f16(acc2[nb], a0, a1, a2, a3, bv.z, bv.w);
            }
        }
        // ---- epilogue 2: +rayBias, gelu, xW2, quad-reduce, sigmoid ----
        const int pA = pbase + m0 + g;
        const int pB = pA + 8;
        const float* biasA = g_bias + (size_t)(pA / NS) * 64;
        const float* biasB = g_bias + (size_t)(pB / NS) * 64;
        float rA0 = 0.f, rA1 = 0.f, rA2 = 0.f, rB0 = 0.f, rB1 = 0.f, rB2 = 0.f;
        #pragma unroll
        for (int nb = 0; nb < 8; nb++) {
            int c0 = nb*8 + 2*q, c1 = c0 + 1;
            float v00 = gelu_exact(acc2[nb][0] + biasA[c0]);
            float v01 = gelu_exact(acc2[nb][1] + biasA[c1]);
            float v10 = gelu_exact(acc2[nb][2] + biasB[c0]);
            float v11 = gelu_exact(acc2[nb][3] + biasB[c1]);
            float w00 = sW2[c0*3+0], w01 = sW2[c0*3+1], w02 = sW2[c0*3+2];
            float w10 = sW2[c1*3+0], w11 = sW2[c1*3+1], w12 = sW2[c1*3+2];
            rA0 += v00*w00 + v01*w10;
            rA1 += v00*w01 + v01*w11;
            rA2 += v00*w02 + v01*w12;
            rB0 += v10*w00 + v11*w10;
            rB1 += v10*w01 + v11*w11;
            rB2 += v10*w02 + v11*w12;
        }
        #pragma unroll
        for (int off = 1; off <= 2; off <<= 1) {
            rA0 += __shfl_xor_sync(0xffffffffu, rA0, off);
            rA1 += __shfl_xor_sync(0xffffffffu, rA1, off);
            rA2 += __shfl_xor_sync(0xffffffffu, rA2, off);
            rB0 += __shfl_xor_sync(0xffffffffu, rB0, off);
            rB1 += __shfl_xor_sync(0xffffffffu, rB1, off);
            rB2 += __shfl_xor_sync(0xffffffffu, rB2, off);
        }
        if (q == 0) {
            float c0 = b2[0], c1 = b2[1], c2 = b2[2];
            float* oA = g_rgb + (size_t)pA * 3;
            oA[0] = 1.0f / (1.0f + expf(-(rA0 + c0)));
            oA[1] = 1.0f / (1.0f + expf(-(rA1 + c1)));
            oA[2] = 1.0f / (1.0f + expf(-(rA2 + c2)));
            float* oB = g_rgb + (size_t)pB * 3;
            oB[0] = 1.0f / (1.0f + expf(-(rB0 + c0)));
            oB[1] = 1.0f / (1.0f + expf(-(rB1 + c1)));
            oB[2] = 1.0f / (1.0f + expf(-(rB2 + c2)));
        }
        __syncthreads();   // sF fully consumed before next tile's sampling
    }
}

// ---------------- per-ray compositing ----------------
__global__ void k_render(float* __restrict__ out_rgb, float* __restrict__ out_depth,
                         float* __restrict__ w) {
    int qq = blockIdx.x * blockDim.x + threadIdx.x;
    if (qq >= NRAYS) return;
    float T = 1.0f, a0 = 0.0f, a1 = 0.0f, a2 = 0.0f, dep = 0.0f;
    const float* rp = g_rgb + (size_t)qq * NS * 3;
    float* wp = w + (size_t)qq * NS;
    #pragma unroll 1
    for (int s = 0; s < NS; s++) {
        float sg = wp[s];
        float al = 1.0f - expf(-sg * DT);
        float wt = al * T;
        T *= (1.0f - al + 1e-10f);
        wp[s] = wt;
        dep += wt * (((float)s + 0.5f) * DT);
        a0 += wt * rp[s*3+0];
        a1 += wt * rp[s*3+1];
        a2 += wt * rp[s*3+2];
    }
    out_rgb[qq*3+0] = a0;
    out_rgb[qq*3+1] = a1;
    out_rgb[qq*3+2] = a2;
    out_depth[qq]   = dep;
}

// ---------------- launch ----------------
extern "C" void kernel_launch(void* const* d_in, const int* in_sizes, int n_in,
                              void* d_out, int out_size) {
    const float* rays_o  = (const float*)d_in[0];
    const float* rays_d  = (const float*)d_in[1];
    const float* matrixs = (const float*)d_in[2];
    const float* vectors = (const float*)d_in[3];
    const float* w_mat   = (const float*)d_in[4];
    const float* b_mat   = (const float*)d_in[5];
    const float* w1      = (const float*)d_in[6];
    const float* b1      = (const float*)d_in[7];
    const float* w2      = (const float*)d_in[8];
    const float* b2      = (const float*)d_in[9];

    float* out       = (float*)d_out;
    float* out_rgb   = out;
    float* out_depth = out + NRAYS*3;
    float* out_w     = out + NRAYS*4;

    static int nsm = 0;
    if (nsm == 0) {
        cudaDeviceProp prop;
        cudaGetDeviceProperties(&prop, 0);
        nsm = prop.multiProcessorCount;
        cudaFuncSetAttribute(k_fused, cudaFuncAttributeMaxDynamicSharedMemorySize,
                             SMEM_FLOATS * sizeof(float));
    }

    k_transpose_mat<<<(3*BATCH*RES*RES*CH + 255)/256, 256>>>(matrixs);
    k_transpose_vec<<<(3*BATCH*RES*CH + 255)/256, 256>>>(vectors);
    k_bias<<<(NRAYS + 127)/128, 128>>>(rays_d, w1, b1);
    k_fused<<<2*nsm, 256, SMEM_FLOATS * sizeof(float)>>>(rays_o, rays_d, w_mat, b_mat,
                                                          w1, w2, b2, out_w);
    k_render<<<(NRAYS + 127)/128, 128>>>(out_rgb, out_depth, out_w);
}

// round 8
// speedup vs baseline: 3.9838x; 1.3594x over previous
#include <cuda_runtime.h>
#include <cuda_fp16.h>
#include <math.h>
#include <stdint.h>

#define BATCH 4
#define RAYS  8192
#define NRAYS (BATCH*RAYS)          // 32768
#define NS    48
#define RES   48
#define CH    32
#define NPTS  (NRAYS*NS)            // 1572864
#define NTILES (NPTS/128)           // 12288

#define DT    0.03125f

// ---------------- device scratch ----------------
__device__ __align__(16) __half g_mat_h[3*BATCH*RES*RES*CH];
__device__ __align__(16) __half g_vec_h[3*BATCH*RES*CH];
__device__ __align__(16) float  g_rgb[(size_t)NPTS*3];
__device__ __align__(16) float  g_bias[(size_t)NRAYS*64];

__device__ __forceinline__ float tanh_apx(float x) {
    float r;
    asm("tanh.approx.f32 %0, %1;" : "=f"(r) : "f"(x));
    return r;
}

// fast gelu: tanh-form with HW tanh (|err vs exact| <~4e-4, typ ~1e-4)
__device__ __forceinline__ float gelu_fast(float x) {
    float inner = 0.7978845608f * x * fmaf(0.044715f * x, x, 1.0f);
    return 0.5f * x * (1.0f + tanh_apx(inner));
}

__device__ __forceinline__ float sigmoid_fast(float x) {
    return 0.5f * (1.0f + tanh_apx(0.5f * x));   // exact identity
}

__device__ __forceinline__ void mma_f16(float d[4],
                                        uint32_t a0, uint32_t a1, uint32_t a2, uint32_t a3,
                                        uint32_t b0, uint32_t b1) {
    asm volatile("mma.sync.aligned.m16n8k16.row.col.f32.f16.f16.f32 "
                 "{%0,%1,%2,%3}, {%4,%5,%6,%7}, {%8,%9}, {%0,%1,%2,%3};"
                 : "+f"(d[0]), "+f"(d[1]), "+f"(d[2]), "+f"(d[3])
                 : "r"(a0), "r"(a1), "r"(a2), "r"(a3), "r"(b0), "r"(b1));
}

__device__ __forceinline__ uint32_t pack_h2(float lo, float hi) {
    __half2 h = __floats2half2_rn(lo, hi);
    return *(uint32_t*)&h;
}

// ---------------- prep: transposes to channel-last fp16 ----------------
__global__ void k_transpose_mat(const float* __restrict__ m) {
    int idx = blockIdx.x * blockDim.x + threadIdx.x;
    if (idx >= 3*BATCH*RES*RES*CH) return;
    int c   = idx % CH;
    int pix = (idx / CH) % (RES*RES);
    int ib  = idx / (CH*RES*RES);
    g_mat_h[idx] = __float2half_rn(m[((size_t)ib*CH + c)*(RES*RES) + pix]);
}

__global__ void k_transpose_vec(const float* __restrict__ v) {
    int idx = blockIdx.x * blockDim.x + threadIdx.x;
    if (idx >= 3*BATCH*RES*CH) return;
    int c  = idx % CH;
    int r  = (idx / CH) % RES;
    int ib = idx / (CH*RES);
    g_vec_h[idx] = __float2half_rn(v[((size_t)ib*CH + c)*RES + r]);
}

__global__ void k_bias(const float* __restrict__ rays_d,
                       const float* __restrict__ w1, const float* __restrict__ b1) {
    int q = blockIdx.x * blockDim.x + threadIdx.x;
    if (q >= NRAYS) return;
    float dx = rays_d[q*3+0], dy = rays_d[q*3+1], dz = rays_d[q*3+2];
    float inv = 1.0f / sqrtf(dx*dx + dy*dy + dz*dz);
    dx *= inv; dy *= inv; dz *= inv;
    float pe[27];
    pe[0] = dx; pe[1] = dy; pe[2] = dz;
    float f = 1.0f;
    #pragma unroll
    for (int fi = 0; fi < 4; fi++) {
        float s, c;
        sincosf(dx*f, &s, &c); pe[3 + fi*3 + 0] = s; pe[15 + fi*3 + 0] = c;
        sincosf(dy*f, &s, &c); pe[3 + fi*3 + 1] = s; pe[15 + fi*3 + 1] = c;
        sincosf(dz*f, &s, &c); pe[3 + fi*3 + 2] = s; pe[15 + fi*3 + 2] = c;
        f *= 2.0f;
    }
    float acc[64];
    #pragma unroll
    for (int j = 0; j < 64; j++) acc[j] = b1[j];
    #pragma unroll 1
    for (int k = 0; k < 27; k++) {
        float v = pe[k];
        const float* wr = w1 + (64 + k) * 64;
        #pragma unroll
        for (int j = 0; j < 64; j++) acc[j] += v * wr[j];
    }
    float* o = g_bias + (size_t)q * 64;
    #pragma unroll
    for (int j = 0; j < 64; j++) o[j] = acc[j];
}

// ---------------- fused persistent: sample -> GEMM1 -> GEMM2 -> head ------------
#define F_BUF_FLOATS 5120                 // 128*80/2
#define OF_B1   F_BUF_FLOATS              // 5120, [5][4] rows x 264 words
#define OF_B2   (OF_B1 + 5*4*264)         // +5280 -> 10400
#define OF_W2   (OF_B2 + 4*4*264)         // +4224 -> 14624
#define OF_BM   (OF_W2 + 192)             // 14816
#define SMEM_FLOATS (OF_BM + 64)          // 14880 floats = 59520 B

__global__ __launch_bounds__(256, 2)
void k_fused(const float* __restrict__ rays_o, const float* __restrict__ rays_d,
             const float* __restrict__ w_mat, const float* __restrict__ b_mat,
             const float* __restrict__ w1, const float* __restrict__ w2,
             const float* __restrict__ b2, float* __restrict__ out_sigma) {
    extern __shared__ float sm[];
    float* sB1 = sm + OF_B1;
    float* sB2 = sm + OF_B2;
    float* sW2 = sm + OF_W2;
    float* sBm = sm + OF_BM;
    __half* sF = (__half*)sm;

    const int tid  = threadIdx.x;
    const int lane = tid & 31;
    const int wid  = tid >> 5;
    const int q    = lane & 3;
    const int g    = lane >> 2;

    if (tid < 128)
        *(uint4*)(sF + tid*80 + 72) = make_uint4(0,0,0,0);

    // ---- one-time fp16 hi/lo weight packing ----
    for (int i = tid; i < 5*4*64; i += 256) {
        int kb = i >> 8, qq = (i >> 6) & 3, n = i & 63;
        int k0 = kb*16 + 2*qq;
        float v0 = w_mat[k0*64 + n];
        float v1 = w_mat[(k0+1)*64 + n];
        float v2 = (k0+8 < 72) ? w_mat[(k0+8)*64 + n] : 0.0f;
        float v3 = (k0+9 < 72) ? w_mat[(k0+9)*64 + n] : 0.0f;
        __half h0 = __float2half_rn(v0), h1 = __float2half_rn(v1);
        __half h2v = __float2half_rn(v2), h3 = __float2half_rn(v3);
        uint32_t b0h = pack_h2(__half2float(h0), __half2float(h1));
        uint32_t b1h = pack_h2(__half2float(h2v), __half2float(h3));
        uint32_t b0l = pack_h2(v0 - __half2float(h0), v1 - __half2float(h1));
        uint32_t b1l = pack_h2(v2 - __half2float(h2v), v3 - __half2float(h3));
        *(uint4*)(sB1 + (kb*4 + qq)*264 + n*4) = make_uint4(b0h, b1h, b0l, b1l);
    }
    for (int i = tid; i < 4*4*64; i += 256) {
        int kb = i >> 8, qq = (i >> 6) & 3, n = i & 63;
        int k0 = kb*16 + 2*qq;
        float v0 = w1[k0*64 + n];
        float v1 = w1[(k0+1)*64 + n];
        float v2 = w1[(k0+8)*64 + n];
        float v3 = w1[(k0+9)*64 + n];
        __half h0 = __float2half_rn(v0), h1 = __float2half_rn(v1);
        __half h2v = __float2half_rn(v2), h3 = __float2half_rn(v3);
        uint32_t b0h = pack_h2(__half2float(h0), __half2float(h1));
        uint32_t b1h = pack_h2(__half2float(h2v), __half2float(h3));
        uint32_t b0l = pack_h2(v0 - __half2float(h0), v1 - __half2float(h1));
        uint32_t b1l = pack_h2(v2 - __half2float(h2v), v3 - __half2float(h3));
        *(uint4*)(sB2 + (kb*4 + qq)*264 + n*4) = make_uint4(b0h, b1h, b0l, b1l);
    }
    if (tid < 192) sW2[tid] = w2[tid];
    if (tid < 64)  sBm[tid] = b_mat[tid];
    __syncthreads();

    const int m0 = wid * 16;
    const int lp = tid & 127;       // local point row
    const int halfsel = tid >> 7;   // 0: chunks 0,1  1: chunks 2,3

    #pragma unroll 1
    for (int tile = blockIdx.x; tile < NTILES; tile += gridDim.x) {
        const int pbase = tile * 128;

        // ================= sampling phase: 2 threads per point =================
        {
            const int p   = pbase + lp;
            const int s   = p % NS;
            const int ray = p / NS;
            const int b   = ray / RAYS;

            const float ox = rays_o[ray*3+0], oy = rays_o[ray*3+1], oz = rays_o[ray*3+2];
            const float dx = rays_d[ray*3+0], dy = rays_d[ray*3+1], dz = rays_d[ray*3+2];
            const float t  = ((float)s + 0.5f) * DT;

            const float px = ((ox + dx*t) + 0.8f) * 1.25f - 1.0f;
            const float py = ((oy + dy*t) + 0.8f) * 1.25f - 1.0f;
            const float pz = ((oz + dz*t) + 0.8f) * 1.25f - 1.0f;

            float sigma = 0.0f;
            __half* fo = sF + lp*80;
            const int cc0 = halfsel*2;

            #pragma unroll 1
            for (int pl = 0; pl < 3; pl++) {
                const float cx = (pl == 0) ? px : ((pl == 1) ? pz : py);
                const float cy = (pl == 0) ? py : ((pl == 1) ? px : pz);
                const float cz = (pl == 0) ? pz : ((pl == 1) ? py : px);

                const float fx = (cx + 1.0f) * 23.5f;
                const float fy = (cy + 1.0f) * 23.5f;
                const float fz = (cz + 1.0f) * 23.5f;
                const float x0f = floorf(fx), y0f = floorf(fy), z0f = floorf(fz);
                const float wx = fx - x0f, wy = fy - y0f, wz = fz - z0f;
                const int ix0 = (int)x0f, iy0 = (int)y0f, iz0 = (int)z0f;

                const float mx0 = (ix0 >= 0  && ix0 <  RES)   ? 1.0f : 0.0f;
                const float mx1 = (ix0 >= -1 && ix0 <  RES-1) ? 1.0f : 0.0f;
                const float my0 = (iy0 >= 0  && iy0 <  RES)   ? 1.0f : 0.0f;
                const float my1 = (iy0 >= -1 && iy0 <  RES-1) ? 1.0f : 0.0f;
                const float mz0 = (iz0 >= 0  && iz0 <  RES)   ? 1.0f : 0.0f;
                const float mz1 = (iz0 >= -1 && iz0 <  RES-1) ? 1.0f : 0.0f;

                const int cx0 = min(max(ix0,   0), RES-1), cx1 = min(max(ix0+1, 0), RES-1);
                const int cy0 = min(max(iy0,   0), RES-1), cy1 = min(max(iy0+1, 0), RES-1);
                const int cz0 = min(max(iz0,   0), RES-1), cz1 = min(max(iz0+1, 0), RES-1);

                const float w00 = (1.0f-wx)*(1.0f-wy)*mx0*my0;
                const float w10 = wx*(1.0f-wy)*mx1*my0;
                const float w01 = (1.0f-wx)*wy*mx0*my1;
                const float w11 = wx*wy*mx1*my1;
                const float u0  = (1.0f-wz)*mz0;
                const float u1  = wz*mz1;

                const __half* mb = g_mat_h + ((size_t)(pl*BATCH + b) * (RES*RES)) * CH;
                const __half* vb = g_vec_h + ((size_t)(pl*BATCH + b) * RES) * CH;
                const uint4* p00 = (const uint4*)(mb + (size_t)(cy0*RES + cx0) * CH);
                const uint4* p10 = (const uint4*)(mb + (size_t)(cy0*RES + cx1) * CH);
                const uint4* p01 = (const uint4*)(mb + (size_t)(cy1*RES + cx0) * CH);
                const uint4* p11 = (const uint4*)(mb + (size_t)(cy1*RES + cx1) * CH);
                const uint4* q0  = (const uint4*)(vb + (size_t)cz0 * CH);
                const uint4* q1  = (const uint4*)(vb + (size_t)cz1 * CH);

                #pragma unroll
                for (int ci = 0; ci < 2; ci++) {
                    const int cc = cc0 + ci;
                    uint4 ua = p00[cc], ub = p10[cc], uc = p01[cc], ud = p11[cc];
                    uint4 ue = q0[cc],  uf = q1[cc];
                    const __half2* ha = (const __half2*)&ua;
                    const __half2* hb = (const __half2*)&ub;
                    const __half2* hc = (const __half2*)&uc;
                    const __half2* hd = (const __half2*)&ud;
                    const __half2* he = (const __half2*)&ue;
                    const __half2* hf = (const __half2*)&uf;
                    float vals[8];
                    #pragma unroll
                    for (int j = 0; j < 4; j++) {
                        float2 fa = __half22float2(ha[j]);
                        float2 fb = __half22float2(hb[j]);
                        float2 fc = __half22float2(hc[j]);
                        float2 fd = __half22float2(hd[j]);
                        float2 fe = __half22float2(he[j]);
                        float2 ff = __half22float2(hf[j]);
                        float pf0 = w00*fa.x + w10*fb.x + w01*fc.x + w11*fd.x;
                        float pf1 = w00*fa.y + w10*fb.y + w01*fc.y + w11*fd.y;
                        float lf0 = u0*fe.x + u1*ff.x;
                        float lf1 = u0*fe.y + u1*ff.y;
                        vals[j*2]   = pf0 * lf0;
                        vals[j*2+1] = pf1 * lf1;
                    }
                    if (cc == 0) {
                        #pragma unroll
                        for (int j = 0; j < 8; j++) sigma += vals[j];
                    } else {
                        uint4 packed;
                        packed.x = pack_h2(gelu_fast(vals[0]), gelu_fast(vals[1]));
                        packed.y = pack_h2(gelu_fast(vals[2]), gelu_fast(vals[3]));
                        packed.z = pack_h2(gelu_fast(vals[4]), gelu_fast(vals[5]));
                        packed.w = pack_h2(gelu_fast(vals[6]), gelu_fast(vals[7]));
                        *(uint4*)(fo + pl*24 + (cc-1)*8) = packed;
                    }
                }
            }
            if (halfsel == 0) out_sigma[p] = fmaxf(sigma, 0.0f);
        }
        __syncthreads();

        // ================= GEMM1: acc = F @ Wmat + b_mat =================
        float acc[8][4];
        #pragma unroll
        for (int nb = 0; nb < 8; nb++) {
            float bv0 = sBm[nb*8 + 2*q];
            float bv1 = sBm[nb*8 + 2*q + 1];
            acc[nb][0] = bv0; acc[nb][1] = bv1; acc[nb][2] = bv0; acc[nb][3] = bv1;
        }
        #pragma unroll 1
        for (int kb = 0; kb < 5; kb++) {
            int r0 = (m0 + g)*80 + kb*16 + 2*q;
            uint32_t a0 = *(const uint32_t*)(sF + r0);
            uint32_t a1 = *(const uint32_t*)(sF + r0 + 8*80);
            uint32_t a2 = *(const uint32_t*)(sF + r0 + 8);
            uint32_t a3 = *(const uint32_t*)(sF + r0 + 8*80 + 8);
            const float* brow = sB1 + (kb*4 + q)*264 + g*4;
            #pragma unroll
            for (int nb = 0; nb < 8; nb++) {
                uint4 bv = *(const uint4*)(brow + nb*32);
                mma_f16(acc[nb], a0, a1, a2, a3, bv.x, bv.y);
                mma_f16(acc[nb], a0, a1, a2, a3, bv.z, bv.w);
            }
        }
        __syncwarp();
        #pragma unroll
        for (int nb = 0; nb < 8; nb++) {
            int c0 = nb*8 + 2*q;
            __half2* dA = (__half2*)(sF + (m0 + g)*80 + c0);
            __half2* dB = (__half2*)(sF + (m0 + g + 8)*80 + c0);
            *dA = __floats2half2_rn(gelu_fast(acc[nb][0]), gelu_fast(acc[nb][1]));
            *dB = __floats2half2_rn(gelu_fast(acc[nb][2]), gelu_fast(acc[nb][3]));
        }
        __syncwarp();
        // ================= GEMM2: acc2 = H @ W1a =================
        float acc2[8][4];
        #pragma unroll
        for (int nb = 0; nb < 8; nb++)
            acc2[nb][0] = acc2[nb][1] = acc2[nb][2] = acc2[nb][3] = 0.0f;
        #pragma unroll 1
        for (int kb = 0; kb < 4; kb++) {
            int r0 = (m0 + g)*80 + kb*16 + 2*q;
            uint32_t a0 = *(const uint32_t*)(sF + r0);
            uint32_t a1 = *(const uint32_t*)(sF + r0 + 8*80);
            uint32_t a2 = *(const uint32_t*)(sF + r0 + 8);
            uint32_t a3 = *(const uint32_t*)(sF + r0 + 8*80 + 8);
            const float* brow = sB2 + (kb*4 + q)*264 + g*4;
            #pragma unroll
            for (int nb = 0; nb < 8; nb++) {
                uint4 bv = *(const uint4*)(brow + nb*32);
                mma_f16(acc2[nb], a0, a1, a2, a3, bv.x, bv.y);
                mma_f16(acc2[nb], a0, a1, a2, a3, bv.z, bv.w);
            }
        }
        // ---- epilogue 2: +rayBias, gelu, xW2, quad-reduce, sigmoid ----
        const int pA = pbase + m0 + g;
        const int pB = pA + 8;
        const float* biasA = g_bias + (size_t)(pA / NS) * 64;
        const float* biasB = g_bias + (size_t)(pB / NS) * 64;
        float rA0 = 0.f, rA1 = 0.f, rA2 = 0.f, rB0 = 0.f, rB1 = 0.f, rB2 = 0.f;
        #pragma unroll
        for (int nb = 0; nb < 8; nb++) {
            int c0 = nb*8 + 2*q, c1 = c0 + 1;
            float v00 = gelu_fast(acc2[nb][0] + biasA[c0]);
            float v01 = gelu_fast(acc2[nb][1] + biasA[c1]);
            float v10 = gelu_fast(acc2[nb][2] + biasB[c0]);
            float v11 = gelu_fast(acc2[nb][3] + biasB[c1]);
            float w00 = sW2[c0*3+0], w01 = sW2[c0*3+1], w02 = sW2[c0*3+2];
            float w10 = sW2[c1*3+0], w11 = sW2[c1*3+1], w12 = sW2[c1*3+2];
            rA0 += v00*w00 + v01*w10;
            rA1 += v00*w01 + v01*w11;
            rA2 += v00*w02 + v01*w12;
            rB0 += v10*w00 + v11*w10;
            rB1 += v10*w01 + v11*w11;
            rB2 += v10*w02 + v11*w12;
        }
        #pragma unroll
        for (int off = 1; off <= 2; off <<= 1) {
            rA0 += __shfl_xor_sync(0xffffffffu, rA0, off);
            rA1 += __shfl_xor_sync(0xffffffffu, rA1, off);
            rA2 += __shfl_xor_sync(0xffffffffu, rA2, off);
            rB0 += __shfl_xor_sync(0xffffffffu, rB0, off);
            rB1 += __shfl_xor_sync(0xffffffffu, rB1, off);
            rB2 += __shfl_xor_sync(0xffffffffu, rB2, off);
        }
        if (q == 0) {
            float c0 = b2[0], c1 = b2[1], c2 = b2[2];
            float* oA = g_rgb + (size_t)pA * 3;
            oA[0] = sigmoid_fast(rA0 + c0);
            oA[1] = sigmoid_fast(rA1 + c1);
            oA[2] = sigmoid_fast(rA2 + c2);
            float* oB = g_rgb + (size_t)pB * 3;
            oB[0] = sigmoid_fast(rB0 + c0);
            oB[1] = sigmoid_fast(rB1 + c1);
            oB[2] = sigmoid_fast(rB2 + c2);
        }
        __syncthreads();
    }
}

// ---------------- per-ray compositing (accurate expf kept) ----------------
__global__ void k_render(float* __restrict__ out_rgb, float* __restrict__ out_depth,
                         float* __restrict__ w) {
    int qq = blockIdx.x * blockDim.x + threadIdx.x;
    if (qq >= NRAYS) return;
    float T = 1.0f, a0 = 0.0f, a1 = 0.0f, a2 = 0.0f, dep = 0.0f;
    const float* rp = g_rgb + (size_t)qq * NS * 3;
    float* wp = w + (size_t)qq * NS;
    #pragma unroll 1
    for (int s = 0; s < NS; s++) {
        float sg = wp[s];
        float al = 1.0f - expf(-sg * DT);
        float wt = al * T;
        T *= (1.0f - al + 1e-10f);
        wp[s] = wt;
        dep += wt * (((float)s + 0.5f) * DT);
        a0 += wt * rp[s*3+0];
        a1 += wt * rp[s*3+1];
        a2 += wt * rp[s*3+2];
    }
    out_rgb[qq*3+0] = a0;
    out_rgb[qq*3+1] = a1;
    out_rgb[qq*3+2] = a2;
    out_depth[qq]   = dep;
}

// ---------------- launch ----------------
extern "C" void kernel_launch(void* const* d_in, const int* in_sizes, int n_in,
                              void* d_out, int out_size) {
    const float* rays_o  = (const float*)d_in[0];
    const float* rays_d  = (const float*)d_in[1];
    const float* matrixs = (const float*)d_in[2];
    const float* vectors = (const float*)d_in[3];
    const float* w_mat   = (const float*)d_in[4];
    const float* b_mat   = (const float*)d_in[5];
    const float* w1      = (const float*)d_in[6];
    const float* b1      = (const float*)d_in[7];
    const float* w2      = (const float*)d_in[8];
    const float* b2      = (const float*)d_in[9];

    float* out       = (float*)d_out;
    float* out_rgb   = out;
    float* out_depth = out + NRAYS*3;
    float* out_w     = out + NRAYS*4;

    static int nsm = 0;
    if (nsm == 0) {
        cudaDeviceProp prop;
        cudaGetDeviceProperties(&prop, 0);
        nsm = prop.multiProcessorCount;
        cudaFuncSetAttribute(k_fused, cudaFuncAttributeMaxDynamicSharedMemorySize,
                             SMEM_FLOATS * sizeof(float));
    }

    k_transpose_mat<<<(3*BATCH*RES*RES*CH + 255)/256, 256>>>(matrixs);
    k_transpose_vec<<<(3*BATCH*RES*CH + 255)/256, 256>>>(vectors);
    k_bias<<<(NRAYS + 127)/128, 128>>>(rays_d, w1, b1);
    k_fused<<<2*nsm, 256, SMEM_FLOATS * sizeof(float)>>>(rays_o, rays_d, w_mat, b_mat,
                                                          w1, w2, b2, out_w);
    k_render<<<(NRAYS + 127)/128, 128>>>(out_rgb, out_depth, out_w);
}

// round 9
// speedup vs baseline: 4.5991x; 1.1545x over previous
#include <cuda_runtime.h>
#include <cuda_fp16.h>
#include <math.h>
#include <stdint.h>

#define BATCH 4
#define RAYS  8192
#define NRAYS (BATCH*RAYS)          // 32768
#define NS    48
#define RES   48
#define CH    32
#define NPTS  (NRAYS*NS)            // 1572864
#define NTILES (NPTS/128)           // 12288

#define DT    0.03125f

// ---------------- device scratch ----------------
__device__ __align__(16) __half g_mat_h[3*BATCH*RES*RES*CH];
__device__ __align__(16) __half g_vec_h[3*BATCH*RES*CH];
__device__ __align__(16) float  g_rgb[(size_t)NPTS*3];
__device__ __align__(16) float  g_bias[(size_t)NRAYS*64];

__device__ __forceinline__ float tanh_apx(float x) {
    float r;
    asm("tanh.approx.f32 %0, %1;" : "=f"(r) : "f"(x));
    return r;
}

__device__ __forceinline__ float gelu_fast(float x) {
    float inner = 0.7978845608f * x * fmaf(0.044715f * x, x, 1.0f);
    return 0.5f * x * (1.0f + tanh_apx(inner));
}

__device__ __forceinline__ float sigmoid_fast(float x) {
    return 0.5f * (1.0f + tanh_apx(0.5f * x));
}

__device__ __forceinline__ void mma_f16(float d[4],
                                        uint32_t a0, uint32_t a1, uint32_t a2, uint32_t a3,
                                        uint32_t b0, uint32_t b1) {
    asm volatile("mma.sync.aligned.m16n8k16.row.col.f32.f16.f16.f32 "
                 "{%0,%1,%2,%3}, {%4,%5,%6,%7}, {%8,%9}, {%0,%1,%2,%3};"
                 : "+f"(d[0]), "+f"(d[1]), "+f"(d[2]), "+f"(d[3])
                 : "r"(a0), "r"(a1), "r"(a2), "r"(a3), "r"(b0), "r"(b1));
}

__device__ __forceinline__ void ldsm_x4(uint32_t& r0, uint32_t& r1, uint32_t& r2, uint32_t& r3,
                                        uint32_t saddr) {
    asm volatile("ldmatrix.sync.aligned.m8n8.x4.shared.b16 {%0,%1,%2,%3}, [%4];"
                 : "=r"(r0), "=r"(r1), "=r"(r2), "=r"(r3) : "r"(saddr));
}

__device__ __forceinline__ uint32_t pack_h2(float lo, float hi) {
    __half2 h = __floats2half2_rn(lo, hi);
    return *(uint32_t*)&h;
}

// ---------------- prep: transposes to channel-last fp16 ----------------
__global__ void k_transpose_mat(const float* __restrict__ m) {
    int idx = blockIdx.x * blockDim.x + threadIdx.x;
    if (idx >= 3*BATCH*RES*RES*CH) return;
    int c   = idx % CH;
    int pix = (idx / CH) % (RES*RES);
    int ib  = idx / (CH*RES*RES);
    g_mat_h[idx] = __float2half_rn(m[((size_t)ib*CH + c)*(RES*RES) + pix]);
}

__global__ void k_transpose_vec(const float* __restrict__ v) {
    int idx = blockIdx.x * blockDim.x + threadIdx.x;
    if (idx >= 3*BATCH*RES*CH) return;
    int c  = idx % CH;
    int r  = (idx / CH) % RES;
    int ib = idx / (CH*RES);
    g_vec_h[idx] = __float2half_rn(v[((size_t)ib*CH + c)*RES + r]);
}

__global__ void k_bias(const float* __restrict__ rays_d,
                       const float* __restrict__ w1, const float* __restrict__ b1) {
    int q = blockIdx.x * blockDim.x + threadIdx.x;
    if (q >= NRAYS) return;
    float dx = rays_d[q*3+0], dy = rays_d[q*3+1], dz = rays_d[q*3+2];
    float inv = 1.0f / sqrtf(dx*dx + dy*dy + dz*dz);
    dx *= inv; dy *= inv; dz *= inv;
    float pe[27];
    pe[0] = dx; pe[1] = dy; pe[2] = dz;
    float f = 1.0f;
    #pragma unroll
    for (int fi = 0; fi < 4; fi++) {
        float s, c;
        sincosf(dx*f, &s, &c); pe[3 + fi*3 + 0] = s; pe[15 + fi*3 + 0] = c;
        sincosf(dy*f, &s, &c); pe[3 + fi*3 + 1] = s; pe[15 + fi*3 + 1] = c;
        sincosf(dz*f, &s, &c); pe[3 + fi*3 + 2] = s; pe[15 + fi*3 + 2] = c;
        f *= 2.0f;
    }
    float acc[64];
    #pragma unroll
    for (int j = 0; j < 64; j++) acc[j] = b1[j];
    #pragma unroll 1
    for (int k = 0; k < 27; k++) {
        float v = pe[k];
        const float* wr = w1 + (64 + k) * 64;
        #pragma unroll
        for (int j = 0; j < 64; j++) acc[j] += v * wr[j];
    }
    float* o = g_bias + (size_t)q * 64;
    #pragma unroll
    for (int j = 0; j < 64; j++) o[j] = acc[j];
}

// ---------------- fused persistent: sample -> GEMM1 -> GEMM2 -> head ------------
// F tile: 128 rows x 88-half pitch (176 B) -> LDSM conflict-free
#define F_PITCH 88
#define F_BUF_FLOATS (128*F_PITCH/2)      // 5632
// B rows: stride 136 words, entries uint2 {h2(k0,k0+1), h2(k0+8,k0+9)}
#define OF_B1   F_BUF_FLOATS              // 5632
#define OF_B2   (OF_B1 + 5*4*136)         // +2720 -> 8352
#define OF_W2   (OF_B2 + 4*4*136)         // +2176 -> 10528
#define OF_BM   (OF_W2 + 192)             // 10720
#define SMEM_FLOATS (OF_BM + 64)          // 10784 floats = 43136 B

__global__ __launch_bounds__(256, 2)
void k_fused(const float* __restrict__ rays_o, const float* __restrict__ rays_d,
             const float* __restrict__ w_mat, const float* __restrict__ b_mat,
             const float* __restrict__ w1, const float* __restrict__ w2,
             const float* __restrict__ b2, float* __restrict__ out_sigma) {
    extern __shared__ float sm[];
    float* sB1 = sm + OF_B1;
    float* sB2 = sm + OF_B2;
    float* sW2 = sm + OF_W2;
    float* sBm = sm + OF_BM;
    __half* sF = (__half*)sm;

    const int tid  = threadIdx.x;
    const int lane = tid & 31;
    const int wid  = tid >> 5;
    const int q    = lane & 3;
    const int g    = lane >> 2;

    // zero pad cols 72..79 (read by GEMM1 kb=4; never written again)
    if (tid < 128)
        *(uint4*)(sF + tid*F_PITCH + 72) = make_uint4(0,0,0,0);

    // ---- one-time fp16 weight packing (hi only) ----
    for (int i = tid; i < 5*4*64; i += 256) {
        int kb = i >> 8, qq = (i >> 6) & 3, n = i & 63;
        int k0 = kb*16 + 2*qq;
        float v0 = w_mat[k0*64 + n];
        float v1 = w_mat[(k0+1)*64 + n];
        float v2 = (k0+8 < 72) ? w_mat[(k0+8)*64 + n] : 0.0f;
        float v3 = (k0+9 < 72) ? w_mat[(k0+9)*64 + n] : 0.0f;
        uint2 e;
        e.x = pack_h2(v0, v1);
        e.y = pack_h2(v2, v3);
        *(uint2*)(sB1 + (kb*4 + qq)*136 + n*2) = e;
    }
    for (int i = tid; i < 4*4*64; i += 256) {
        int kb = i >> 8, qq = (i >> 6) & 3, n = i & 63;
        int k0 = kb*16 + 2*qq;
        uint2 e;
        e.x = pack_h2(w1[k0*64 + n],     w1[(k0+1)*64 + n]);
        e.y = pack_h2(w1[(k0+8)*64 + n], w1[(k0+9)*64 + n]);
        *(uint2*)(sB2 + (kb*4 + qq)*136 + n*2) = e;
    }
    if (tid < 192) sW2[tid] = w2[tid];
    if (tid < 64)  sBm[tid] = b_mat[tid];
    __syncthreads();

    const int m0 = wid * 16;
    const int lp = tid & 127;
    const int halfsel = tid >> 7;

    // ldmatrix per-lane base address (bytes, shared space)
    const uint32_t sF_sh = (uint32_t)__cvta_generic_to_shared(sF);
    const uint32_t a_base = sF_sh +
        (uint32_t)(((m0 + (lane & 15)) * F_PITCH + ((lane >> 4) * 8)) * 2);

    #pragma unroll 1
    for (int tile = blockIdx.x; tile < NTILES; tile += gridDim.x) {
        const int pbase = tile * 128;

        // ================= sampling phase: 2 threads per point =================
        {
            const int p   = pbase + lp;
            const int s   = p % NS;
            const int ray = p / NS;
            const int b   = ray / RAYS;

            const float ox = rays_o[ray*3+0], oy = rays_o[ray*3+1], oz = rays_o[ray*3+2];
            const float dx = rays_d[ray*3+0], dy = rays_d[ray*3+1], dz = rays_d[ray*3+2];
            const float t  = ((float)s + 0.5f) * DT;

            const float px = ((ox + dx*t) + 0.8f) * 1.25f - 1.0f;
            const float py = ((oy + dy*t) + 0.8f) * 1.25f - 1.0f;
            const float pz = ((oz + dz*t) + 0.8f) * 1.25f - 1.0f;

            float sigma = 0.0f;
            __half* fo = sF + lp*F_PITCH;
            const int cc0 = halfsel*2;

            #pragma unroll 1
            for (int pl = 0; pl < 3; pl++) {
                const float cx = (pl == 0) ? px : ((pl == 1) ? pz : py);
                const float cy = (pl == 0) ? py : ((pl == 1) ? px : pz);
                const float cz = (pl == 0) ? pz : ((pl == 1) ? py : px);

                const float fx = (cx + 1.0f) * 23.5f;
                const float fy = (cy + 1.0f) * 23.5f;
                const float fz = (cz + 1.0f) * 23.5f;
                const float x0f = floorf(fx), y0f = floorf(fy), z0f = floorf(fz);
                const float wx = fx - x0f, wy = fy - y0f, wz = fz - z0f;
                const int ix0 = (int)x0f, iy0 = (int)y0f, iz0 = (int)z0f;

                const float mx0 = (ix0 >= 0  && ix0 <  RES)   ? 1.0f : 0.0f;
                const float mx1 = (ix0 >= -1 && ix0 <  RES-1) ? 1.0f : 0.0f;
                const float my0 = (iy0 >= 0  && iy0 <  RES)   ? 1.0f : 0.0f;
                const float my1 = (iy0 >= -1 && iy0 <  RES-1) ? 1.0f : 0.0f;
                const float mz0 = (iz0 >= 0  && iz0 <  RES)   ? 1.0f : 0.0f;
                const float mz1 = (iz0 >= -1 && iz0 <  RES-1) ? 1.0f : 0.0f;

                const int cx0 = min(max(ix0,   0), RES-1), cx1 = min(max(ix0+1, 0), RES-1);
                const int cy0 = min(max(iy0,   0), RES-1), cy1 = min(max(iy0+1, 0), RES-1);
                const int cz0 = min(max(iz0,   0), RES-1), cz1 = min(max(iz0+1, 0), RES-1);

                const float w00 = (1.0f-wx)*(1.0f-wy)*mx0*my0;
                const float w10 = wx*(1.0f-wy)*mx1*my0;
                const float w01 = (1.0f-wx)*wy*mx0*my1;
                const float w11 = wx*wy*mx1*my1;
                const float u0  = (1.0f-wz)*mz0;
                const float u1  = wz*mz1;

                const __half* mb = g_mat_h + ((size_t)(pl*BATCH + b) * (RES*RES)) * CH;
                const __half* vb = g_vec_h + ((size_t)(pl*BATCH + b) * RES) * CH;
                const uint4* p00 = (const uint4*)(mb + (size_t)(cy0*RES + cx0) * CH);
                const uint4* p10 = (const uint4*)(mb + (size_t)(cy0*RES + cx1) * CH);
                const uint4* p01 = (const uint4*)(mb + (size_t)(cy1*RES + cx0) * CH);
                const uint4* p11 = (const uint4*)(mb + (size_t)(cy1*RES + cx1) * CH);
                const uint4* q0  = (const uint4*)(vb + (size_t)cz0 * CH);
                const uint4* q1  = (const uint4*)(vb + (size_t)cz1 * CH);

                #pragma unroll
                for (int ci = 0; ci < 2; ci++) {
                    const int cc = cc0 + ci;
                    uint4 ua = p00[cc], ub = p10[cc], uc = p01[cc], ud = p11[cc];
                    uint4 ue = q0[cc],  uf = q1[cc];
                    const __half2* ha = (const __half2*)&ua;
                    const __half2* hb = (const __half2*)&ub;
                    const __half2* hc = (const __half2*)&uc;
                    const __half2* hd = (const __half2*)&ud;
                    const __half2* he = (const __half2*)&ue;
                    const __half2* hf = (const __half2*)&uf;
                    float vals[8];
                    #pragma unroll
                    for (int j = 0; j < 4; j++) {
                        float2 fa = __half22float2(ha[j]);
                        float2 fb = __half22float2(hb[j]);
                        float2 fc = __half22float2(hc[j]);
                        float2 fd = __half22float2(hd[j]);
                        float2 fe = __half22float2(he[j]);
                        float2 ff = __half22float2(hf[j]);
                        float pf0 = w00*fa.x + w10*fb.x + w01*fc.x + w11*fd.x;
                        float pf1 = w00*fa.y + w10*fb.y + w01*fc.y + w11*fd.y;
                        float lf0 = u0*fe.x + u1*ff.x;
                        float lf1 = u0*fe.y + u1*ff.y;
                        vals[j*2]   = pf0 * lf0;
                        vals[j*2+1] = pf1 * lf1;
                    }
                    if (cc == 0) {
                        #pragma unroll
                        for (int j = 0; j < 8; j++) sigma += vals[j];
                    } else {
                        uint4 packed;
                        packed.x = pack_h2(gelu_fast(vals[0]), gelu_fast(vals[1]));
                        packed.y = pack_h2(gelu_fast(vals[2]), gelu_fast(vals[3]));
                        packed.z = pack_h2(gelu_fast(vals[4]), gelu_fast(vals[5]));
                        packed.w = pack_h2(gelu_fast(vals[6]), gelu_fast(vals[7]));
                        *(uint4*)(fo + pl*24 + (cc-1)*8) = packed;
                    }
                }
            }
            if (halfsel == 0) out_sigma[p] = fmaxf(sigma, 0.0f);
        }
        __syncthreads();

        // ================= GEMM1: acc = F @ Wmat + b_mat =================
        float acc[8][4];
        #pragma unroll
        for (int nb = 0; nb < 8; nb++) {
            float bv0 = sBm[nb*8 + 2*q];
            float bv1 = sBm[nb*8 + 2*q + 1];
            acc[nb][0] = bv0; acc[nb][1] = bv1; acc[nb][2] = bv0; acc[nb][3] = bv1;
        }
        #pragma unroll 1
        for (int kb = 0; kb < 5; kb++) {
            uint32_t a0, a1, a2, a3;
            ldsm_x4(a0, a1, a2, a3, a_base + kb*32);
            const float* brow = sB1 + (kb*4 + q)*136 + g*2;
            #pragma unroll
            for (int nb = 0; nb < 8; nb++) {
                uint2 bv = *(const uint2*)(brow + nb*16);
                mma_f16(acc[nb], a0, a1, a2, a3, bv.x, bv.y);
            }
        }
        // ---- epilogue 1: gelu -> fp16 back into sF (warp-private rows) ----
        __syncwarp();
        #pragma unroll
        for (int nb = 0; nb < 8; nb++) {
            int c0 = nb*8 + 2*q;
            __half2* dA = (__half2*)(sF + (m0 + g)*F_PITCH + c0);
            __half2* dB = (__half2*)(sF + (m0 + g + 8)*F_PITCH + c0);
            *dA = __floats2half2_rn(gelu_fast(acc[nb][0]), gelu_fast(acc[nb][1]));
            *dB = __floats2half2_rn(gelu_fast(acc[nb][2]), gelu_fast(acc[nb][3]));
        }
        __syncwarp();
        // ================= GEMM2: acc2 = H @ W1a =================
        float acc2[8][4];
        #pragma unroll
        for (int nb = 0; nb < 8; nb++)
            acc2[nb][0] = acc2[nb][1] = acc2[nb][2] = acc2[nb][3] = 0.0f;
        #pragma unroll 1
        for (int kb = 0; kb < 4; kb++) {
            uint32_t a0, a1, a2, a3;
            ldsm_x4(a0, a1, a2, a3, a_base + kb*32);
            const float* brow = sB2 + (kb*4 + q)*136 + g*2;
            #pragma unroll
            for (int nb = 0; nb < 8; nb++) {
                uint2 bv = *(const uint2*)(brow + nb*16);
                mma_f16(acc2[nb], a0, a1, a2, a3, bv.x, bv.y);
            }
        }
        // ---- epilogue 2: +rayBias, gelu, xW2, quad-reduce, sigmoid ----
        const int pA = pbase + m0 + g;
        const int pB = pA + 8;
        const float* biasA = g_bias + (size_t)(pA / NS) * 64;
        const float* biasB = g_bias + (size_t)(pB / NS) * 64;
        float rA0 = 0.f, rA1 = 0.f, rA2 = 0.f, rB0 = 0.f, rB1 = 0.f, rB2 = 0.f;
        #pragma unroll
        for (int nb = 0; nb < 8; nb++) {
            int c0 = nb*8 + 2*q, c1 = c0 + 1;
            float v00 = gelu_fast(acc2[nb][0] + biasA[c0]);
            float v01 = gelu_fast(acc2[nb][1] + biasA[c1]);
            float v10 = gelu_fast(acc2[nb][2] + biasB[c0]);
            float v11 = gelu_fast(acc2[nb][3] + biasB[c1]);
            float w00 = sW2[c0*3+0], w01 = sW2[c0*3+1], w02 = sW2[c0*3+2];
            float w10 = sW2[c1*3+0], w11 = sW2[c1*3+1], w12 = sW2[c1*3+2];
            rA0 += v00*w00 + v01*w10;
            rA1 += v00*w01 + v01*w11;
            rA2 += v00*w02 + v01*w12;
            rB0 += v10*w00 + v11*w10;
            rB1 += v10*w01 + v11*w11;
            rB2 += v10*w02 + v11*w12;
        }
        #pragma unroll
        for (int off = 1; off <= 2; off <<= 1) {
            rA0 += __shfl_xor_sync(0xffffffffu, rA0, off);
            rA1 += __shfl_xor_sync(0xffffffffu, rA1, off);
            rA2 += __shfl_xor_sync(0xffffffffu, rA2, off);
            rB0 += __shfl_xor_sync(0xffffffffu, rB0, off);
            rB1 += __shfl_xor_sync(0xffffffffu, rB1, off);
            rB2 += __shfl_xor_sync(0xffffffffu, rB2, off);
        }
        if (q == 0) {
            float c0 = b2[0], c1 = b2[1], c2 = b2[2];
            float* oA = g_rgb + (size_t)pA * 3;
            oA[0] = sigmoid_fast(rA0 + c0);
            oA[1] = sigmoid_fast(rA1 + c1);
            oA[2] = sigmoid_fast(rA2 + c2);
            float* oB = g_rgb + (size_t)pB * 3;
            oB[0] = sigmoid_fast(rB0 + c0);
            oB[1] = sigmoid_fast(rB1 + c1);
            oB[2] = sigmoid_fast(rB2 + c2);
        }
        __syncthreads();
    }
}

// ---------------- per-ray compositing (accurate expf kept) ----------------
__global__ void k_render(float* __restrict__ out_rgb, float* __restrict__ out_depth,
                         float* __restrict__ w) {
    int qq = blockIdx.x * blockDim.x + threadIdx.x;
    if (qq >= NRAYS) return;
    float T = 1.0f, a0 = 0.0f, a1 = 0.0f, a2 = 0.0f, dep = 0.0f;
    const float* rp = g_rgb + (size_t)qq * NS * 3;
    float* wp = w + (size_t)qq * NS;
    #pragma unroll 1
    for (int s = 0; s < NS; s++) {
        float sg = wp[s];
        float al = 1.0f - expf(-sg * DT);
        float wt = al * T;
        T *= (1.0f - al + 1e-10f);
        wp[s] = wt;
        dep += wt * (((float)s + 0.5f) * DT);
        a0 += wt * rp[s*3+0];
        a1 += wt * rp[s*3+1];
        a2 += wt * rp[s*3+2];
    }
    out_rgb[qq*3+0] = a0;
    out_rgb[qq*3+1] = a1;
    out_rgb[qq*3+2] = a2;
    out_depth[qq]   = dep;
}

// ---------------- launch ----------------
extern "C" void kernel_launch(void* const* d_in, const int* in_sizes, int n_in,
                              void* d_out, int out_size) {
    const float* rays_o  = (const float*)d_in[0];
    const float* rays_d  = (const float*)d_in[1];
    const float* matrixs = (const float*)d_in[2];
    const float* vectors = (const float*)d_in[3];
    const float* w_mat   = (const float*)d_in[4];
    const float* b_mat   = (const float*)d_in[5];
    const float* w1      = (const float*)d_in[6];
    const float* b1      = (const float*)d_in[7];
    const float* w2      = (const float*)d_in[8];
    const float* b2      = (const float*)d_in[9];

    float* out       = (float*)d_out;
    float* out_rgb   = out;
    float* out_depth = out + NRAYS*3;
    float* out_w     = out + NRAYS*4;

    static int nsm = 0;
    if (nsm == 0) {
        cudaDeviceProp prop;
        cudaGetDeviceProperties(&prop, 0);
        nsm = prop.multiProcessorCount;
        cudaFuncSetAttribute(k_fused, cudaFuncAttributeMaxDynamicSharedMemorySize,
                             SMEM_FLOATS * sizeof(float));
    }

    k_transpose_mat<<<(3*BATCH*RES*RES*CH + 255)/256, 256>>>(matrixs);
    k_transpose_vec<<<(3*BATCH*RES*CH + 255)/256, 256>>>(vectors);
    k_bias<<<(NRAYS + 127)/128, 128>>>(rays_d, w1, b1);
    k_fused<<<2*nsm, 256, SMEM_FLOATS * sizeof(float)>>>(rays_o, rays_d, w_mat, b_mat,
                                                          w1, w2, b2, out_w);
    k_render<<<(NRAYS + 127)/128, 128>>>(out_rgb, out_depth, out_w);
}

// round 10
// speedup vs baseline: 4.6910x; 1.0200x over previous
#include <cuda_runtime.h>
#include <cuda_fp16.h>
#include <math.h>
#include <stdint.h>

#define BATCH 4
#define RAYS  8192
#define NRAYS (BATCH*RAYS)          // 32768
#define NS    48
#define RES   48
#define CH    32
#define NPTS  (NRAYS*NS)            // 1572864
#define NTILES (NPTS/128)           // 12288

#define DT    0.03125f

// ---------------- device scratch ----------------
__device__ __align__(16) __half g_mat_h[3*BATCH*RES*RES*CH];
__device__ __align__(16) __half g_vec_h[3*BATCH*RES*CH];
__device__ __align__(16) float  g_rgb[(size_t)NPTS*3];
__device__ __align__(16) float  g_bias[(size_t)NRAYS*64];

__device__ __forceinline__ float tanh_apx(float x) {
    float r;
    asm("tanh.approx.f32 %0, %1;" : "=f"(r) : "f"(x));
    return r;
}

__device__ __forceinline__ float gelu_fast(float x) {
    float inner = 0.7978845608f * x * fmaf(0.044715f * x, x, 1.0f);
    return 0.5f * x * (1.0f + tanh_apx(inner));
}

__device__ __forceinline__ float sigmoid_fast(float x) {
    return 0.5f * (1.0f + tanh_apx(0.5f * x));
}

// half2 gelu: tanh-form, HW f16x2 tanh
__device__ __forceinline__ __half2 gelu_h2(__half2 x) {
    const __half2 K2  = __float2half2_rn(0.035677408f);   // 0.79788456*0.044715
    const __half2 K0  = __float2half2_rn(0.7978845608f);
    const __half2 H05 = __float2half2_rn(0.5f);
    __half2 x2 = __hmul2(x, x);
    __half2 inner = __hmul2(x, __hfma2(x2, K2, K0));
    uint32_t ti;
    asm("tanh.approx.f16x2 %0, %1;" : "=r"(ti) : "r"(*(uint32_t*)&inner));
    __half2 th = *(__half2*)&ti;
    __half2 h = __hmul2(x, H05);
    return __hfma2(h, th, h);
}

__device__ __forceinline__ void mma_f16(float d[4],
                                        uint32_t a0, uint32_t a1, uint32_t a2, uint32_t a3,
                                        uint32_t b0, uint32_t b1) {
    asm volatile("mma.sync.aligned.m16n8k16.row.col.f32.f16.f16.f32 "
                 "{%0,%1,%2,%3}, {%4,%5,%6,%7}, {%8,%9}, {%0,%1,%2,%3};"
                 : "+f"(d[0]), "+f"(d[1]), "+f"(d[2]), "+f"(d[3])
                 : "r"(a0), "r"(a1), "r"(a2), "r"(a3), "r"(b0), "r"(b1));
}

__device__ __forceinline__ void ldsm_x4(uint32_t& r0, uint32_t& r1, uint32_t& r2, uint32_t& r3,
                                        uint32_t saddr) {
    asm volatile("ldmatrix.sync.aligned.m8n8.x4.shared.b16 {%0,%1,%2,%3}, [%4];"
                 : "=r"(r0), "=r"(r1), "=r"(r2), "=r"(r3) : "r"(saddr));
}

__device__ __forceinline__ uint32_t pack_h2(float lo, float hi) {
    __half2 h = __floats2half2_rn(lo, hi);
    return *(uint32_t*)&h;
}

// ---------------- prep: transposes to channel-last fp16 ----------------
__global__ void k_transpose_mat(const float* __restrict__ m) {
    int idx = blockIdx.x * blockDim.x + threadIdx.x;
    if (idx >= 3*BATCH*RES*RES*CH) return;
    int c   = idx % CH;
    int pix = (idx / CH) % (RES*RES);
    int ib  = idx / (CH*RES*RES);
    g_mat_h[idx] = __float2half_rn(m[((size_t)ib*CH + c)*(RES*RES) + pix]);
}

__global__ void k_transpose_vec(const float* __restrict__ v) {
    int idx = blockIdx.x * blockDim.x + threadIdx.x;
    if (idx >= 3*BATCH*RES*CH) return;
    int c  = idx % CH;
    int r  = (idx / CH) % RES;
    int ib = idx / (CH*RES);
    g_vec_h[idx] = __float2half_rn(v[((size_t)ib*CH + c)*RES + r]);
}

__global__ void k_bias(const float* __restrict__ rays_d,
                       const float* __restrict__ w1, const float* __restrict__ b1) {
    int q = blockIdx.x * blockDim.x + threadIdx.x;
    if (q >= NRAYS) return;
    float dx = rays_d[q*3+0], dy = rays_d[q*3+1], dz = rays_d[q*3+2];
    float inv = 1.0f / sqrtf(dx*dx + dy*dy + dz*dz);
    dx *= inv; dy *= inv; dz *= inv;
    float pe[27];
    pe[0] = dx; pe[1] = dy; pe[2] = dz;
    float f = 1.0f;
    #pragma unroll
    for (int fi = 0; fi < 4; fi++) {
        float s, c;
        sincosf(dx*f, &s, &c); pe[3 + fi*3 + 0] = s; pe[15 + fi*3 + 0] = c;
        sincosf(dy*f, &s, &c); pe[3 + fi*3 + 1] = s; pe[15 + fi*3 + 1] = c;
        sincosf(dz*f, &s, &c); pe[3 + fi*3 + 2] = s; pe[15 + fi*3 + 2] = c;
        f *= 2.0f;
    }
    float acc[64];
    #pragma unroll
    for (int j = 0; j < 64; j++) acc[j] = b1[j];
    #pragma unroll 1
    for (int k = 0; k < 27; k++) {
        float v = pe[k];
        const float* wr = w1 + (64 + k) * 64;
        #pragma unroll
        for (int j = 0; j < 64; j++) acc[j] += v * wr[j];
    }
    float* o = g_bias + (size_t)q * 64;
    #pragma unroll
    for (int j = 0; j < 64; j++) o[j] = acc[j];
}

// ---------------- fused persistent: sample -> GEMM1 -> GEMM2 -> head ------------
#define F_PITCH 88
#define F_BUF_FLOATS (128*F_PITCH/2)      // 5632
#define OF_B1   F_BUF_FLOATS              // 5632
#define OF_B2   (OF_B1 + 5*4*136)         // +2720 -> 8352
#define OF_W2   (OF_B2 + 4*4*136)         // +2176 -> 10528
#define OF_BM   (OF_W2 + 192)             // 10720
#define SMEM_FLOATS (OF_BM + 64)          // 10784 floats = 43136 B

__global__ __launch_bounds__(256, 2)
void k_fused(const float* __restrict__ rays_o, const float* __restrict__ rays_d,
             const float* __restrict__ w_mat, const float* __restrict__ b_mat,
             const float* __restrict__ w1, const float* __restrict__ w2,
             const float* __restrict__ b2, float* __restrict__ out_sigma) {
    extern __shared__ float sm[];
    float* sB1 = sm + OF_B1;
    float* sB2 = sm + OF_B2;
    float* sW2 = sm + OF_W2;
    float* sBm = sm + OF_BM;
    __half* sF = (__half*)sm;

    const int tid  = threadIdx.x;
    const int lane = tid & 31;
    const int wid  = tid >> 5;
    const int q    = lane & 3;
    const int g    = lane >> 2;

    if (tid < 128)
        *(uint4*)(sF + tid*F_PITCH + 72) = make_uint4(0,0,0,0);

    // ---- one-time fp16 weight packing (hi only) ----
    for (int i = tid; i < 5*4*64; i += 256) {
        int kb = i >> 8, qq = (i >> 6) & 3, n = i & 63;
        int k0 = kb*16 + 2*qq;
        float v0 = w_mat[k0*64 + n];
        float v1 = w_mat[(k0+1)*64 + n];
        float v2 = (k0+8 < 72) ? w_mat[(k0+8)*64 + n] : 0.0f;
        float v3 = (k0+9 < 72) ? w_mat[(k0+9)*64 + n] : 0.0f;
        uint2 e;
        e.x = pack_h2(v0, v1);
        e.y = pack_h2(v2, v3);
        *(uint2*)(sB1 + (kb*4 + qq)*136 + n*2) = e;
    }
    for (int i = tid; i < 4*4*64; i += 256) {
        int kb = i >> 8, qq = (i >> 6) & 3, n = i & 63;
        int k0 = kb*16 + 2*qq;
        uint2 e;
        e.x = pack_h2(w1[k0*64 + n],     w1[(k0+1)*64 + n]);
        e.y = pack_h2(w1[(k0+8)*64 + n], w1[(k0+9)*64 + n]);
        *(uint2*)(sB2 + (kb*4 + qq)*136 + n*2) = e;
    }
    if (tid < 192) sW2[tid] = w2[tid];
    if (tid < 64)  sBm[tid] = b_mat[tid];
    __syncthreads();

    const int m0 = wid * 16;
    const int lp = tid & 127;
    const int halfsel = tid >> 7;

    const uint32_t sF_sh = (uint32_t)__cvta_generic_to_shared(sF);
    const uint32_t a_base = sF_sh +
        (uint32_t)(((m0 + (lane & 15)) * F_PITCH + ((lane >> 4) * 8)) * 2);

    #pragma unroll 1
    for (int tile = blockIdx.x; tile < NTILES; tile += gridDim.x) {
        const int pbase = tile * 128;

        // ================= sampling phase: 2 threads per point =================
        {
            const int p   = pbase + lp;
            const int s   = p % NS;
            const int ray = p / NS;
            const int b   = ray / RAYS;

            const float ox = rays_o[ray*3+0], oy = rays_o[ray*3+1], oz = rays_o[ray*3+2];
            const float dx = rays_d[ray*3+0], dy = rays_d[ray*3+1], dz = rays_d[ray*3+2];
            const float t  = ((float)s + 0.5f) * DT;

            const float px = ((ox + dx*t) + 0.8f) * 1.25f - 1.0f;
            const float py = ((oy + dy*t) + 0.8f) * 1.25f - 1.0f;
            const float pz = ((oz + dz*t) + 0.8f) * 1.25f - 1.0f;

            float sigma = 0.0f;
            __half* fo = sF + lp*F_PITCH;
            const int cc0 = halfsel*2;

            #pragma unroll 1
            for (int pl = 0; pl < 3; pl++) {
                const float cx = (pl == 0) ? px : ((pl == 1) ? pz : py);
                const float cy = (pl == 0) ? py : ((pl == 1) ? px : pz);
                const float cz = (pl == 0) ? pz : ((pl == 1) ? py : px);

                const float fx = (cx + 1.0f) * 23.5f;
                const float fy = (cy + 1.0f) * 23.5f;
                const float fz = (cz + 1.0f) * 23.5f;
                const float x0f = floorf(fx), y0f = floorf(fy), z0f = floorf(fz);
                const float wx = fx - x0f, wy = fy - y0f, wz = fz - z0f;
                const int ix0 = (int)x0f, iy0 = (int)y0f, iz0 = (int)z0f;

                const float mx0 = (ix0 >= 0  && ix0 <  RES)   ? 1.0f : 0.0f;
                const float mx1 = (ix0 >= -1 && ix0 <  RES-1) ? 1.0f : 0.0f;
                const float my0 = (iy0 >= 0  && iy0 <  RES)   ? 1.0f : 0.0f;
                const float my1 = (iy0 >= -1 && iy0 <  RES-1) ? 1.0f : 0.0f;
                const float mz0 = (iz0 >= 0  && iz0 <  RES)   ? 1.0f : 0.0f;
                const float mz1 = (iz0 >= -1 && iz0 <  RES-1) ? 1.0f : 0.0f;

                const int cx0 = min(max(ix0,   0), RES-1), cx1 = min(max(ix0+1, 0), RES-1);
                const int cy0 = min(max(iy0,   0), RES-1), cy1 = min(max(iy0+1, 0), RES-1);
                const int cz0 = min(max(iz0,   0), RES-1), cz1 = min(max(iz0+1, 0), RES-1);

                const float w00 = (1.0f-wx)*(1.0f-wy)*mx0*my0;
                const float w10 = wx*(1.0f-wy)*mx1*my0;
                const float w01 = (1.0f-wx)*wy*mx0*my1;
                const float w11 = wx*wy*mx1*my1;
                const float u0  = (1.0f-wz)*mz0;
                const float u1  = wz*mz1;

                const __half* mb = g_mat_h + ((size_t)(pl*BATCH + b) * (RES*RES)) * CH;
                const __half* vb = g_vec_h + ((size_t)(pl*BATCH + b) * RES) * CH;
                const uint4* p00 = (const uint4*)(mb + (size_t)(cy0*RES + cx0) * CH);
                const uint4* p10 = (const uint4*)(mb + (size_t)(cy0*RES + cx1) * CH);
                const uint4* p01 = (const uint4*)(mb + (size_t)(cy1*RES + cx0) * CH);
                const uint4* p11 = (const uint4*)(mb + (size_t)(cy1*RES + cx1) * CH);
                const uint4* q0  = (const uint4*)(vb + (size_t)cz0 * CH);
                const uint4* q1  = (const uint4*)(vb + (size_t)cz1 * CH);

                const __half2 W00 = __float2half2_rn(w00);
                const __half2 W10 = __float2half2_rn(w10);
                const __half2 W01 = __float2half2_rn(w01);
                const __half2 W11 = __float2half2_rn(w11);
                const __half2 U0  = __float2half2_rn(u0);
                const __half2 U1  = __float2half2_rn(u1);

                #pragma unroll
                for (int ci = 0; ci < 2; ci++) {
                    const int cc = cc0 + ci;
                    uint4 ua = p00[cc], ub = p10[cc], uc = p01[cc], ud = p11[cc];
                    uint4 ue = q0[cc],  uf = q1[cc];
                    const __half2* ha = (const __half2*)&ua;
                    const __half2* hb = (const __half2*)&ub;
                    const __half2* hc = (const __half2*)&uc;
                    const __half2* hd = (const __half2*)&ud;
                    const __half2* he = (const __half2*)&ue;
                    const __half2* hf = (const __half2*)&uf;
                    if (cc == 0) {
                        // sigma channels in fp32 (accuracy for weights output)
                        #pragma unroll
                        for (int j = 0; j < 4; j++) {
                            float2 fa = __half22float2(ha[j]);
                            float2 fb = __half22float2(hb[j]);
                            float2 fc = __half22float2(hc[j]);
                            float2 fd = __half22float2(hd[j]);
                            float2 fe = __half22float2(he[j]);
                            float2 ff = __half22float2(hf[j]);
                            float pf0 = w00*fa.x + w10*fb.x + w01*fc.x + w11*fd.x;
                            float pf1 = w00*fa.y + w10*fb.y + w01*fc.y + w11*fd.y;
                            float lf0 = u0*fe.x + u1*ff.x;
                            float lf1 = u0*fe.y + u1*ff.y;
                            sigma += pf0*lf0 + pf1*lf1;
                        }
                    } else {
                        // rgb feature channels: half2 interpolation + half2 gelu
                        uint4 packed;
                        uint32_t* pk = &packed.x;
                        #pragma unroll
                        for (int j = 0; j < 4; j++) {
                            __half2 pf = __hmul2(hd[j], W11);
                            pf = __hfma2(hc[j], W01, pf);
                            pf = __hfma2(hb[j], W10, pf);
                            pf = __hfma2(ha[j], W00, pf);
                            __half2 lf = __hmul2(hf[j], U1);
                            lf = __hfma2(he[j], U0, lf);
                            __half2 gv = gelu_h2(__hmul2(pf, lf));
                            pk[j] = *(uint32_t*)&gv;
                        }
                        *(uint4*)(fo + pl*24 + (cc-1)*8) = packed;
                    }
                }
            }
            if (halfsel == 0) out_sigma[p] = fmaxf(sigma, 0.0f);
        }
        __syncthreads();

        // ================= GEMM1: acc = F @ Wmat + b_mat =================
        float acc[8][4];
        #pragma unroll
        for (int nb = 0; nb < 8; nb++) {
            float bv0 = sBm[nb*8 + 2*q];
            float bv1 = sBm[nb*8 + 2*q + 1];
            acc[nb][0] = bv0; acc[nb][1] = bv1; acc[nb][2] = bv0; acc[nb][3] = bv1;
        }
        #pragma unroll 1
        for (int kb = 0; kb < 5; kb++) {
            uint32_t a0, a1, a2, a3;
            ldsm_x4(a0, a1, a2, a3, a_base + kb*32);
            const float* brow = sB1 + (kb*4 + q)*136 + g*2;
            #pragma unroll
            for (int nb = 0; nb < 8; nb++) {
                uint2 bv = *(const uint2*)(brow + nb*16);
                mma_f16(acc[nb], a0, a1, a2, a3, bv.x, bv.y);
            }
        }
        __syncwarp();
        #pragma unroll
        for (int nb = 0; nb < 8; nb++) {
            int c0 = nb*8 + 2*q;
            __half2* dA = (__half2*)(sF + (m0 + g)*F_PITCH + c0);
            __half2* dB = (__half2*)(sF + (m0 + g + 8)*F_PITCH + c0);
            *dA = __floats2half2_rn(gelu_fast(acc[nb][0]), gelu_fast(acc[nb][1]));
            *dB = __floats2half2_rn(gelu_fast(acc[nb][2]), gelu_fast(acc[nb][3]));
        }
        __syncwarp();
        // ================= GEMM2: acc2 = H @ W1a =================
        float acc2[8][4];
        #pragma unroll
        for (int nb = 0; nb < 8; nb++)
            acc2[nb][0] = acc2[nb][1] = acc2[nb][2] = acc2[nb][3] = 0.0f;
        #pragma unroll 1
        for (int kb = 0; kb < 4; kb++) {
            uint32_t a0, a1, a2, a3;
            ldsm_x4(a0, a1, a2, a3, a_base + kb*32);
            const float* brow = sB2 + (kb*4 + q)*136 + g*2;
            #pragma unroll
            for (int nb = 0; nb < 8; nb++) {
                uint2 bv = *(const uint2*)(brow + nb*16);
                mma_f16(acc2[nb], a0, a1, a2, a3, bv.x, bv.y);
            }
        }
        // ---- epilogue 2 ----
        const int pA = pbase + m0 + g;
        const int pB = pA + 8;
        const float* biasA = g_bias + (size_t)(pA / NS) * 64;
        const float* biasB = g_bias + (size_t)(pB / NS) * 64;
        float rA0 = 0.f, rA1 = 0.f, rA2 = 0.f, rB0 = 0.f, rB1 = 0.f, rB2 = 0.f;
        #pragma unroll
        for (int nb = 0; nb < 8; nb++) {
            int c0 = nb*8 + 2*q, c1 = c0 + 1;
            float v00 = gelu_fast(acc2[nb][0] + biasA[c0]);
            float v01 = gelu_fast(acc2[nb][1] + biasA[c1]);
            float v10 = gelu_fast(acc2[nb][2] + biasB[c0]);
            float v11 = gelu_fast(acc2[nb][3] + biasB[c1]);
            float w00 = sW2[c0*3+0], w01 = sW2[c0*3+1], w02 = sW2[c0*3+2];
            float w10 = sW2[c1*3+0], w11 = sW2[c1*3+1], w12 = sW2[c1*3+2];
            rA0 += v00*w00 + v01*w10;
            rA1 += v00*w01 + v01*w11;
            rA2 += v00*w02 + v01*w12;
            rB0 += v10*w00 + v11*w10;
            rB1 += v10*w01 + v11*w11;
            rB2 += v10*w02 + v11*w12;
        }
        #pragma unroll
        for (int off = 1; off <= 2; off <<= 1) {
            rA0 += __shfl_xor_sync(0xffffffffu, rA0, off);
            rA1 += __shfl_xor_sync(0xffffffffu, rA1, off);
            rA2 += __shfl_xor_sync(0xffffffffu, rA2, off);
            rB0 += __shfl_xor_sync(0xffffffffu, rB0, off);
            rB1 += __shfl_xor_sync(0xffffffffu, rB1, off);
            rB2 += __shfl_xor_sync(0xffffffffu, rB2, off);
        }
        if (q == 0) {
            float c0 = b2[0], c1 = b2[1], c2 = b2[2];
            float* oA = g_rgb + (size_t)pA * 3;
            oA[0] = sigmoid_fast(rA0 + c0);
            oA[1] = sigmoid_fast(rA1 + c1);
            oA[2] = sigmoid_fast(rA2 + c2);
            float* oB = g_rgb + (size_t)pB * 3;
            oB[0] = sigmoid_fast(rB0 + c0);
            oB[1] = sigmoid_fast(rB1 + c1);
            oB[2] = sigmoid_fast(rB2 + c2);
        }
        __syncthreads();
    }
}

// ---------------- per-ray compositing ----------------
__global__ void k_render(float* __restrict__ out_rgb, float* __restrict__ out_depth,
                         float* __restrict__ w) {
    int qq = blockIdx.x * blockDim.x + threadIdx.x;
    if (qq >= NRAYS) return;
    float T = 1.0f, a0 = 0.0f, a1 = 0.0f, a2 = 0.0f, dep = 0.0f;
    const float* rp = g_rgb + (size_t)qq * NS * 3;
    float* wp = w + (size_t)qq * NS;
    #pragma unroll 1
    for (int s = 0; s < NS; s++) {
        float sg = wp[s];
        float al = 1.0f - __expf(-sg * DT);
        float wt = al * T;
        T *= (1.0f - al + 1e-10f);
        wp[s] = wt;
        dep += wt * (((float)s + 0.5f) * DT);
        a0 += wt * rp[s*3+0];
        a1 += wt * rp[s*3+1];
        a2 += wt * rp[s*3+2];
    }
    out_rgb[qq*3+0] = a0;
    out_rgb[qq*3+1] = a1;
    out_rgb[qq*3+2] = a2;
    out_depth[qq]   = dep;
}

// ---------------- launch ----------------
extern "C" void kernel_launch(void* const* d_in, const int* in_sizes, int n_in,
                              void* d_out, int out_size) {
    const float* rays_o  = (const float*)d_in[0];
    const float* rays_d  = (const float*)d_in[1];
    const float* matrixs = (const float*)d_in[2];
    const float* vectors = (const float*)d_in[3];
    const float* w_mat   = (const float*)d_in[4];
    const float* b_mat   = (const float*)d_in[5];
    const float* w1      = (const float*)d_in[6];
    const float* b1      = (const float*)d_in[7];
    const float* w2      = (const float*)d_in[8];
    const float* b2      = (const float*)d_in[9];

    float* out       = (float*)d_out;
    float* out_rgb   = out;
    float* out_depth = out + NRAYS*3;
    float* out_w     = out + NRAYS*4;

    static int nsm = 0;
    if (nsm == 0) {
        cudaDeviceProp prop;
        cudaGetDeviceProperties(&prop, 0);
        nsm = prop.multiProcessorCount;
        cudaFuncSetAttribute(k_fused, cudaFuncAttributeMaxDynamicSharedMemorySize,
                             SMEM_FLOATS * sizeof(float));
    }

    k_transpose_mat<<<(3*BATCH*RES*RES*CH + 255)/256, 256>>>(matrixs);
    k_transpose_vec<<<(3*BATCH*RES*CH + 255)/256, 256>>>(vectors);
    k_bias<<<(NRAYS + 127)/128, 128>>>(rays_d, w1, b1);
    k_fused<<<2*nsm, 256, SMEM_FLOATS * sizeof(float)>>>(rays_o, rays_d, w_mat, b_mat,
                                                          w1, w2, b2, out_w);
    k_render<<<(NRAYS + 127)/128, 128>>>(out_rgb, out_depth, out_w);
}

// round 11
// speedup vs baseline: 4.9467x; 1.0545x over previous
#include <cuda_runtime.h>
#include <cuda_fp16.h>
#include <math.h>
#include <stdint.h>

#define BATCH 4
#define RAYS  8192
#define NRAYS (BATCH*RAYS)          // 32768
#define NS    48
#define RES   48
#define CH    32
#define NPTS  (NRAYS*NS)            // 1572864
#define NTILES (NPTS/128)           // 12288

#define DT    0.03125f

// ---------------- device scratch ----------------
__device__ __align__(16) __half g_mat_h[3*BATCH*RES*RES*CH];
__device__ __align__(16) __half g_vec_h[3*BATCH*RES*CH];
__device__ __align__(16) float  g_rgb[(size_t)NPTS*3];
__device__ __align__(16) float  g_bias[(size_t)NRAYS*64];

__device__ __forceinline__ float tanh_apx(float x) {
    float r;
    asm("tanh.approx.f32 %0, %1;" : "=f"(r) : "f"(x));
    return r;
}

__device__ __forceinline__ float gelu_fast(float x) {
    float inner = 0.7978845608f * x * fmaf(0.044715f * x, x, 1.0f);
    return 0.5f * x * (1.0f + tanh_apx(inner));
}

__device__ __forceinline__ float sigmoid_fast(float x) {
    return 0.5f * (1.0f + tanh_apx(0.5f * x));
}

// half2 gelu: tanh-form, HW f16x2 tanh
__device__ __forceinline__ __half2 gelu_h2(__half2 x) {
    const __half2 K2  = __float2half2_rn(0.035677408f);   // 0.79788456*0.044715
    const __half2 K0  = __float2half2_rn(0.7978845608f);
    const __half2 H05 = __float2half2_rn(0.5f);
    __half2 x2 = __hmul2(x, x);
    __half2 inner = __hmul2(x, __hfma2(x2, K2, K0));
    uint32_t ti;
    asm("tanh.approx.f16x2 %0, %1;" : "=r"(ti) : "r"(*(uint32_t*)&inner));
    __half2 th = *(__half2*)&ti;
    __half2 h = __hmul2(x, H05);
    return __hfma2(h, th, h);
}

__device__ __forceinline__ void mma_f16(float d[4],
                                        uint32_t a0, uint32_t a1, uint32_t a2, uint32_t a3,
                                        uint32_t b0, uint32_t b1) {
    asm volatile("mma.sync.aligned.m16n8k16.row.col.f32.f16.f16.f32 "
                 "{%0,%1,%2,%3}, {%4,%5,%6,%7}, {%8,%9}, {%0,%1,%2,%3};"
                 : "+f"(d[0]), "+f"(d[1]), "+f"(d[2]), "+f"(d[3])
                 : "r"(a0), "r"(a1), "r"(a2), "r"(a3), "r"(b0), "r"(b1));
}

__device__ __forceinline__ void ldsm_x4(uint32_t& r0, uint32_t& r1, uint32_t& r2, uint32_t& r3,
                                        uint32_t saddr) {
    asm volatile("ldmatrix.sync.aligned.m8n8.x4.shared.b16 {%0,%1,%2,%3}, [%4];"
                 : "=r"(r0), "=r"(r1), "=r"(r2), "=r"(r3) : "r"(saddr));
}

__device__ __forceinline__ uint32_t pack_h2(float lo, float hi) {
    __half2 h = __floats2half2_rn(lo, hi);
    return *(uint32_t*)&h;
}

// ---------------- prep: transposes to channel-last fp16 ----------------
__global__ void k_transpose_mat(const float* __restrict__ m) {
    int idx = blockIdx.x * blockDim.x + threadIdx.x;
    if (idx >= 3*BATCH*RES*RES*CH) return;
    int c   = idx % CH;
    int pix = (idx / CH) % (RES*RES);
    int ib  = idx / (CH*RES*RES);
    g_mat_h[idx] = __float2half_rn(m[((size_t)ib*CH + c)*(RES*RES) + pix]);
}

__global__ void k_transpose_vec(const float* __restrict__ v) {
    int idx = blockIdx.x * blockDim.x + threadIdx.x;
    if (idx >= 3*BATCH*RES*CH) return;
    int c  = idx % CH;
    int r  = (idx / CH) % RES;
    int ib = idx / (CH*RES);
    g_vec_h[idx] = __float2half_rn(v[((size_t)ib*CH + c)*RES + r]);
}

__global__ void k_bias(const float* __restrict__ rays_d,
                       const float* __restrict__ w1, const float* __restrict__ b1) {
    int q = blockIdx.x * blockDim.x + threadIdx.x;
    if (q >= NRAYS) return;
    float dx = rays_d[q*3+0], dy = rays_d[q*3+1], dz = rays_d[q*3+2];
    float inv = 1.0f / sqrtf(dx*dx + dy*dy + dz*dz);
    dx *= inv; dy *= inv; dz *= inv;
    float pe[27];
    pe[0] = dx; pe[1] = dy; pe[2] = dz;
    float f = 1.0f;
    #pragma unroll
    for (int fi = 0; fi < 4; fi++) {
        float s, c;
        sincosf(dx*f, &s, &c); pe[3 + fi*3 + 0] = s; pe[15 + fi*3 + 0] = c;
        sincosf(dy*f, &s, &c); pe[3 + fi*3 + 1] = s; pe[15 + fi*3 + 1] = c;
        sincosf(dz*f, &s, &c); pe[3 + fi*3 + 2] = s; pe[15 + fi*3 + 2] = c;
        f *= 2.0f;
    }
    float acc[64];
    #pragma unroll
    for (int j = 0; j < 64; j++) acc[j] = b1[j];
    #pragma unroll 1
    for (int k = 0; k < 27; k++) {
        float v = pe[k];
        const float* wr = w1 + (64 + k) * 64;
        #pragma unroll
        for (int j = 0; j < 64; j++) acc[j] += v * wr[j];
    }
    float* o = g_bias + (size_t)q * 64;
    #pragma unroll
    for (int j = 0; j < 64; j++) o[j] = acc[j];
}

// ---------------- fused persistent: sample -> GEMM1 -> GEMM2 -> head ------------
#define F_PITCH 88
#define F_BUF_FLOATS (128*F_PITCH/2)      // 5632
#define OF_B1   F_BUF_FLOATS              // 5632
#define OF_B2   (OF_B1 + 5*4*136)         // +2720 -> 8352
#define OF_W2   (OF_B2 + 4*4*136)         // +2176 -> 10528
#define OF_BM   (OF_W2 + 192)             // 10720
#define SMEM_FLOATS (OF_BM + 64)          // 10784 floats = 43136 B

__global__ __launch_bounds__(256, 2)
void k_fused(const float* __restrict__ rays_o, const float* __restrict__ rays_d,
             const float* __restrict__ w_mat, const float* __restrict__ b_mat,
             const float* __restrict__ w1, const float* __restrict__ w2,
             const float* __restrict__ b2, float* __restrict__ out_sigma) {
    extern __shared__ float sm[];
    float* sB1 = sm + OF_B1;
    float* sB2 = sm + OF_B2;
    float* sW2 = sm + OF_W2;
    float* sBm = sm + OF_BM;
    __half* sF = (__half*)sm;

    const int tid  = threadIdx.x;
    const int lane = tid & 31;
    const int wid  = tid >> 5;
    const int q    = lane & 3;
    const int g    = lane >> 2;

    if (tid < 128)
        *(uint4*)(sF + tid*F_PITCH + 72) = make_uint4(0,0,0,0);

    // ---- one-time fp16 weight packing (hi only) ----
    for (int i = tid; i < 5*4*64; i += 256) {
        int kb = i >> 8, qq = (i >> 6) & 3, n = i & 63;
        int k0 = kb*16 + 2*qq;
        float v0 = w_mat[k0*64 + n];
        float v1 = w_mat[(k0+1)*64 + n];
        float v2 = (k0+8 < 72) ? w_mat[(k0+8)*64 + n] : 0.0f;
        float v3 = (k0+9 < 72) ? w_mat[(k0+9)*64 + n] : 0.0f;
        uint2 e;
        e.x = pack_h2(v0, v1);
        e.y = pack_h2(v2, v3);
        *(uint2*)(sB1 + (kb*4 + qq)*136 + n*2) = e;
    }
    for (int i = tid; i < 4*4*64; i += 256) {
        int kb = i >> 8, qq = (i >> 6) & 3, n = i & 63;
        int k0 = kb*16 + 2*qq;
        uint2 e;
        e.x = pack_h2(w1[k0*64 + n],     w1[(k0+1)*64 + n]);
        e.y = pack_h2(w1[(k0+8)*64 + n], w1[(k0+9)*64 + n]);
        *(uint2*)(sB2 + (kb*4 + qq)*136 + n*2) = e;
    }
    if (tid < 192) sW2[tid] = w2[tid];
    if (tid < 64)  sBm[tid] = b_mat[tid];
    __syncthreads();

    const int m0 = wid * 16;
    // interleaved mapping: 2 adjacent lanes per point -> contiguous 32B tap halves
    const int lp   = tid >> 1;      // local point row (0..127)
    const int csel = tid & 1;       // 0: chunks 0,1   1: chunks 2,3

    const uint32_t sF_sh = (uint32_t)__cvta_generic_to_shared(sF);
    const uint32_t a_base = sF_sh +
        (uint32_t)(((m0 + (lane & 15)) * F_PITCH + ((lane >> 4) * 8)) * 2);

    #pragma unroll 1
    for (int tile = blockIdx.x; tile < NTILES; tile += gridDim.x) {
        const int pbase = tile * 128;

        // ================= sampling phase: 2 adjacent threads per point ========
        {
            const int p   = pbase + lp;
            const int s   = p % NS;
            const int ray = p / NS;
            const int b   = ray / RAYS;

            const float ox = rays_o[ray*3+0], oy = rays_o[ray*3+1], oz = rays_o[ray*3+2];
            const float dx = rays_d[ray*3+0], dy = rays_d[ray*3+1], dz = rays_d[ray*3+2];
            const float t  = ((float)s + 0.5f) * DT;

            const float px = ((ox + dx*t) + 0.8f) * 1.25f - 1.0f;
            const float py = ((oy + dy*t) + 0.8f) * 1.25f - 1.0f;
            const float pz = ((oz + dz*t) + 0.8f) * 1.25f - 1.0f;

            float sigma = 0.0f;
            __half* fo = sF + lp*F_PITCH;
            const int cc0 = csel*2;

            #pragma unroll 1
            for (int pl = 0; pl < 3; pl++) {
                const float cx = (pl == 0) ? px : ((pl == 1) ? pz : py);
                const float cy = (pl == 0) ? py : ((pl == 1) ? px : pz);
                const float cz = (pl == 0) ? pz : ((pl == 1) ? py : px);

                const float fx = (cx + 1.0f) * 23.5f;
                const float fy = (cy + 1.0f) * 23.5f;
                const float fz = (cz + 1.0f) * 23.5f;
                const float x0f = floorf(fx), y0f = floorf(fy), z0f = floorf(fz);
                const float wx = fx - x0f, wy = fy - y0f, wz = fz - z0f;
                const int ix0 = (int)x0f, iy0 = (int)y0f, iz0 = (int)z0f;

                const float mx0 = (ix0 >= 0  && ix0 <  RES)   ? 1.0f : 0.0f;
                const float mx1 = (ix0 >= -1 && ix0 <  RES-1) ? 1.0f : 0.0f;
                const float my0 = (iy0 >= 0  && iy0 <  RES)   ? 1.0f : 0.0f;
                const float my1 = (iy0 >= -1 && iy0 <  RES-1) ? 1.0f : 0.0f;
                const float mz0 = (iz0 >= 0  && iz0 <  RES)   ? 1.0f : 0.0f;
                const float mz1 = (iz0 >= -1 && iz0 <  RES-1) ? 1.0f : 0.0f;

                const int cx0 = min(max(ix0,   0), RES-1), cx1 = min(max(ix0+1, 0), RES-1);
                const int cy0 = min(max(iy0,   0), RES-1), cy1 = min(max(iy0+1, 0), RES-1);
                const int cz0 = min(max(iz0,   0), RES-1), cz1 = min(max(iz0+1, 0), RES-1);

                const float w00 = (1.0f-wx)*(1.0f-wy)*mx0*my0;
                const float w10 = wx*(1.0f-wy)*mx1*my0;
                const float w01 = (1.0f-wx)*wy*mx0*my1;
                const float w11 = wx*wy*mx1*my1;
                const float u0  = (1.0f-wz)*mz0;
                const float u1  = wz*mz1;

                const __half* mb = g_mat_h + ((size_t)(pl*BATCH + b) * (RES*RES)) * CH;
                const __half* vb = g_vec_h + ((size_t)(pl*BATCH + b) * RES) * CH;
                const uint4* p00 = (const uint4*)(mb + (size_t)(cy0*RES + cx0) * CH);
                const uint4* p10 = (const uint4*)(mb + (size_t)(cy0*RES + cx1) * CH);
                const uint4* p01 = (const uint4*)(mb + (size_t)(cy1*RES + cx0) * CH);
                const uint4* p11 = (const uint4*)(mb + (size_t)(cy1*RES + cx1) * CH);
                const uint4* q0  = (const uint4*)(vb + (size_t)cz0 * CH);
                const uint4* q1  = (const uint4*)(vb + (size_t)cz1 * CH);

                const __half2 W00 = __float2half2_rn(w00);
                const __half2 W10 = __float2half2_rn(w10);
                const __half2 W01 = __float2half2_rn(w01);
                const __half2 W11 = __float2half2_rn(w11);
                const __half2 U0  = __float2half2_rn(u0);
                const __half2 U1  = __float2half2_rn(u1);

                #pragma unroll
                for (int ci = 0; ci < 2; ci++) {
                    const int cc = cc0 + ci;
                    uint4 ua = p00[cc], ub = p10[cc], uc = p01[cc], ud = p11[cc];
                    uint4 ue = q0[cc],  uf = q1[cc];
                    const __half2* ha = (const __half2*)&ua;
                    const __half2* hb = (const __half2*)&ub;
                    const __half2* hc = (const __half2*)&uc;
                    const __half2* hd = (const __half2*)&ud;
                    const __half2* he = (const __half2*)&ue;
                    const __half2* hf = (const __half2*)&uf;
                    if (cc == 0) {
                        // sigma channels in fp32 (accuracy for weights output)
                        #pragma unroll
                        for (int j = 0; j < 4; j++) {
                            float2 fa = __half22float2(ha[j]);
                            float2 fb = __half22float2(hb[j]);
                            float2 fc = __half22float2(hc[j]);
                            float2 fd = __half22float2(hd[j]);
                            float2 fe = __half22float2(he[j]);
                            float2 ff = __half22float2(hf[j]);
                            float pf0 = w00*fa.x + w10*fb.x + w01*fc.x + w11*fd.x;
                            float pf1 = w00*fa.y + w10*fb.y + w01*fc.y + w11*fd.y;
                            float lf0 = u0*fe.x + u1*ff.x;
                            float lf1 = u0*fe.y + u1*ff.y;
                            sigma += pf0*lf0 + pf1*lf1;
                        }
                    } else {
                        // rgb feature channels: half2 interpolation + half2 gelu
                        uint4 packed;
                        uint32_t* pk = &packed.x;
                        #pragma unroll
                        for (int j = 0; j < 4; j++) {
                            __half2 pf = __hmul2(hd[j], W11);
                            pf = __hfma2(hc[j], W01, pf);
                            pf = __hfma2(hb[j], W10, pf);
                            pf = __hfma2(ha[j], W00, pf);
                            __half2 lf = __hmul2(hf[j], U1);
                            lf = __hfma2(he[j], U0, lf);
                            __half2 gv = gelu_h2(__hmul2(pf, lf));
                            pk[j] = *(uint32_t*)&gv;
                        }
                        *(uint4*)(fo + pl*24 + (cc-1)*8) = packed;
                    }
                }
            }
            if (csel == 0) out_sigma[p] = fmaxf(sigma, 0.0f);
        }
        __syncthreads();

        // ================= GEMM1: acc = F @ Wmat + b_mat =================
        float acc[8][4];
        #pragma unroll
        for (int nb = 0; nb < 8; nb++) {
            float bv0 = sBm[nb*8 + 2*q];
            float bv1 = sBm[nb*8 + 2*q + 1];
            acc[nb][0] = bv0; acc[nb][1] = bv1; acc[nb][2] = bv0; acc[nb][3] = bv1;
        }
        #pragma unroll 1
        for (int kb = 0; kb < 5; kb++) {
            uint32_t a0, a1, a2, a3;
            ldsm_x4(a0, a1, a2, a3, a_base + kb*32);
            const float* brow = sB1 + (kb*4 + q)*136 + g*2;
            #pragma unroll
            for (int nb = 0; nb < 8; nb++) {
                uint2 bv = *(const uint2*)(brow + nb*16);
                mma_f16(acc[nb], a0, a1, a2, a3, bv.x, bv.y);
            }
        }
        __syncwarp();
        #pragma unroll
        for (int nb = 0; nb < 8; nb++) {
            int c0 = nb*8 + 2*q;
            __half2* dA = (__half2*)(sF + (m0 + g)*F_PITCH + c0);
            __half2* dB = (__half2*)(sF + (m0 + g + 8)*F_PITCH + c0);
            *dA = __floats2half2_rn(gelu_fast(acc[nb][0]), gelu_fast(acc[nb][1]));
            *dB = __floats2half2_rn(gelu_fast(acc[nb][2]), gelu_fast(acc[nb][3]));
        }
        __syncwarp();
        // ================= GEMM2: acc2 = H @ W1a =================
        float acc2[8][4];
        #pragma unroll
        for (int nb = 0; nb < 8; nb++)
            acc2[nb][0] = acc2[nb][1] = acc2[nb][2] = acc2[nb][3] = 0.0f;
        #pragma unroll 1
        for (int kb = 0; kb < 4; kb++) {
            uint32_t a0, a1, a2, a3;
            ldsm_x4(a0, a1, a2, a3, a_base + kb*32);
            const float* brow = sB2 + (kb*4 + q)*136 + g*2;
            #pragma unroll
            for (int nb = 0; nb < 8; nb++) {
                uint2 bv = *(const uint2*)(brow + nb*16);
                mma_f16(acc2[nb], a0, a1, a2, a3, bv.x, bv.y);
            }
        }
        // ---- epilogue 2 ----
        const int pA = pbase + m0 + g;
        const int pB = pA + 8;
        const float* biasA = g_bias + (size_t)(pA / NS) * 64;
        const float* biasB = g_bias + (size_t)(pB / NS) * 64;
        float rA0 = 0.f, rA1 = 0.f, rA2 = 0.f, rB0 = 0.f, rB1 = 0.f, rB2 = 0.f;
        #pragma unroll
        for (int nb = 0; nb < 8; nb++) {
            int c0 = nb*8 + 2*q, c1 = c0 + 1;
            float v00 = gelu_fast(acc2[nb][0] + biasA[c0]);
            float v01 = gelu_fast(acc2[nb][1] + biasA[c1]);
            float v10 = gelu_fast(acc2[nb][2] + biasB[c0]);
            float v11 = gelu_fast(acc2[nb][3] + biasB[c1]);
            float w00 = sW2[c0*3+0], w01 = sW2[c0*3+1], w02 = sW2[c0*3+2];
            float w10 = sW2[c1*3+0], w11 = sW2[c1*3+1], w12 = sW2[c1*3+2];
            rA0 += v00*w00 + v01*w10;
            rA1 += v00*w01 + v01*w11;
            rA2 += v00*w02 + v01*w12;
            rB0 += v10*w00 + v11*w10;
            rB1 += v10*w01 + v11*w11;
            rB2 += v10*w02 + v11*w12;
        }
        #pragma unroll
        for (int off = 1; off <= 2; off <<= 1) {
            rA0 += __shfl_xor_sync(0xffffffffu, rA0, off);
            rA1 += __shfl_xor_sync(0xffffffffu, rA1, off);
            rA2 += __shfl_xor_sync(0xffffffffu, rA2, off);
            rB0 += __shfl_xor_sync(0xffffffffu, rB0, off);
            rB1 += __shfl_xor_sync(0xffffffffu, rB1, off);
            rB2 += __shfl_xor_sync(0xffffffffu, rB2, off);
        }
        if (q == 0) {
            float c0 = b2[0], c1 = b2[1], c2 = b2[2];
            float* oA = g_rgb + (size_t)pA * 3;
            oA[0] = sigmoid_fast(rA0 + c0);
            oA[1] = sigmoid_fast(rA1 + c1);
            oA[2] = sigmoid_fast(rA2 + c2);
            float* oB = g_rgb + (size_t)pB * 3;
            oB[0] = sigmoid_fast(rB0 + c0);
            oB[1] = sigmoid_fast(rB1 + c1);
            oB[2] = sigmoid_fast(rB2 + c2);
        }
        __syncthreads();
    }
}

// ---------------- per-ray compositing ----------------
__global__ void k_render(float* __restrict__ out_rgb, float* __restrict__ out_depth,
                         float* __restrict__ w) {
    int qq = blockIdx.x * blockDim.x + threadIdx.x;
    if (qq >= NRAYS) return;
    float T = 1.0f, a0 = 0.0f, a1 = 0.0f, a2 = 0.0f, dep = 0.0f;
    const float* rp = g_rgb + (size_t)qq * NS * 3;
    float* wp = w + (size_t)qq * NS;
    #pragma unroll 1
    for (int s = 0; s < NS; s++) {
        float sg = wp[s];
        float al = 1.0f - __expf(-sg * DT);
        float wt = al * T;
        T *= (1.0f - al + 1e-10f);
        wp[s] = wt;
        dep += wt * (((float)s + 0.5f) * DT);
        a0 += wt * rp[s*3+0];
        a1 += wt * rp[s*3+1];
        a2 += wt * rp[s*3+2];
    }
    out_rgb[qq*3+0] = a0;
    out_rgb[qq*3+1] = a1;
    out_rgb[qq*3+2] = a2;
    out_depth[qq]   = dep;
}

// ---------------- launch ----------------
extern "C" void kernel_launch(void* const* d_in, const int* in_sizes, int n_in,
                              void* d_out, int out_size) {
    const float* rays_o  = (const float*)d_in[0];
    const float* rays_d  = (const float*)d_in[1];
    const float* matrixs = (const float*)d_in[2];
    const float* vectors = (const float*)d_in[3];
    const float* w_mat   = (const float*)d_in[4];
    const float* b_mat   = (const float*)d_in[5];
    const float* w1      = (const float*)d_in[6];
    const float* b1      = (const float*)d_in[7];
    const float* w2      = (const float*)d_in[8];
    const float* b2      = (const float*)d_in[9];

    float* out       = (float*)d_out;
    float* out_rgb   = out;
    float* out_depth = out + NRAYS*3;
    float* out_w     = out + NRAYS*4;

    static int nsm = 0;
    if (nsm == 0) {
        cudaDeviceProp prop;
        cudaGetDeviceProperties(&prop, 0);
        nsm = prop.multiProcessorCount;
        cudaFuncSetAttribute(k_fused, cudaFuncAttributeMaxDynamicSharedMemorySize,
                             SMEM_FLOATS * sizeof(float));
    }

    k_transpose_mat<<<(3*BATCH*RES*RES*CH + 255)/256, 256>>>(matrixs);
    k_transpose_vec<<<(3*BATCH*RES*CH + 255)/256, 256>>>(vectors);
    k_bias<<<(NRAYS + 127)/128, 128>>>(rays_d, w1, b1);
    k_fused<<<2*nsm, 256, SMEM_FLOATS * sizeof(float)>>>(rays_o, rays_d, w_mat, b_mat,
                                                          w1, w2, b2, out_w);
    k_render<<<(NRAYS + 127)/128, 128>>>(out_rgb, out_depth, out_w);
}

// round 12
// speedup vs baseline: 5.1054x; 1.0321x over previous
#include <cuda_runtime.h>
#include <cuda_fp16.h>
#include <math.h>
#include <stdint.h>

#define BATCH 4
#define RAYS  8192
#define NRAYS (BATCH*RAYS)          // 32768
#define NS    48
#define RES   48
#define CH    32
#define NPTS  (NRAYS*NS)            // 1572864
#define NTILES (NPTS/128)           // 12288

#define DT    0.03125f

// ---------------- device scratch ----------------
__device__ __align__(16) __half g_mat_h[3*BATCH*RES*RES*CH];
__device__ __align__(16) __half g_vec_h[3*BATCH*RES*CH];
__device__ __align__(16) float  g_rgb[(size_t)NPTS*3];
__device__ __align__(16) float  g_bias[(size_t)NRAYS*64];

__device__ __forceinline__ float tanh_apx(float x) {
    float r;
    asm("tanh.approx.f32 %0, %1;" : "=f"(r) : "f"(x));
    return r;
}

__device__ __forceinline__ float gelu_fast(float x) {
    float inner = 0.7978845608f * x * fmaf(0.044715f * x, x, 1.0f);
    return 0.5f * x * (1.0f + tanh_apx(inner));
}

__device__ __forceinline__ float sigmoid_fast(float x) {
    return 0.5f * (1.0f + tanh_apx(0.5f * x));
}

// half2 gelu: tanh-form, HW f16x2 tanh
__device__ __forceinline__ __half2 gelu_h2(__half2 x) {
    const __half2 K2  = __float2half2_rn(0.035677408f);   // 0.79788456*0.044715
    const __half2 K0  = __float2half2_rn(0.7978845608f);
    const __half2 H05 = __float2half2_rn(0.5f);
    __half2 x2 = __hmul2(x, x);
    __half2 inner = __hmul2(x, __hfma2(x2, K2, K0));
    uint32_t ti;
    asm("tanh.approx.f16x2 %0, %1;" : "=r"(ti) : "r"(*(uint32_t*)&inner));
    __half2 th = *(__half2*)&ti;
    __half2 h = __hmul2(x, H05);
    return __hfma2(h, th, h);
}

__device__ __forceinline__ void mma_f16(float d[4],
                                        uint32_t a0, uint32_t a1, uint32_t a2, uint32_t a3,
                                        uint32_t b0, uint32_t b1) {
    asm volatile("mma.sync.aligned.m16n8k16.row.col.f32.f16.f16.f32 "
                 "{%0,%1,%2,%3}, {%4,%5,%6,%7}, {%8,%9}, {%0,%1,%2,%3};"
                 : "+f"(d[0]), "+f"(d[1]), "+f"(d[2]), "+f"(d[3])
                 : "r"(a0), "r"(a1), "r"(a2), "r"(a3), "r"(b0), "r"(b1));
}

__device__ __forceinline__ void ldsm_x4(uint32_t& r0, uint32_t& r1, uint32_t& r2, uint32_t& r3,
                                        uint32_t saddr) {
    asm volatile("ldmatrix.sync.aligned.m8n8.x4.shared.b16 {%0,%1,%2,%3}, [%4];"
                 : "=r"(r0), "=r"(r1), "=r"(r2), "=r"(r3) : "r"(saddr));
}

__device__ __forceinline__ uint32_t pack_h2(float lo, float hi) {
    __half2 h = __floats2half2_rn(lo, hi);
    return *(uint32_t*)&h;
}

// ---------------- prep: transposes to channel-last fp16 ----------------
__global__ void k_transpose_mat(const float* __restrict__ m) {
    int idx = blockIdx.x * blockDim.x + threadIdx.x;
    if (idx >= 3*BATCH*RES*RES*CH) return;
    int c   = idx % CH;
    int pix = (idx / CH) % (RES*RES);
    int ib  = idx / (CH*RES*RES);
    g_mat_h[idx] = __float2half_rn(m[((size_t)ib*CH + c)*(RES*RES) + pix]);
}

__global__ void k_transpose_vec(const float* __restrict__ v) {
    int idx = blockIdx.x * blockDim.x + threadIdx.x;
    if (idx >= 3*BATCH*RES*CH) return;
    int c  = idx % CH;
    int r  = (idx / CH) % RES;
    int ib = idx / (CH*RES);
    g_vec_h[idx] = __float2half_rn(v[((size_t)ib*CH + c)*RES + r]);
}

__global__ void k_bias(const float* __restrict__ rays_d,
                       const float* __restrict__ w1, const float* __restrict__ b1) {
    int q = blockIdx.x * blockDim.x + threadIdx.x;
    if (q >= NRAYS) return;
    float dx = rays_d[q*3+0], dy = rays_d[q*3+1], dz = rays_d[q*3+2];
    float inv = 1.0f / sqrtf(dx*dx + dy*dy + dz*dz);
    dx *= inv; dy *= inv; dz *= inv;
    float pe[27];
    pe[0] = dx; pe[1] = dy; pe[2] = dz;
    float f = 1.0f;
    #pragma unroll
    for (int fi = 0; fi < 4; fi++) {
        float s, c;
        sincosf(dx*f, &s, &c); pe[3 + fi*3 + 0] = s; pe[15 + fi*3 + 0] = c;
        sincosf(dy*f, &s, &c); pe[3 + fi*3 + 1] = s; pe[15 + fi*3 + 1] = c;
        sincosf(dz*f, &s, &c); pe[3 + fi*3 + 2] = s; pe[15 + fi*3 + 2] = c;
        f *= 2.0f;
    }
    float acc[64];
    #pragma unroll
    for (int j = 0; j < 64; j++) acc[j] = b1[j];
    #pragma unroll 1
    for (int k = 0; k < 27; k++) {
        float v = pe[k];
        const float* wr = w1 + (64 + k) * 64;
        #pragma unroll
        for (int j = 0; j < 64; j++) acc[j] += v * wr[j];
    }
    float* o = g_bias + (size_t)q * 64;
    #pragma unroll
    for (int j = 0; j < 64; j++) o[j] = acc[j];
}

// ---------------- fused persistent, double-buffered ----------------
#define F_PITCH 88
#define F_BUF_FLOATS (128*F_PITCH/2)      // 5632
#define F_BUF_BYTES  (F_BUF_FLOATS*4)     // 22528
#define OF_B1   (2*F_BUF_FLOATS)          // 11264
#define OF_B2   (OF_B1 + 5*4*136)         // +2720 -> 13984
#define OF_W2   (OF_B2 + 4*4*136)         // +2176 -> 16160
#define OF_BM   (OF_W2 + 192)             // 16352
#define OF_BIAS (OF_BM + 64)              // 16416, 2 x 256 floats
#define SMEM_FLOATS (OF_BIAS + 512)       // 16928 floats = 67712 B

__global__ __launch_bounds__(256, 2)
void k_fused(const float* __restrict__ rays_o, const float* __restrict__ rays_d,
             const float* __restrict__ w_mat, const float* __restrict__ b_mat,
             const float* __restrict__ w1, const float* __restrict__ w2,
             const float* __restrict__ b2, float* __restrict__ out_sigma) {
    extern __shared__ float sm[];
    float* sB1   = sm + OF_B1;
    float* sB2   = sm + OF_B2;
    float* sW2   = sm + OF_W2;
    float* sBm   = sm + OF_BM;
    float* sBias = sm + OF_BIAS;

    const int tid  = threadIdx.x;
    const int lane = tid & 31;
    const int wid  = tid >> 5;
    const int q    = lane & 3;
    const int g    = lane >> 2;

    // zero pad cols 72..79 of BOTH F buffers (never written again)
    {
        int bufr = tid >> 7, row = tid & 127;
        *(uint4*)((__half*)sm + bufr*F_BUF_FLOATS*2 + row*F_PITCH + 72) = make_uint4(0,0,0,0);
    }

    // ---- one-time fp16 weight packing (hi only) ----
    for (int i = tid; i < 5*4*64; i += 256) {
        int kb = i >> 8, qq = (i >> 6) & 3, n = i & 63;
        int k0 = kb*16 + 2*qq;
        float v0 = w_mat[k0*64 + n];
        float v1 = w_mat[(k0+1)*64 + n];
        float v2 = (k0+8 < 72) ? w_mat[(k0+8)*64 + n] : 0.0f;
        float v3 = (k0+9 < 72) ? w_mat[(k0+9)*64 + n] : 0.0f;
        uint2 e;
        e.x = pack_h2(v0, v1);
        e.y = pack_h2(v2, v3);
        *(uint2*)(sB1 + (kb*4 + qq)*136 + n*2) = e;
    }
    for (int i = tid; i < 4*4*64; i += 256) {
        int kb = i >> 8, qq = (i >> 6) & 3, n = i & 63;
        int k0 = kb*16 + 2*qq;
        uint2 e;
        e.x = pack_h2(w1[k0*64 + n],     w1[(k0+1)*64 + n]);
        e.y = pack_h2(w1[(k0+8)*64 + n], w1[(k0+9)*64 + n]);
        *(uint2*)(sB2 + (kb*4 + qq)*136 + n*2) = e;
    }
    if (tid < 192) sW2[tid] = w2[tid];
    if (tid < 64)  sBm[tid] = b_mat[tid];
    __syncthreads();

    const int m0 = wid * 16;
    const int lp   = tid >> 1;      // local point row (0..127)
    const int csel = tid & 1;       // 0: chunks 0,1   1: chunks 2,3

    const uint32_t sF_sh0 = (uint32_t)__cvta_generic_to_shared((__half*)sm);
    const uint32_t a_base0 = sF_sh0 +
        (uint32_t)(((m0 + (lane & 15)) * F_PITCH + ((lane >> 4) * 8)) * 2);

    int buf = 0;
    #pragma unroll 1
    for (int tile = blockIdx.x; tile < NTILES; tile += gridDim.x, buf ^= 1) {
        const int pbase = tile * 128;
        __half* sF    = (__half*)sm + buf * F_BUF_FLOATS * 2;
        float*  sBiasB = sBias + buf * 256;
        const int ray0 = pbase / NS;

        // ---- stage per-ray bias (<=4 rays per 128-pt tile) ----
        {
            int row = tid >> 6, col = tid & 63;
            int r = ray0 + row;
            if (r > NRAYS-1) r = NRAYS-1;
            sBiasB[row*64 + col] = g_bias[(size_t)r*64 + col];
        }

        // ================= sampling phase: 2 adjacent threads per point ========
        {
            const int p   = pbase + lp;
            const int s   = p % NS;
            const int ray = p / NS;
            const int b   = ray / RAYS;

            const float ox = rays_o[ray*3+0], oy = rays_o[ray*3+1], oz = rays_o[ray*3+2];
            const float dx = rays_d[ray*3+0], dy = rays_d[ray*3+1], dz = rays_d[ray*3+2];
            const float t  = ((float)s + 0.5f) * DT;

            const float px = ((ox + dx*t) + 0.8f) * 1.25f - 1.0f;
            const float py = ((oy + dy*t) + 0.8f) * 1.25f - 1.0f;
            const float pz = ((oz + dz*t) + 0.8f) * 1.25f - 1.0f;

            float sigma = 0.0f;
            __half* fo = sF + lp*F_PITCH;
            const int cc0 = csel*2;

            #pragma unroll 1
            for (int pl = 0; pl < 3; pl++) {
                const float cx = (pl == 0) ? px : ((pl == 1) ? pz : py);
                const float cy = (pl == 0) ? py : ((pl == 1) ? px : pz);
                const float cz = (pl == 0) ? pz : ((pl == 1) ? py : px);

                const float fx = (cx + 1.0f) * 23.5f;
                const float fy = (cy + 1.0f) * 23.5f;
                const float fz = (cz + 1.0f) * 23.5f;
                const float x0f = floorf(fx), y0f = floorf(fy), z0f = floorf(fz);
                const float wx = fx - x0f, wy = fy - y0f, wz = fz - z0f;
                const int ix0 = (int)x0f, iy0 = (int)y0f, iz0 = (int)z0f;

                const float mx0 = (ix0 >= 0  && ix0 <  RES)   ? 1.0f : 0.0f;
                const float mx1 = (ix0 >= -1 && ix0 <  RES-1) ? 1.0f : 0.0f;
                const float my0 = (iy0 >= 0  && iy0 <  RES)   ? 1.0f : 0.0f;
                const float my1 = (iy0 >= -1 && iy0 <  RES-1) ? 1.0f : 0.0f;
                const float mz0 = (iz0 >= 0  && iz0 <  RES)   ? 1.0f : 0.0f;
                const float mz1 = (iz0 >= -1 && iz0 <  RES-1) ? 1.0f : 0.0f;

                const int cx0 = min(max(ix0,   0), RES-1), cx1 = min(max(ix0+1, 0), RES-1);
                const int cy0 = min(max(iy0,   0), RES-1), cy1 = min(max(iy0+1, 0), RES-1);
                const int cz0 = min(max(iz0,   0), RES-1), cz1 = min(max(iz0+1, 0), RES-1);

                const float w00 = (1.0f-wx)*(1.0f-wy)*mx0*my0;
                const float w10 = wx*(1.0f-wy)*mx1*my0;
                const float w01 = (1.0f-wx)*wy*mx0*my1;
                const float w11 = wx*wy*mx1*my1;
                const float u0  = (1.0f-wz)*mz0;
                const float u1  = wz*mz1;

                const __half* mb = g_mat_h + ((size_t)(pl*BATCH + b) * (RES*RES)) * CH;
                const __half* vb = g_vec_h + ((size_t)(pl*BATCH + b) * RES) * CH;
                const uint4* p00 = (const uint4*)(mb + (size_t)(cy0*RES + cx0) * CH);
                const uint4* p10 = (const uint4*)(mb + (size_t)(cy0*RES + cx1) * CH);
                const uint4* p01 = (const uint4*)(mb + (size_t)(cy1*RES + cx0) * CH);
                const uint4* p11 = (const uint4*)(mb + (size_t)(cy1*RES + cx1) * CH);
                const uint4* q0  = (const uint4*)(vb + (size_t)cz0 * CH);
                const uint4* q1  = (const uint4*)(vb + (size_t)cz1 * CH);

                const __half2 W00 = __float2half2_rn(w00);
                const __half2 W10 = __float2half2_rn(w10);
                const __half2 W01 = __float2half2_rn(w01);
                const __half2 W11 = __float2half2_rn(w11);
                const __half2 U0  = __float2half2_rn(u0);
                const __half2 U1  = __float2half2_rn(u1);

                #pragma unroll
                for (int ci = 0; ci < 2; ci++) {
                    const int cc = cc0 + ci;
                    uint4 ua = p00[cc], ub = p10[cc], uc = p01[cc], ud = p11[cc];
                    uint4 ue = q0[cc],  uf = q1[cc];
                    const __half2* ha = (const __half2*)&ua;
                    const __half2* hb = (const __half2*)&ub;
                    const __half2* hc = (const __half2*)&uc;
                    const __half2* hd = (const __half2*)&ud;
                    const __half2* he = (const __half2*)&ue;
                    const __half2* hf = (const __half2*)&uf;
                    if (cc == 0) {
                        // sigma channels in fp32 (accuracy for weights output)
                        #pragma unroll
                        for (int j = 0; j < 4; j++) {
                            float2 fa = __half22float2(ha[j]);
                            float2 fb = __half22float2(hb[j]);
                            float2 fc = __half22float2(hc[j]);
                            float2 fd = __half22float2(hd[j]);
                            float2 fe = __half22float2(he[j]);
                            float2 ff = __half22float2(hf[j]);
                            float pf0 = w00*fa.x + w10*fb.x + w01*fc.x + w11*fd.x;
                            float pf1 = w00*fa.y + w10*fb.y + w01*fc.y + w11*fd.y;
                            float lf0 = u0*fe.x + u1*ff.x;
                            float lf1 = u0*fe.y + u1*ff.y;
                            sigma += pf0*lf0 + pf1*lf1;
                        }
                    } else {
                        // rgb feature channels: half2 interpolation + half2 gelu
                        uint4 packed;
                        uint32_t* pk = &packed.x;
                        #pragma unroll
                        for (int j = 0; j < 4; j++) {
                            __half2 pf = __hmul2(hd[j], W11);
                            pf = __hfma2(hc[j], W01, pf);
                            pf = __hfma2(hb[j], W10, pf);
                            pf = __hfma2(ha[j], W00, pf);
                            __half2 lf = __hmul2(hf[j], U1);
                            lf = __hfma2(he[j], U0, lf);
                            __half2 gv = gelu_h2(__hmul2(pf, lf));
                            pk[j] = *(uint32_t*)&gv;
                        }
                        *(uint4*)(fo + pl*24 + (cc-1)*8) = packed;
                    }
                }
            }
            if (csel == 0) out_sigma[p] = fmaxf(sigma, 0.0f);
        }
        __syncthreads();   // sole barrier per tile (double-buffered sF)

        const uint32_t a_base = a_base0 + buf * F_BUF_BYTES;

        // ================= GEMM1: acc = F @ Wmat + b_mat =================
        float acc[8][4];
        #pragma unroll
        for (int nb = 0; nb < 8; nb++) {
            float bv0 = sBm[nb*8 + 2*q];
            float bv1 = sBm[nb*8 + 2*q + 1];
            acc[nb][0] = bv0; acc[nb][1] = bv1; acc[nb][2] = bv0; acc[nb][3] = bv1;
        }
        #pragma unroll 1
        for (int kb = 0; kb < 5; kb++) {
            uint32_t a0, a1, a2, a3;
            ldsm_x4(a0, a1, a2, a3, a_base + kb*32);
            const float* brow = sB1 + (kb*4 + q)*136 + g*2;
            #pragma unroll
            for (int nb = 0; nb < 8; nb++) {
                uint2 bv = *(const uint2*)(brow + nb*16);
                mma_f16(acc[nb], a0, a1, a2, a3, bv.x, bv.y);
            }
        }
        __syncwarp();
        #pragma unroll
        for (int nb = 0; nb < 8; nb++) {
            int c0 = nb*8 + 2*q;
            __half2* dA = (__half2*)(sF + (m0 + g)*F_PITCH + c0);
            __half2* dB = (__half2*)(sF + (m0 + g + 8)*F_PITCH + c0);
            *dA = gelu_h2(__floats2half2_rn(acc[nb][0], acc[nb][1]));
            *dB = gelu_h2(__floats2half2_rn(acc[nb][2], acc[nb][3]));
        }
        __syncwarp();
        // ================= GEMM2: acc2 = H @ W1a =================
        float acc2[8][4];
        #pragma unroll
        for (int nb = 0; nb < 8; nb++)
            acc2[nb][0] = acc2[nb][1] = acc2[nb][2] = acc2[nb][3] = 0.0f;
        #pragma unroll 1
        for (int kb = 0; kb < 4; kb++) {
            uint32_t a0, a1, a2, a3;
            ldsm_x4(a0, a1, a2, a3, a_base + kb*32);
            const float* brow = sB2 + (kb*4 + q)*136 + g*2;
            #pragma unroll
            for (int nb = 0; nb < 8; nb++) {
                uint2 bv = *(const uint2*)(brow + nb*16);
                mma_f16(acc2[nb], a0, a1, a2, a3, bv.x, bv.y);
            }
        }
        // ---- epilogue 2: +rayBias(smem), gelu, xW2, quad-reduce, sigmoid ----
        const int pA = pbase + m0 + g;
        const int pB = pA + 8;
        const float* biasA = sBiasB + (pA / NS - ray0) * 64;
        const float* biasB = sBiasB + (pB / NS - ray0) * 64;
        float rA0 = 0.f, rA1 = 0.f, rA2 = 0.f, rB0 = 0.f, rB1 = 0.f, rB2 = 0.f;
        #pragma unroll
        for (int nb = 0; nb < 8; nb++) {
            int c0 = nb*8 + 2*q, c1 = c0 + 1;
            float v00 = gelu_fast(acc2[nb][0] + biasA[c0]);
            float v01 = gelu_fast(acc2[nb][1] + biasA[c1]);
            float v10 = gelu_fast(acc2[nb][2] + biasB[c0]);
            float v11 = gelu_fast(acc2[nb][3] + biasB[c1]);
            float w00 = sW2[c0*3+0], w01 = sW2[c0*3+1], w02 = sW2[c0*3+2];
            float w10 = sW2[c1*3+0], w11 = sW2[c1*3+1], w12 = sW2[c1*3+2];
            rA0 += v00*w00 + v01*w10;
            rA1 += v00*w01 + v01*w11;
            rA2 += v00*w02 + v01*w12;
            rB0 += v10*w00 + v11*w10;
            rB1 += v10*w01 + v11*w11;
            rB2 += v10*w02 + v11*w12;
        }
        #pragma unroll
        for (int off = 1; off <= 2; off <<= 1) {
            rA0 += __shfl_xor_sync(0xffffffffu, rA0, off);
            rA1 += __shfl_xor_sync(0xffffffffu, rA1, off);
            rA2 += __shfl_xor_sync(0xffffffffu, rA2, off);
            rB0 += __shfl_xor_sync(0xffffffffu, rB0, off);
            rB1 += __shfl_xor_sync(0xffffffffu, rB1, off);
            rB2 += __shfl_xor_sync(0xffffffffu, rB2, off);
        }
        if (q == 0) {
            float c0 = b2[0], c1 = b2[1], c2 = b2[2];
            float* oA = g_rgb + (size_t)pA * 3;
            oA[0] = sigmoid_fast(rA0 + c0);
            oA[1] = sigmoid_fast(rA1 + c1);
            oA[2] = sigmoid_fast(rA2 + c2);
            float* oB = g_rgb + (size_t)pB * 3;
            oB[0] = sigmoid_fast(rB0 + c0);
            oB[1] = sigmoid_fast(rB1 + c1);
            oB[2] = sigmoid_fast(rB2 + c2);
        }
        // no trailing sync: next tile samples into the other buffer
    }
}

// ---------------- per-ray compositing ----------------
__global__ void k_render(float* __restrict__ out_rgb, float* __restrict__ out_depth,
                         float* __restrict__ w) {
    int qq = blockIdx.x * blockDim.x + threadIdx.x;
    if (qq >= NRAYS) return;
    float T = 1.0f, a0 = 0.0f, a1 = 0.0f, a2 = 0.0f, dep = 0.0f;
    const float* rp = g_rgb + (size_t)qq * NS * 3;
    float* wp = w + (size_t)qq * NS;
    #pragma unroll 1
    for (int s = 0; s < NS; s++) {
        float sg = wp[s];
        float al = 1.0f - __expf(-sg * DT);
        float wt = al * T;
        T *= (1.0f - al + 1e-10f);
        wp[s] = wt;
        dep += wt * (((float)s + 0.5f) * DT);
        a0 += wt * rp[s*3+0];
        a1 += wt * rp[s*3+1];
        a2 += wt * rp[s*3+2];
    }
    out_rgb[qq*3+0] = a0;
    out_rgb[qq*3+1] = a1;
    out_rgb[qq*3+2] = a2;
    out_depth[qq]   = dep;
}

// ---------------- launch ----------------
extern "C" void kernel_launch(void* const* d_in, const int* in_sizes, int n_in,
                              void* d_out, int out_size) {
    const float* rays_o  = (const float*)d_in[0];
    const float* rays_d  = (const float*)d_in[1];
    const float* matrixs = (const float*)d_in[2];
    const float* vectors = (const float*)d_in[3];
    const float* w_mat   = (const float*)d_in[4];
    const float* b_mat   = (const float*)d_in[5];
    const float* w1      = (const float*)d_in[6];
    const float* b1      = (const float*)d_in[7];
    const float* w2      = (const float*)d_in[8];
    const float* b2      = (const float*)d_in[9];

    float* out       = (float*)d_out;
    float* out_rgb   = out;
    float* out_depth = out + NRAYS*3;
    float* out_w     = out + NRAYS*4;

    static int nsm = 0;
    if (nsm == 0) {
        cudaDeviceProp prop;
        cudaGetDeviceProperties(&prop, 0);
        nsm = prop.multiProcessorCount;
        cudaFuncSetAttribute(k_fused, cudaFuncAttributeMaxDynamicSharedMemorySize,
                             SMEM_FLOATS * sizeof(float));
    }

    k_transpose_mat<<<(3*BATCH*RES*RES*CH + 255)/256, 256>>>(matrixs);
    k_transpose_vec<<<(3*BATCH*RES*CH + 255)/256, 256>>>(vectors);
    k_bias<<<(NRAYS + 127)/128, 128>>>(rays_d, w1, b1);
    k_fused<<<2*nsm, 256, SMEM_FLOATS * sizeof(float)>>>(rays_o, rays_d, w_mat, b_mat,
                                                          w1, w2, b2, out_w);
    k_render<<<(NRAYS + 127)/128, 128>>>(out_rgb, out_depth, out_w);
}